// round 2
// baseline (speedup 1.0000x reference)
#include <cuda_runtime.h>
#include <math.h>

#define B_  4
#define L_  2048
#define H_  512
#define N_  8
#define D_  64
#define M_  (B_*L_)   // 8192 rows

// ---------------- scratch (static device globals; no allocation) ----------------
__device__ float g_qc  [M_*H_];
__device__ float g_qp  [M_*H_];
__device__ float g_k   [M_*H_];
__device__ float g_v   [M_*H_];
__device__ float g_r   [L_*H_];
__device__ float g_attn[M_*H_];
__device__ float g_t1  [M_*H_];
__device__ float g_a   [M_*H_];
__device__ float g_h1  [M_*H_];
__device__ float g_h2  [M_*H_];

// ---------------- GEMM: C[M,N] = A[M,K] @ B + epilogue ----------------
// MODE 0 (NHD):  B[k][c] = W[(c>>6)*K*64 + k*64 + (c&63)]   (weights [N,H,D])
// MODE 1 (T):    B[k][c] = W[c*K + k]                        (A @ W.T)
enum { MODE_NHD = 0, MODE_T = 1 };
enum { EPI_BIAS = 0, EPI_QCQP = 1, EPI_GELU = 2 };

template<int MODE, int EPI>
__global__ __launch_bounds__(256)
void gemm_kernel(const float* __restrict__ A, const float* __restrict__ W,
                 const float* __restrict__ bias, const float* __restrict__ bias2,
                 const float* __restrict__ bias3,
                 float* __restrict__ out1, float* __restrict__ out2,
                 int M, int N, int K)
{
    __shared__ float As[16][129];
    __shared__ float Bs[16][132];
    const int tid = threadIdx.x;
    const int tx = tid & 15, ty = tid >> 4;
    const int m0 = blockIdx.y << 7, c0 = blockIdx.x << 7;

    float acc[8][8];
#pragma unroll
    for (int i = 0; i < 8; i++)
#pragma unroll
        for (int j = 0; j < 8; j++) acc[i][j] = 0.f;

    for (int k0 = 0; k0 < K; k0 += 16) {
        // A tile: 128 rows x 16 k, float4 along k, stored transposed
#pragma unroll
        for (int jj = 0; jj < 2; jj++) {
            int f   = tid + jj * 256;          // [0,512)
            int row = f >> 2;
            int kq  = (f & 3) << 2;
            float4 a4 = *(const float4*)(A + (size_t)(m0 + row) * K + k0 + kq);
            As[kq + 0][row] = a4.x; As[kq + 1][row] = a4.y;
            As[kq + 2][row] = a4.z; As[kq + 3][row] = a4.w;
        }
        // B tile: 16 k x 128 cols
        if (MODE == MODE_NHD) {
#pragma unroll
            for (int jj = 0; jj < 8; jj++) {
                int i  = tid + jj * 256;
                int kk = i >> 7, c = i & 127;
                int cc = c0 + c;
                Bs[kk][c] = W[(size_t)(cc >> 6) * ((size_t)K * 64)
                              + (size_t)(k0 + kk) * 64 + (cc & 63)];
            }
        } else {
#pragma unroll
            for (int jj = 0; jj < 8; jj++) {
                int i  = tid + jj * 256;
                int c  = i >> 4, kk = i & 15;
                Bs[kk][c] = W[(size_t)(c0 + c) * K + k0 + kk];
            }
        }
        __syncthreads();
#pragma unroll
        for (int kk = 0; kk < 16; kk++) {
            float ar[8], br[8];
#pragma unroll
            for (int i = 0; i < 8; i++) ar[i] = As[kk][ty + 16 * i];
#pragma unroll
            for (int j = 0; j < 8; j++) br[j] = Bs[kk][tx + 16 * j];
#pragma unroll
            for (int i = 0; i < 8; i++)
#pragma unroll
                for (int j = 0; j < 8; j++)
                    acc[i][j] = fmaf(ar[i], br[j], acc[i][j]);
        }
        __syncthreads();
    }

#pragma unroll
    for (int i = 0; i < 8; i++) {
        int m = m0 + ty + 16 * i;
#pragma unroll
        for (int j = 0; j < 8; j++) {
            int c = c0 + tx + 16 * j;
            float v = acc[i][j] + bias[c];
            size_t o = (size_t)m * N + c;
            if (EPI == EPI_BIAS) {
                out1[o] = v;
            } else if (EPI == EPI_QCQP) {
                out1[o] = v + bias2[c];
                out2[o] = v + bias3[c];
            } else { // GELU (exact erf form)
                out1[o] = v * 0.5f * (1.f + erff(v * 0.70710678118654752f));
            }
        }
    }
}

// ---------------- Flash-style causal attention with rel-shift ----------------
// scores[i,j] = (qc[i].k[j] + qp[i].r[L-1-(i-j)]) / 8, j <= i
// qc/qp/k/v stored [B*L, H] with head n occupying cols [n*64, n*64+64)
// r stored [L, H] same column blocking.
#define SMEM_FLOATS (4*64*65 + 128*65)   // 24960 floats = 99840 bytes

__global__ __launch_bounds__(256)
void attn_kernel(const float* __restrict__ qc, const float* __restrict__ qp,
                 const float* __restrict__ kmat, const float* __restrict__ vmat,
                 const float* __restrict__ rmat, float* __restrict__ out)
{
    extern __shared__ float sm[];
    float* qc_s = sm;                 // 64*65
    float* qp_s = qc_s + 64 * 65;     // 64*65
    float* k_s  = qp_s + 64 * 65;     // 64*65, reused for P
    float* v_s  = k_s  + 64 * 65;     // 64*65
    float* r_s  = v_s  + 64 * 65;     // 128*65, reused for Spos (stride 129)

    const int tid = threadIdx.x;
    const int tx = tid & 15, ty = tid >> 4;
    const int bh = blockIdx.y;        // 0..31
    const int b  = bh >> 3, n = bh & 7;
    const int i0 = blockIdx.x << 6;
    const int col = n << 6;
    const size_t qbase = ((size_t)(b * L_) + i0) * H_ + col;

    // load query tiles (persist across j-loop)
#pragma unroll
    for (int jj = 0; jj < 4; jj++) {
        int f = tid + jj * 256;
        int row = f >> 4, cq = (f & 15) << 2;
        float4 a = *(const float4*)(qc + qbase + (size_t)row * H_ + cq);
        qc_s[row * 65 + cq + 0] = a.x; qc_s[row * 65 + cq + 1] = a.y;
        qc_s[row * 65 + cq + 2] = a.z; qc_s[row * 65 + cq + 3] = a.w;
        float4 p = *(const float4*)(qp + qbase + (size_t)row * H_ + cq);
        qp_s[row * 65 + cq + 0] = p.x; qp_s[row * 65 + cq + 1] = p.y;
        qp_s[row * 65 + cq + 2] = p.z; qp_s[row * 65 + cq + 3] = p.w;
    }

    float mI[4], lI[4], O[4][4];
#pragma unroll
    for (int r = 0; r < 4; r++) {
        mI[r] = -INFINITY; lI[r] = 0.f;
#pragma unroll
        for (int c = 0; c < 4; c++) O[r][c] = 0.f;
    }

    for (int j0 = 0; j0 <= i0; j0 += 64) {
        __syncthreads();   // protect smem reuse from previous iteration
        // ---- load K/V tiles
        const size_t kb = ((size_t)(b * L_) + j0) * H_ + col;
#pragma unroll
        for (int jj = 0; jj < 4; jj++) {
            int f = tid + jj * 256;
            int row = f >> 4, cq = (f & 15) << 2;
            float4 a = *(const float4*)(kmat + kb + (size_t)row * H_ + cq);
            k_s[row * 65 + cq + 0] = a.x; k_s[row * 65 + cq + 1] = a.y;
            k_s[row * 65 + cq + 2] = a.z; k_s[row * 65 + cq + 3] = a.w;
            float4 vv = *(const float4*)(vmat + kb + (size_t)row * H_ + cq);
            v_s[row * 65 + cq + 0] = vv.x; v_s[row * 65 + cq + 1] = vv.y;
            v_s[row * 65 + cq + 2] = vv.z; v_s[row * 65 + cq + 3] = vv.w;
        }
        // ---- load r window: rows p = pbase..pbase+127 (OOB -> 0)
        const int pbase = (L_ - D_) + j0 - i0;   // 1984 + j0 - i0 >= 0
#pragma unroll
        for (int jj = 0; jj < 8; jj++) {
            int f = tid + jj * 256;
            int row = f >> 4, cq = (f & 15) << 2;
            int p = pbase + row;
            if (p < L_) {
                float4 a = *(const float4*)(rmat + (size_t)p * H_ + col + cq);
                r_s[row * 65 + cq + 0] = a.x; r_s[row * 65 + cq + 1] = a.y;
                r_s[row * 65 + cq + 2] = a.z; r_s[row * 65 + cq + 3] = a.w;
            } else {
                r_s[row * 65 + cq + 0] = 0.f; r_s[row * 65 + cq + 1] = 0.f;
                r_s[row * 65 + cq + 2] = 0.f; r_s[row * 65 + cq + 3] = 0.f;
            }
        }
        __syncthreads();

        // ---- Pass A: S = qc @ k^T ; Pass B: Sp = qp @ r^T (128-wide band)
        float S[4][4];
#pragma unroll
        for (int r = 0; r < 4; r++)
#pragma unroll
            for (int c = 0; c < 4; c++) S[r][c] = 0.f;
        float Sp[4][8];
#pragma unroll
        for (int r = 0; r < 4; r++)
#pragma unroll
            for (int u = 0; u < 8; u++) Sp[r][u] = 0.f;

#pragma unroll 8
        for (int kk = 0; kk < 64; kk++) {
            float aq[4], ap[4];
#pragma unroll
            for (int r = 0; r < 4; r++) {
                int ii = ty + 16 * r;
                aq[r] = qc_s[ii * 65 + kk];
                ap[r] = qp_s[ii * 65 + kk];
            }
            float bk[4];
#pragma unroll
            for (int c = 0; c < 4; c++) bk[c] = k_s[(tx + 16 * c) * 65 + kk];
#pragma unroll
            for (int r = 0; r < 4; r++)
#pragma unroll
                for (int c = 0; c < 4; c++) S[r][c] = fmaf(aq[r], bk[c], S[r][c]);
            float br8[8];
#pragma unroll
            for (int u = 0; u < 8; u++) br8[u] = r_s[(tx + 16 * u) * 65 + kk];
#pragma unroll
            for (int r = 0; r < 4; r++)
#pragma unroll
                for (int u = 0; u < 8; u++) Sp[r][u] = fmaf(ap[r], br8[u], Sp[r][u]);
        }
        __syncthreads();
        // Spos -> smem (reuse r_s region, stride 129)
#pragma unroll
        for (int r = 0; r < 4; r++) {
            int ii = ty + 16 * r;
#pragma unroll
            for (int u = 0; u < 8; u++) r_s[ii * 129 + tx + 16 * u] = Sp[r][u];
        }
        __syncthreads();

        const bool diag = (j0 == i0);
#pragma unroll
        for (int r = 0; r < 4; r++) {
            int ii = ty + 16 * r;
#pragma unroll
            for (int c = 0; c < 4; c++) {
                int jj = tx + 16 * c;
                // rel-shift: Spos column 63 + jj - ii  (in [0,126])
                float s = (S[r][c] + r_s[ii * 129 + 63 + jj - ii]) * 0.125f;
                if (diag && jj > ii) s = -1e30f;   // causal mask (only diagonal tile)
                S[r][c] = s;
            }
        }

        // ---- online softmax update (rows shared across 16 lanes)
#pragma unroll
        for (int r = 0; r < 4; r++) {
            float mx = fmaxf(fmaxf(S[r][0], S[r][1]), fmaxf(S[r][2], S[r][3]));
#pragma unroll
            for (int o = 1; o < 16; o <<= 1) mx = fmaxf(mx, __shfl_xor_sync(0xffffffffu, mx, o));
            float mnew = fmaxf(mI[r], mx);
            float corr = __expf(mI[r] - mnew);
            float rs = 0.f;
#pragma unroll
            for (int c = 0; c < 4; c++) { float p = __expf(S[r][c] - mnew); S[r][c] = p; rs += p; }
#pragma unroll
            for (int o = 1; o < 16; o <<= 1) rs += __shfl_xor_sync(0xffffffffu, rs, o);
            lI[r] = lI[r] * corr + rs;
            mI[r] = mnew;
#pragma unroll
            for (int c = 0; c < 4; c++) O[r][c] *= corr;
        }

        // ---- P -> smem (reuse k_s), then O += P @ V
#pragma unroll
        for (int r = 0; r < 4; r++) {
            int ii = ty + 16 * r;
#pragma unroll
            for (int c = 0; c < 4; c++) k_s[ii * 65 + tx + 16 * c] = S[r][c];
        }
        __syncthreads();
#pragma unroll 8
        for (int j2 = 0; j2 < 64; j2++) {
            float pr[4];
#pragma unroll
            for (int r = 0; r < 4; r++) pr[r] = k_s[(ty + 16 * r) * 65 + j2];
            float vc[4];
#pragma unroll
            for (int c = 0; c < 4; c++) vc[c] = v_s[j2 * 65 + tx + 16 * c];
#pragma unroll
            for (int r = 0; r < 4; r++)
#pragma unroll
                for (int c = 0; c < 4; c++) O[r][c] = fmaf(pr[r], vc[c], O[r][c]);
        }
    }

    // ---- write normalized output
#pragma unroll
    for (int r = 0; r < 4; r++) {
        int ii = ty + 16 * r;
        float inv = 1.f / lI[r];
#pragma unroll
        for (int c = 0; c < 4; c++)
            out[qbase + (size_t)ii * H_ + tx + 16 * c] = O[r][c] * inv;
    }
}

// ---------------- fused residual-add + LayerNorm ----------------
__global__ __launch_bounds__(256)
void ln_kernel(const float* __restrict__ a, const float* __restrict__ b,
               const float* __restrict__ w, const float* __restrict__ beta,
               float* __restrict__ out)
{
    const int row = blockIdx.x;
    const int tid = threadIdx.x;
    const size_t base = (size_t)row * H_;
    float x0 = a[base + tid]       + b[base + tid];
    float x1 = a[base + tid + 256] + b[base + tid + 256];
    float s  = x0 + x1;
    float sq = x0 * x0 + x1 * x1;
#pragma unroll
    for (int o = 16; o > 0; o >>= 1) {
        s  += __shfl_xor_sync(0xffffffffu, s,  o);
        sq += __shfl_xor_sync(0xffffffffu, sq, o);
    }
    __shared__ float rs[8], rq[8];
    int wid = tid >> 5;
    if ((tid & 31) == 0) { rs[wid] = s; rq[wid] = sq; }
    __syncthreads();
    if (tid < 32) {
        float ss = (tid < 8) ? rs[tid] : 0.f;
        float qq = (tid < 8) ? rq[tid] : 0.f;
#pragma unroll
        for (int o = 4; o > 0; o >>= 1) {
            ss += __shfl_xor_sync(0xffffffffu, ss, o);
            qq += __shfl_xor_sync(0xffffffffu, qq, o);
        }
        if (tid == 0) { rs[0] = ss; rq[0] = qq; }
    }
    __syncthreads();
    float mean = rs[0] * (1.f / H_);
    float var  = rq[0] * (1.f / H_) - mean * mean;
    float inv  = rsqrtf(var + 1e-12f);
    out[base + tid]       = w[tid]       * (x0 - mean) * inv + beta[tid];
    out[base + tid + 256] = w[tid + 256] * (x1 - mean) * inv + beta[tid + 256];
}

// ---------------- launcher ----------------
extern "C" void kernel_launch(void* const* d_in, const int* in_sizes, int n_in,
                              void* d_out, int out_size)
{
    const float* x   = (const float*)d_in[0];
    const float* pe  = (const float*)d_in[1];
    const float* Wq  = (const float*)d_in[2];
    const float* bq  = (const float*)d_in[3];
    const float* Wk  = (const float*)d_in[4];
    const float* bk  = (const float*)d_in[5];
    const float* Wv  = (const float*)d_in[6];
    const float* bv  = (const float*)d_in[7];
    const float* Wr  = (const float*)d_in[8];
    const float* br  = (const float*)d_in[9];
    const float* cb  = (const float*)d_in[10];
    const float* pb  = (const float*)d_in[11];
    const float* Wc  = (const float*)d_in[12];
    const float* bc  = (const float*)d_in[13];
    const float* W1  = (const float*)d_in[14];
    const float* b1  = (const float*)d_in[15];
    const float* W2  = (const float*)d_in[16];
    const float* b2  = (const float*)d_in[17];
    const float* lnw = (const float*)d_in[18];
    const float* lnb = (const float*)d_in[19];
    // d_in[20] = mask: deterministic causal triu, implemented in-kernel
    float* out = (float*)d_out;

    float *qcP, *qpP, *kP, *vP, *rP, *attnP, *t1P, *aP, *h1P, *h2P;
    cudaGetSymbolAddress((void**)&qcP,   g_qc);
    cudaGetSymbolAddress((void**)&qpP,   g_qp);
    cudaGetSymbolAddress((void**)&kP,    g_k);
    cudaGetSymbolAddress((void**)&vP,    g_v);
    cudaGetSymbolAddress((void**)&rP,    g_r);
    cudaGetSymbolAddress((void**)&attnP, g_attn);
    cudaGetSymbolAddress((void**)&t1P,   g_t1);
    cudaGetSymbolAddress((void**)&aP,    g_a);
    cudaGetSymbolAddress((void**)&h1P,   g_h1);
    cudaGetSymbolAddress((void**)&h2P,   g_h2);

    const dim3 gBig(H_ / 128, M_ / 128);   // (4, 64)
    const dim3 gPos(H_ / 128, L_ / 128);   // (4, 16)

    // QKV + R projections (fused biases; qc/qp get content/pos bias too)
    gemm_kernel<MODE_NHD, EPI_QCQP><<<gBig, 256>>>(x,  Wq, bq, cb, pb, qcP, qpP, M_, H_, H_);
    gemm_kernel<MODE_NHD, EPI_BIAS><<<gBig, 256>>>(x,  Wk, bk, nullptr, nullptr, kP, nullptr, M_, H_, H_);
    gemm_kernel<MODE_NHD, EPI_BIAS><<<gBig, 256>>>(x,  Wv, bv, nullptr, nullptr, vP, nullptr, M_, H_, H_);
    gemm_kernel<MODE_NHD, EPI_BIAS><<<gPos, 256>>>(pe, Wr, br, nullptr, nullptr, rP, nullptr, L_, H_, H_);

    // attention
    const int smemB = SMEM_FLOATS * (int)sizeof(float);   // 99840
    cudaFuncSetAttribute(attn_kernel, cudaFuncAttributeMaxDynamicSharedMemorySize, smemB);
    attn_kernel<<<dim3(L_ / 64, B_ * N_), 256, smemB>>>(qcP, qpP, kP, vP, rP, attnP);

    // out-proj + LN1
    gemm_kernel<MODE_T, EPI_BIAS><<<gBig, 256>>>(attnP, Wc, bc, nullptr, nullptr, t1P, nullptr, M_, H_, H_);
    ln_kernel<<<M_, 256>>>(t1P, x, lnw, lnb, aP);

    // FFN + LN2
    gemm_kernel<MODE_T, EPI_GELU><<<gBig, 256>>>(aP,  W1, b1, nullptr, nullptr, h1P, nullptr, M_, H_, H_);
    gemm_kernel<MODE_T, EPI_BIAS><<<gBig, 256>>>(h1P, W2, b2, nullptr, nullptr, h2P, nullptr, M_, H_, H_);
    ln_kernel<<<M_, 256>>>(aP, h2P, lnw, lnb, out);
}

// round 3
// speedup vs baseline: 1.0917x; 1.0917x over previous
#include <cuda_runtime.h>
#include <math.h>

#define B_  4
#define L_  2048
#define H_  512
#define N_  8
#define D_  64
#define M_  (B_*L_)   // 8192 rows

typedef unsigned long long u64;

#define FMA2(d, a, b) asm("fma.rn.f32x2 %0, %1, %2, %0;" : "+l"(d) : "l"(a), "l"(b))
#define MUL2(d, a, b) asm("mul.rn.f32x2 %0, %1, %2;" : "=l"(d) : "l"(a), "l"(b))

__device__ __forceinline__ u64 pack2(float lo, float hi) {
    u64 r; asm("mov.b64 %0, {%1,%2};" : "=l"(r) : "f"(lo), "f"(hi)); return r;
}
__device__ __forceinline__ float2 unpack2(u64 v) {
    float2 f; asm("mov.b64 {%0,%1}, %2;" : "=f"(f.x), "=f"(f.y) : "l"(v)); return f;
}
__device__ __forceinline__ u64 ld64s(const float* p) { return *(const u64*)p; }

// ---------------- scratch ----------------
__device__ float g_qc  [M_*H_];
__device__ float g_qp  [M_*H_];
__device__ float g_k   [M_*H_];
__device__ float g_v   [M_*H_];
__device__ float g_r   [L_*H_];
__device__ float g_attn[M_*H_];
__device__ float g_t1  [M_*H_];
__device__ float g_a   [M_*H_];
__device__ float g_h1  [M_*H_];
__device__ float g_h2  [M_*H_];

// ---------------- GEMM (FFMA2 row-pair scheme) ----------------
enum { MODE_NHD = 0, MODE_T = 1 };
enum { EPI_BIAS = 0, EPI_QCQP = 1, EPI_GELU = 2 };

template<int MODE, int EPI>
__global__ __launch_bounds__(256)
void gemm_kernel(const float* __restrict__ A, const float* __restrict__ W,
                 const float* __restrict__ bias, const float* __restrict__ bias2,
                 const float* __restrict__ bias3,
                 float* __restrict__ out1, float* __restrict__ out2,
                 int M, int N, int K)
{
    __shared__ float As[16][130];   // [kk][row], even stride for aligned row-pairs
    __shared__ float Bs[16][132];   // [kk][col]
    const int tid = threadIdx.x;
    const int tx = tid & 15, ty = tid >> 4;
    const int m0 = blockIdx.y << 7, c0 = blockIdx.x << 7;

    u64 acc2[4][8];   // row-pairs (2ty+32i, +1) x cols (tx+16j)
#pragma unroll
    for (int i = 0; i < 4; i++)
#pragma unroll
        for (int j = 0; j < 8; j++) acc2[i][j] = 0ull;

    for (int k0 = 0; k0 < K; k0 += 16) {
#pragma unroll
        for (int jj = 0; jj < 2; jj++) {
            int f   = tid + jj * 256;
            int row = f >> 2;
            int kq  = (f & 3) << 2;
            float4 a4 = *(const float4*)(A + (size_t)(m0 + row) * K + k0 + kq);
            As[kq + 0][row] = a4.x; As[kq + 1][row] = a4.y;
            As[kq + 2][row] = a4.z; As[kq + 3][row] = a4.w;
        }
        if (MODE == MODE_NHD) {
#pragma unroll
            for (int jj = 0; jj < 8; jj++) {
                int i  = tid + jj * 256;
                int kk = i >> 7, c = i & 127;
                int cc = c0 + c;
                Bs[kk][c] = W[(size_t)(cc >> 6) * ((size_t)K * 64)
                              + (size_t)(k0 + kk) * 64 + (cc & 63)];
            }
        } else {
#pragma unroll
            for (int jj = 0; jj < 8; jj++) {
                int i  = tid + jj * 256;
                int c  = i >> 4, kk = i & 15;
                Bs[kk][c] = W[(size_t)(c0 + c) * K + k0 + kk];
            }
        }
        __syncthreads();
#pragma unroll
        for (int kk = 0; kk < 16; kk++) {
            u64 a2[4];
#pragma unroll
            for (int i = 0; i < 4; i++) a2[i] = ld64s(&As[kk][2 * ty + 32 * i]);
            u64 b2[8];
#pragma unroll
            for (int j = 0; j < 8; j++) {
                float b = Bs[kk][tx + 16 * j];
                b2[j] = pack2(b, b);
            }
#pragma unroll
            for (int i = 0; i < 4; i++)
#pragma unroll
                for (int j = 0; j < 8; j++)
                    FMA2(acc2[i][j], a2[i], b2[j]);
        }
        __syncthreads();
    }

#pragma unroll
    for (int i = 0; i < 4; i++) {
        int m = m0 + 2 * ty + 32 * i;
#pragma unroll
        for (int j = 0; j < 8; j++) {
            int c = c0 + tx + 16 * j;
            float2 v = unpack2(acc2[i][j]);
            float v0 = v.x + bias[c];
            float v1 = v.y + bias[c];
            size_t o0 = (size_t)m * N + c;
            size_t o1 = o0 + N;
            if (EPI == EPI_BIAS) {
                out1[o0] = v0; out1[o1] = v1;
            } else if (EPI == EPI_QCQP) {
                out1[o0] = v0 + bias2[c]; out1[o1] = v1 + bias2[c];
                out2[o0] = v0 + bias3[c]; out2[o1] = v1 + bias3[c];
            } else {
                out1[o0] = v0 * 0.5f * (1.f + erff(v0 * 0.70710678118654752f));
                out1[o1] = v1 * 0.5f * (1.f + erff(v1 * 0.70710678118654752f));
            }
        }
    }
}

// ---------------- Flash-style causal attention (FFMA2 k-pair scheme) ----------------
// smem strides padded to 66 so float2 loads along the reduction dim are
// 8B-aligned and lane-stride-66 stays bank-conflict-free.
#define ST66 66
#define SMEM_FLOATS (ST66*(64*2 + 64 + 64 + 128))   // qc, qp, k(/P), v, r(/Spos)

__global__ __launch_bounds__(256)
void attn_kernel(const float* __restrict__ qc, const float* __restrict__ qp,
                 const float* __restrict__ kmat, const float* __restrict__ vmat,
                 const float* __restrict__ rmat, float* __restrict__ out)
{
    extern __shared__ float sm[];
    float* qc_s = sm;                    // [row][d]    64x66
    float* qp_s = qc_s + 64 * ST66;      // [row][d]    64x66
    float* k_s  = qp_s + 64 * ST66;      // [j][d]      64x66  (reused as P [row][j])
    float* v_s  = k_s  + 64 * ST66;      // [d][j]      64x66  (transposed!)
    float* r_s  = v_s  + 64 * ST66;      // [p][d]     128x66  (reused as Spos stride 129)

    const int tid = threadIdx.x;
    const int tx = tid & 15, ty = tid >> 4;
    const int bh = blockIdx.y;
    const int b  = bh >> 3, n = bh & 7;
    const int i0 = (gridDim.x - 1 - blockIdx.x) << 6;   // heavy tiles first
    const int col = n << 6;
    const size_t qbase = ((size_t)(b * L_) + i0) * H_ + col;

    // persistent query tiles
#pragma unroll
    for (int jj = 0; jj < 4; jj++) {
        int f = tid + jj * 256;
        int row = f >> 4, cq = (f & 15) << 2;
        float4 a = *(const float4*)(qc + qbase + (size_t)row * H_ + cq);
        *(float2*)&qc_s[row * ST66 + cq]     = make_float2(a.x, a.y);
        *(float2*)&qc_s[row * ST66 + cq + 2] = make_float2(a.z, a.w);
        float4 p = *(const float4*)(qp + qbase + (size_t)row * H_ + cq);
        *(float2*)&qp_s[row * ST66 + cq]     = make_float2(p.x, p.y);
        *(float2*)&qp_s[row * ST66 + cq + 2] = make_float2(p.z, p.w);
    }

    float mI[4], lI[4];
    u64 O2[4][4];                       // even/odd-j2 partial sums packed
#pragma unroll
    for (int r = 0; r < 4; r++) {
        mI[r] = -INFINITY; lI[r] = 0.f;
#pragma unroll
        for (int c = 0; c < 4; c++) O2[r][c] = 0ull;
    }

    for (int j0 = 0; j0 <= i0; j0 += 64) {
        __syncthreads();
        const size_t kb = ((size_t)(b * L_) + j0) * H_ + col;
#pragma unroll
        for (int jj = 0; jj < 4; jj++) {
            int f = tid + jj * 256;
            int row = f >> 4, cq = (f & 15) << 2;
            float4 a = *(const float4*)(kmat + kb + (size_t)row * H_ + cq);
            *(float2*)&k_s[row * ST66 + cq]     = make_float2(a.x, a.y);
            *(float2*)&k_s[row * ST66 + cq + 2] = make_float2(a.z, a.w);
            float4 vv = *(const float4*)(vmat + kb + (size_t)row * H_ + cq);
            v_s[(cq + 0) * ST66 + row] = vv.x;   // transposed [d][j]
            v_s[(cq + 1) * ST66 + row] = vv.y;
            v_s[(cq + 2) * ST66 + row] = vv.z;
            v_s[(cq + 3) * ST66 + row] = vv.w;
        }
        const int pbase = (L_ - D_) + j0 - i0;
#pragma unroll
        for (int jj = 0; jj < 8; jj++) {
            int f = tid + jj * 256;
            int row = f >> 4, cq = (f & 15) << 2;
            int p = pbase + row;
            if (p < L_) {
                float4 a = *(const float4*)(rmat + (size_t)p * H_ + col + cq);
                *(float2*)&r_s[row * ST66 + cq]     = make_float2(a.x, a.y);
                *(float2*)&r_s[row * ST66 + cq + 2] = make_float2(a.z, a.w);
            } else {
                *(float2*)&r_s[row * ST66 + cq]     = make_float2(0.f, 0.f);
                *(float2*)&r_s[row * ST66 + cq + 2] = make_float2(0.f, 0.f);
            }
        }
        __syncthreads();

        // ---- score: S = qc@k^T, Sp = qp@r^T, packed even/odd-k halves
        u64 S2[4][4], Sp2[4][8];
#pragma unroll
        for (int r = 0; r < 4; r++) {
#pragma unroll
            for (int c = 0; c < 4; c++) S2[r][c] = 0ull;
#pragma unroll
            for (int u = 0; u < 8; u++) Sp2[r][u] = 0ull;
        }
#pragma unroll 4
        for (int kk = 0; kk < 64; kk += 2) {
            u64 aq2[4], ap2[4];
#pragma unroll
            for (int r = 0; r < 4; r++) {
                int ii = ty + 16 * r;
                aq2[r] = ld64s(&qc_s[ii * ST66 + kk]);
                ap2[r] = ld64s(&qp_s[ii * ST66 + kk]);
            }
            u64 bk2[4];
#pragma unroll
            for (int c = 0; c < 4; c++) bk2[c] = ld64s(&k_s[(tx + 16 * c) * ST66 + kk]);
            u64 br2[8];
#pragma unroll
            for (int u = 0; u < 8; u++) br2[u] = ld64s(&r_s[(tx + 16 * u) * ST66 + kk]);
#pragma unroll
            for (int r = 0; r < 4; r++)
#pragma unroll
                for (int c = 0; c < 4; c++) FMA2(S2[r][c], aq2[r], bk2[c]);
#pragma unroll
            for (int r = 0; r < 4; r++)
#pragma unroll
                for (int u = 0; u < 8; u++) FMA2(Sp2[r][u], ap2[r], br2[u]);
        }
        __syncthreads();
        // Spos -> smem (reuse r_s, stride 129)
#pragma unroll
        for (int r = 0; r < 4; r++) {
            int ii = ty + 16 * r;
#pragma unroll
            for (int u = 0; u < 8; u++) {
                float2 f = unpack2(Sp2[r][u]);
                r_s[ii * 129 + tx + 16 * u] = f.x + f.y;
            }
        }
        __syncthreads();

        const bool diag = (j0 == i0);
        float S[4][4];
#pragma unroll
        for (int r = 0; r < 4; r++) {
            int ii = ty + 16 * r;
#pragma unroll
            for (int c = 0; c < 4; c++) {
                int jj = tx + 16 * c;
                float2 f = unpack2(S2[r][c]);
                float s = (f.x + f.y + r_s[ii * 129 + 63 + jj - ii]) * 0.125f;
                if (diag && jj > ii) s = -1e30f;
                S[r][c] = s;
            }
        }

        // ---- online softmax
#pragma unroll
        for (int r = 0; r < 4; r++) {
            float mx = fmaxf(fmaxf(S[r][0], S[r][1]), fmaxf(S[r][2], S[r][3]));
#pragma unroll
            for (int o = 1; o < 16; o <<= 1) mx = fmaxf(mx, __shfl_xor_sync(0xffffffffu, mx, o));
            float mnew = fmaxf(mI[r], mx);
            float corr = __expf(mI[r] - mnew);
            float rs = 0.f;
#pragma unroll
            for (int c = 0; c < 4; c++) { float p = __expf(S[r][c] - mnew); S[r][c] = p; rs += p; }
#pragma unroll
            for (int o = 1; o < 16; o <<= 1) rs += __shfl_xor_sync(0xffffffffu, rs, o);
            lI[r] = lI[r] * corr + rs;
            mI[r] = mnew;
            u64 c2 = pack2(corr, corr);
#pragma unroll
            for (int c = 0; c < 4; c++) { u64 t; MUL2(t, O2[r][c], c2); O2[r][c] = t; }
        }

        // ---- P -> smem (reuse k_s as [row][j]), then O += P@V
#pragma unroll
        for (int r = 0; r < 4; r++) {
            int ii = ty + 16 * r;
#pragma unroll
            for (int c = 0; c < 4; c++) k_s[ii * ST66 + tx + 16 * c] = S[r][c];
        }
        __syncthreads();
#pragma unroll 4
        for (int j2 = 0; j2 < 64; j2 += 2) {
            u64 p2[4];
#pragma unroll
            for (int r = 0; r < 4; r++) p2[r] = ld64s(&k_s[(ty + 16 * r) * ST66 + j2]);
            u64 v2[4];
#pragma unroll
            for (int c = 0; c < 4; c++) v2[c] = ld64s(&v_s[(tx + 16 * c) * ST66 + j2]);
#pragma unroll
            for (int r = 0; r < 4; r++)
#pragma unroll
                for (int c = 0; c < 4; c++) FMA2(O2[r][c], p2[r], v2[c]);
        }
    }

#pragma unroll
    for (int r = 0; r < 4; r++) {
        int ii = ty + 16 * r;
        float inv = 1.f / lI[r];
#pragma unroll
        for (int c = 0; c < 4; c++) {
            float2 o = unpack2(O2[r][c]);
            out[qbase + (size_t)ii * H_ + tx + 16 * c] = (o.x + o.y) * inv;
        }
    }
}

// ---------------- fused residual-add + LayerNorm ----------------
__global__ __launch_bounds__(256)
void ln_kernel(const float* __restrict__ a, const float* __restrict__ b,
               const float* __restrict__ w, const float* __restrict__ beta,
               float* __restrict__ out)
{
    const int row = blockIdx.x;
    const int tid = threadIdx.x;
    const size_t base = (size_t)row * H_;
    float x0 = a[base + tid]       + b[base + tid];
    float x1 = a[base + tid + 256] + b[base + tid + 256];
    float s  = x0 + x1;
    float sq = x0 * x0 + x1 * x1;
#pragma unroll
    for (int o = 16; o > 0; o >>= 1) {
        s  += __shfl_xor_sync(0xffffffffu, s,  o);
        sq += __shfl_xor_sync(0xffffffffu, sq, o);
    }
    __shared__ float rs[8], rq[8];
    int wid = tid >> 5;
    if ((tid & 31) == 0) { rs[wid] = s; rq[wid] = sq; }
    __syncthreads();
    if (tid < 32) {
        float ss = (tid < 8) ? rs[tid] : 0.f;
        float qq = (tid < 8) ? rq[tid] : 0.f;
#pragma unroll
        for (int o = 4; o > 0; o >>= 1) {
            ss += __shfl_xor_sync(0xffffffffu, ss, o);
            qq += __shfl_xor_sync(0xffffffffu, qq, o);
        }
        if (tid == 0) { rs[0] = ss; rq[0] = qq; }
    }
    __syncthreads();
    float mean = rs[0] * (1.f / H_);
    float var  = rq[0] * (1.f / H_) - mean * mean;
    float inv  = rsqrtf(var + 1e-12f);
    out[base + tid]       = w[tid]       * (x0 - mean) * inv + beta[tid];
    out[base + tid + 256] = w[tid + 256] * (x1 - mean) * inv + beta[tid + 256];
}

// ---------------- launcher ----------------
extern "C" void kernel_launch(void* const* d_in, const int* in_sizes, int n_in,
                              void* d_out, int out_size)
{
    const float* x   = (const float*)d_in[0];
    const float* pe  = (const float*)d_in[1];
    const float* Wq  = (const float*)d_in[2];
    const float* bq  = (const float*)d_in[3];
    const float* Wk  = (const float*)d_in[4];
    const float* bk  = (const float*)d_in[5];
    const float* Wv  = (const float*)d_in[6];
    const float* bv  = (const float*)d_in[7];
    const float* Wr  = (const float*)d_in[8];
    const float* br  = (const float*)d_in[9];
    const float* cb  = (const float*)d_in[10];
    const float* pb  = (const float*)d_in[11];
    const float* Wc  = (const float*)d_in[12];
    const float* bc  = (const float*)d_in[13];
    const float* W1  = (const float*)d_in[14];
    const float* b1  = (const float*)d_in[15];
    const float* W2  = (const float*)d_in[16];
    const float* b2  = (const float*)d_in[17];
    const float* lnw = (const float*)d_in[18];
    const float* lnb = (const float*)d_in[19];
    float* out = (float*)d_out;

    float *qcP, *qpP, *kP, *vP, *rP, *attnP, *t1P, *aP, *h1P, *h2P;
    cudaGetSymbolAddress((void**)&qcP,   g_qc);
    cudaGetSymbolAddress((void**)&qpP,   g_qp);
    cudaGetSymbolAddress((void**)&kP,    g_k);
    cudaGetSymbolAddress((void**)&vP,    g_v);
    cudaGetSymbolAddress((void**)&rP,    g_r);
    cudaGetSymbolAddress((void**)&attnP, g_attn);
    cudaGetSymbolAddress((void**)&t1P,   g_t1);
    cudaGetSymbolAddress((void**)&aP,    g_a);
    cudaGetSymbolAddress((void**)&h1P,   g_h1);
    cudaGetSymbolAddress((void**)&h2P,   g_h2);

    const dim3 gBig(H_ / 128, M_ / 128);   // (4, 64)
    const dim3 gPos(H_ / 128, L_ / 128);   // (4, 16)

    gemm_kernel<MODE_NHD, EPI_QCQP><<<gBig, 256>>>(x,  Wq, bq, cb, pb, qcP, qpP, M_, H_, H_);
    gemm_kernel<MODE_NHD, EPI_BIAS><<<gBig, 256>>>(x,  Wk, bk, nullptr, nullptr, kP, nullptr, M_, H_, H_);
    gemm_kernel<MODE_NHD, EPI_BIAS><<<gBig, 256>>>(x,  Wv, bv, nullptr, nullptr, vP, nullptr, M_, H_, H_);
    gemm_kernel<MODE_NHD, EPI_BIAS><<<gPos, 256>>>(pe, Wr, br, nullptr, nullptr, rP, nullptr, L_, H_, H_);

    const int smemB = SMEM_FLOATS * (int)sizeof(float);   // 101376
    cudaFuncSetAttribute(attn_kernel, cudaFuncAttributeMaxDynamicSharedMemorySize, smemB);
    attn_kernel<<<dim3(L_ / 64, B_ * N_), 256, smemB>>>(qcP, qpP, kP, vP, rP, attnP);

    gemm_kernel<MODE_T, EPI_BIAS><<<gBig, 256>>>(attnP, Wc, bc, nullptr, nullptr, t1P, nullptr, M_, H_, H_);
    ln_kernel<<<M_, 256>>>(t1P, x, lnw, lnb, aP);

    gemm_kernel<MODE_T, EPI_GELU><<<gBig, 256>>>(aP,  W1, b1, nullptr, nullptr, h1P, nullptr, M_, H_, H_);
    gemm_kernel<MODE_T, EPI_BIAS><<<gBig, 256>>>(h1P, W2, b2, nullptr, nullptr, h2P, nullptr, M_, H_, H_);
    ln_kernel<<<M_, 256>>>(aP, h2P, lnw, lnb, out);
}

// round 4
// speedup vs baseline: 2.5007x; 2.2907x over previous
#include <cuda_runtime.h>
#include <math.h>
#include <stdint.h>

#define B_  4
#define L_  2048
#define H_  512
#define N_  8
#define D_  64
#define M_  (B_*L_)   // 8192 rows

// ---------------- scratch ----------------
__device__ float g_qc  [M_*H_];
__device__ float g_qp  [M_*H_];
__device__ float g_k   [M_*H_];
__device__ float g_v   [M_*H_];
__device__ float g_r   [L_*H_];
__device__ float g_attn[M_*H_];
__device__ float g_t1  [M_*H_];
__device__ float g_a   [M_*H_];
__device__ float g_h1  [M_*H_];
__device__ float g_h2  [M_*H_];

// ---------------- tf32 helpers ----------------
__device__ __forceinline__ float to_tf32(float x) {
    uint32_t u;
    asm("cvt.rna.tf32.f32 %0, %1;" : "=r"(u) : "f"(x));
    return __uint_as_float(u);
}
__device__ __forceinline__ uint32_t fbits(float x) { return __float_as_uint(x); }

// D(16x8) += A(16x8) * B(8x8), tf32 inputs, f32 accum
__device__ __forceinline__ void mma_tf32(float* c,
                                         uint32_t a0, uint32_t a1, uint32_t a2, uint32_t a3,
                                         uint32_t b0, uint32_t b1) {
    asm("mma.sync.aligned.m16n8k8.row.col.f32.tf32.tf32.f32 "
        "{%0,%1,%2,%3}, {%4,%5,%6,%7}, {%8,%9}, {%0,%1,%2,%3};"
        : "+f"(c[0]), "+f"(c[1]), "+f"(c[2]), "+f"(c[3])
        : "r"(a0), "r"(a1), "r"(a2), "r"(a3), "r"(b0), "r"(b1));
}

// ---------------- GEMM (tf32 tensor cores) ----------------
// C[M,N] = A[M,K] @ B + epilogue.  128x128 tile, 8 warps of 64x32.
enum { MODE_NHD = 0, MODE_T = 1 };
enum { EPI_BIAS = 0, EPI_QCQP = 1, EPI_GELU = 2 };

#define GST 136   // smem stride: bank = (8k + col) % 32 -> conflict-free frag loads

template<int MODE, int EPI>
__global__ __launch_bounds__(256)
void gemm_kernel(const float* __restrict__ A, const float* __restrict__ W,
                 const float* __restrict__ bias, const float* __restrict__ bias2,
                 const float* __restrict__ bias3,
                 float* __restrict__ out1, float* __restrict__ out2,
                 int M, int N, int K)
{
    __shared__ float As[16][GST];   // [k][row]
    __shared__ float Bs[16][GST];   // [k][col]
    const int tid  = threadIdx.x;
    const int lane = tid & 31;
    const int w    = tid >> 5;
    const int rw64 = (w >> 2) << 6;   // warp row base (0/64)
    const int cw32 = (w & 3) << 5;    // warp col base (0/32/64/96)
    const int m0 = blockIdx.y << 7, c0 = blockIdx.x << 7;
    const int lq = lane >> 2;         // 0..7
    const int lr = lane & 3;          // 0..3

    float C[4][4][4];
#pragma unroll
    for (int mt = 0; mt < 4; mt++)
#pragma unroll
        for (int nt = 0; nt < 4; nt++)
#pragma unroll
            for (int e = 0; e < 4; e++) C[mt][nt][e] = 0.f;

    for (int k0 = 0; k0 < K; k0 += 16) {
#pragma unroll
        for (int jj = 0; jj < 2; jj++) {
            int f   = tid + jj * 256;
            int row = f >> 2;
            int kq  = (f & 3) << 2;
            float4 a4 = *(const float4*)(A + (size_t)(m0 + row) * K + k0 + kq);
            As[kq + 0][row] = to_tf32(a4.x); As[kq + 1][row] = to_tf32(a4.y);
            As[kq + 2][row] = to_tf32(a4.z); As[kq + 3][row] = to_tf32(a4.w);
        }
        if (MODE == MODE_NHD) {
#pragma unroll
            for (int jj = 0; jj < 8; jj++) {
                int i  = tid + jj * 256;
                int kk = i >> 7, c = i & 127;
                int cc = c0 + c;
                Bs[kk][c] = to_tf32(W[(size_t)(cc >> 6) * ((size_t)K * 64)
                                      + (size_t)(k0 + kk) * 64 + (cc & 63)]);
            }
        } else {
#pragma unroll
            for (int jj = 0; jj < 8; jj++) {
                int i  = tid + jj * 256;
                int c  = i >> 4, kk = i & 15;
                Bs[kk][c] = to_tf32(W[(size_t)(c0 + c) * K + k0 + kk]);
            }
        }
        __syncthreads();
#pragma unroll
        for (int kc = 0; kc < 16; kc += 8) {
            uint32_t bf[4][2];
#pragma unroll
            for (int nt = 0; nt < 4; nt++) {
                int n = cw32 + 8 * nt + lq;
                bf[nt][0] = fbits(Bs[kc + lr][n]);
                bf[nt][1] = fbits(Bs[kc + 4 + lr][n]);
            }
#pragma unroll
            for (int mt = 0; mt < 4; mt++) {
                int i = rw64 + 16 * mt + lq;
                uint32_t a0 = fbits(As[kc + lr][i]);
                uint32_t a1 = fbits(As[kc + lr][i + 8]);
                uint32_t a2 = fbits(As[kc + 4 + lr][i]);
                uint32_t a3 = fbits(As[kc + 4 + lr][i + 8]);
#pragma unroll
                for (int nt = 0; nt < 4; nt++)
                    mma_tf32(C[mt][nt], a0, a1, a2, a3, bf[nt][0], bf[nt][1]);
            }
        }
        __syncthreads();
    }

#pragma unroll
    for (int mt = 0; mt < 4; mt++) {
        int m = m0 + rw64 + 16 * mt + lq;
#pragma unroll
        for (int nt = 0; nt < 4; nt++) {
            int c = c0 + cw32 + 8 * nt + 2 * lr;
            float b0 = bias[c], b1 = bias[c + 1];
            float v00 = C[mt][nt][0] + b0, v01 = C[mt][nt][1] + b1;   // row m
            float v10 = C[mt][nt][2] + b0, v11 = C[mt][nt][3] + b1;   // row m+8
            size_t o0 = (size_t)m * N + c;
            size_t o1 = o0 + (size_t)8 * N;
            if (EPI == EPI_BIAS) {
                *(float2*)(out1 + o0) = make_float2(v00, v01);
                *(float2*)(out1 + o1) = make_float2(v10, v11);
            } else if (EPI == EPI_QCQP) {
                float c20 = bias2[c], c21 = bias2[c + 1];
                float p20 = bias3[c], p21 = bias3[c + 1];
                *(float2*)(out1 + o0) = make_float2(v00 + c20, v01 + c21);
                *(float2*)(out1 + o1) = make_float2(v10 + c20, v11 + c21);
                *(float2*)(out2 + o0) = make_float2(v00 + p20, v01 + p21);
                *(float2*)(out2 + o1) = make_float2(v10 + p20, v11 + p21);
            } else {
                v00 = v00 * 0.5f * (1.f + erff(v00 * 0.70710678118654752f));
                v01 = v01 * 0.5f * (1.f + erff(v01 * 0.70710678118654752f));
                v10 = v10 * 0.5f * (1.f + erff(v10 * 0.70710678118654752f));
                v11 = v11 * 0.5f * (1.f + erff(v11 * 0.70710678118654752f));
                *(float2*)(out1 + o0) = make_float2(v00, v01);
                *(float2*)(out1 + o1) = make_float2(v10, v11);
            }
        }
    }
}

// ---------------- flash attention, tf32 tensor cores ----------------
#define AST 68    // stride for qc/qp/k/r/p: bank = 4*row + col
#define VST 72    // stride for v [j][d]:    bank = 8*j + d
#define SPST 136  // Spos stride

#define ATTN_SMEM_FLOATS (64*AST*3 + 64*VST + 128*AST + 64*SPST + 384)

__global__ __launch_bounds__(256, 1)
void attn_kernel(const float* __restrict__ qc, const float* __restrict__ qp,
                 const float* __restrict__ kmat, const float* __restrict__ vmat,
                 const float* __restrict__ rmat, float* __restrict__ out)
{
    extern __shared__ float sm[];
    float* qc_s = sm;                     // [i][d]   64 x AST
    float* qp_s = qc_s + 64 * AST;        // [i][d]
    float* k_s  = qp_s + 64 * AST;        // [j][d]
    float* v_s  = k_s  + 64 * AST;        // [j][d]   64 x VST
    float* r_s  = v_s  + 64 * VST;        // [u][d]  128 x AST
    float* sp_s = r_s  + 128 * AST;       // [i][u]   64 x SPST  (reused as P [i][j] stride AST)
    float* p_s  = sp_s;
    float* m_s  = sp_s + 64 * SPST;       // [64]
    float* l_s  = m_s + 64;               // [64]
    float* redm = l_s + 64;               // [2][64]
    float* reds = redm + 128;             // [2][64]

    const int tid  = threadIdx.x;
    const int lane = tid & 31;
    const int w    = tid >> 5;
    const int rw   = (w & 3) << 4;        // warp row base (0/16/32/48)
    const int cw2  = w >> 2;              // col half (0/1)
    const int lq = lane >> 2, lr = lane & 3;

    const int bh = blockIdx.y;
    const int b  = bh >> 3, n = bh & 7;
    const int i0 = ((int)gridDim.x - 1 - (int)blockIdx.x) << 6;   // heavy tiles first
    const int col = n << 6;
    const size_t qbase = ((size_t)(b * L_) + i0) * H_ + col;

    if (tid < 64) { m_s[tid] = -INFINITY; l_s[tid] = 0.f; }

    // persistent query tiles (tf32)
#pragma unroll
    for (int jj = 0; jj < 4; jj++) {
        int f = tid + jj * 256;
        int row = f >> 4, cq = (f & 15) << 2;
        float4 a = *(const float4*)(qc + qbase + (size_t)row * H_ + cq);
        qc_s[row * AST + cq + 0] = to_tf32(a.x); qc_s[row * AST + cq + 1] = to_tf32(a.y);
        qc_s[row * AST + cq + 2] = to_tf32(a.z); qc_s[row * AST + cq + 3] = to_tf32(a.w);
        float4 p = *(const float4*)(qp + qbase + (size_t)row * H_ + cq);
        qp_s[row * AST + cq + 0] = to_tf32(p.x); qp_s[row * AST + cq + 1] = to_tf32(p.y);
        qp_s[row * AST + cq + 2] = to_tf32(p.z); qp_s[row * AST + cq + 3] = to_tf32(p.w);
    }

    float O[4][4];
#pragma unroll
    for (int nt = 0; nt < 4; nt++)
#pragma unroll
        for (int e = 0; e < 4; e++) O[nt][e] = 0.f;

    const int ia = rw + lq, ib = ia + 8;

    for (int j0 = 0; j0 <= i0; j0 += 64) {
        __syncthreads();   // previous iteration's smem reads complete
        const size_t kb = ((size_t)(b * L_) + j0) * H_ + col;
#pragma unroll
        for (int jj = 0; jj < 4; jj++) {
            int f = tid + jj * 256;
            int row = f >> 4, cq = (f & 15) << 2;
            float4 a = *(const float4*)(kmat + kb + (size_t)row * H_ + cq);
            k_s[row * AST + cq + 0] = to_tf32(a.x); k_s[row * AST + cq + 1] = to_tf32(a.y);
            k_s[row * AST + cq + 2] = to_tf32(a.z); k_s[row * AST + cq + 3] = to_tf32(a.w);
            float4 vv = *(const float4*)(vmat + kb + (size_t)row * H_ + cq);
            v_s[row * VST + cq + 0] = to_tf32(vv.x); v_s[row * VST + cq + 1] = to_tf32(vv.y);
            v_s[row * VST + cq + 2] = to_tf32(vv.z); v_s[row * VST + cq + 3] = to_tf32(vv.w);
        }
        const int pbase = (L_ - 64) + j0 - i0;
#pragma unroll
        for (int jj = 0; jj < 8; jj++) {
            int f = tid + jj * 256;
            int row = f >> 4, cq = (f & 15) << 2;
            int p = pbase + row;
            if (p < L_) {
                float4 a = *(const float4*)(rmat + (size_t)p * H_ + col + cq);
                r_s[row * AST + cq + 0] = to_tf32(a.x); r_s[row * AST + cq + 1] = to_tf32(a.y);
                r_s[row * AST + cq + 2] = to_tf32(a.z); r_s[row * AST + cq + 3] = to_tf32(a.w);
            } else {
                r_s[row * AST + cq + 0] = 0.f; r_s[row * AST + cq + 1] = 0.f;
                r_s[row * AST + cq + 2] = 0.f; r_s[row * AST + cq + 3] = 0.f;
            }
        }
        __syncthreads();

        // ---- S = qc @ k^T  (warp: rows rw..rw+15, cols 32*cw2..+31)
        float S[4][4];
#pragma unroll
        for (int nt = 0; nt < 4; nt++)
#pragma unroll
            for (int e = 0; e < 4; e++) S[nt][e] = 0.f;
#pragma unroll
        for (int kc = 0; kc < 64; kc += 8) {
            uint32_t a0 = fbits(qc_s[ia * AST + kc + lr]);
            uint32_t a1 = fbits(qc_s[ib * AST + kc + lr]);
            uint32_t a2 = fbits(qc_s[ia * AST + kc + 4 + lr]);
            uint32_t a3 = fbits(qc_s[ib * AST + kc + 4 + lr]);
#pragma unroll
            for (int nt = 0; nt < 4; nt++) {
                int nn = (cw2 << 5) + 8 * nt + lq;
                uint32_t b0 = fbits(k_s[nn * AST + kc + lr]);
                uint32_t b1 = fbits(k_s[nn * AST + kc + 4 + lr]);
                mma_tf32(S[nt], a0, a1, a2, a3, b0, b1);
            }
        }
        // ---- Sp = qp @ r^T  (warp: rows rw..rw+15, cols 64*cw2..+63)
        float SP[8][4];
#pragma unroll
        for (int nt = 0; nt < 8; nt++)
#pragma unroll
            for (int e = 0; e < 4; e++) SP[nt][e] = 0.f;
#pragma unroll
        for (int kc = 0; kc < 64; kc += 8) {
            uint32_t a0 = fbits(qp_s[ia * AST + kc + lr]);
            uint32_t a1 = fbits(qp_s[ib * AST + kc + lr]);
            uint32_t a2 = fbits(qp_s[ia * AST + kc + 4 + lr]);
            uint32_t a3 = fbits(qp_s[ib * AST + kc + 4 + lr]);
#pragma unroll
            for (int nt = 0; nt < 8; nt++) {
                int nn = (cw2 << 6) + 8 * nt + lq;
                uint32_t b0 = fbits(r_s[nn * AST + kc + lr]);
                uint32_t b1 = fbits(r_s[nn * AST + kc + 4 + lr]);
                mma_tf32(SP[nt], a0, a1, a2, a3, b0, b1);
            }
        }
        // Spos -> smem
#pragma unroll
        for (int nt = 0; nt < 8; nt++) {
            int cc = (cw2 << 6) + 8 * nt + 2 * lr;
            *(float2*)&sp_s[ia * SPST + cc] = make_float2(SP[nt][0], SP[nt][1]);
            *(float2*)&sp_s[ib * SPST + cc] = make_float2(SP[nt][2], SP[nt][3]);
        }
        __syncthreads();

        // ---- shift + scale + mask
        const bool diag = (j0 == i0);
#pragma unroll
        for (int nt = 0; nt < 4; nt++) {
            int jbase = (cw2 << 5) + 8 * nt + 2 * lr;
#pragma unroll
            for (int e = 0; e < 4; e++) {
                int iloc = (e >= 2) ? ib : ia;
                int jloc = jbase + (e & 1);
                float s = (S[nt][e] + sp_s[iloc * SPST + 63 + jloc - iloc]) * 0.125f;
                if (diag && jloc > iloc) s = -1e30f;
                S[nt][e] = s;
            }
        }

        // ---- row max (two col halves via smem)
        float ma = -INFINITY, mb = -INFINITY;
#pragma unroll
        for (int nt = 0; nt < 4; nt++) {
            ma = fmaxf(ma, fmaxf(S[nt][0], S[nt][1]));
            mb = fmaxf(mb, fmaxf(S[nt][2], S[nt][3]));
        }
        ma = fmaxf(ma, __shfl_xor_sync(0xffffffffu, ma, 1));
        ma = fmaxf(ma, __shfl_xor_sync(0xffffffffu, ma, 2));
        mb = fmaxf(mb, __shfl_xor_sync(0xffffffffu, mb, 1));
        mb = fmaxf(mb, __shfl_xor_sync(0xffffffffu, mb, 2));
        if (lr == 0) { redm[cw2 * 64 + ia] = ma; redm[cw2 * 64 + ib] = mb; }
        __syncthreads();

        float moa = m_s[ia], mob = m_s[ib];
        float mna = fmaxf(moa, fmaxf(redm[ia], redm[64 + ia]));
        float mnb = fmaxf(mob, fmaxf(redm[ib], redm[64 + ib]));
        float ca = __expf(moa - mna), cb = __expf(mob - mnb);

        float sa = 0.f, sb = 0.f;
#pragma unroll
        for (int nt = 0; nt < 4; nt++) {
            float p0 = __expf(S[nt][0] - mna);
            float p1 = __expf(S[nt][1] - mna);
            float p2 = __expf(S[nt][2] - mnb);
            float p3 = __expf(S[nt][3] - mnb);
            sa += p0 + p1; sb += p2 + p3;
            S[nt][0] = to_tf32(p0); S[nt][1] = to_tf32(p1);
            S[nt][2] = to_tf32(p2); S[nt][3] = to_tf32(p3);
        }
        sa += __shfl_xor_sync(0xffffffffu, sa, 1);
        sa += __shfl_xor_sync(0xffffffffu, sa, 2);
        sb += __shfl_xor_sync(0xffffffffu, sb, 1);
        sb += __shfl_xor_sync(0xffffffffu, sb, 2);
        if (lr == 0) { reds[cw2 * 64 + ia] = sa; reds[cw2 * 64 + ib] = sb; }
        // P -> smem (overlays sp region; all sp reads completed before last sync)
#pragma unroll
        for (int nt = 0; nt < 4; nt++) {
            int cc = (cw2 << 5) + 8 * nt + 2 * lr;
            *(float2*)&p_s[ia * AST + cc] = make_float2(S[nt][0], S[nt][1]);
            *(float2*)&p_s[ib * AST + cc] = make_float2(S[nt][2], S[nt][3]);
        }
        __syncthreads();

        if (cw2 == 0 && lr == 0) {
            l_s[ia] = l_s[ia] * ca + reds[ia] + reds[64 + ia];
            l_s[ib] = l_s[ib] * cb + reds[ib] + reds[64 + ib];
            m_s[ia] = mna; m_s[ib] = mnb;
        }
        // rescale O
#pragma unroll
        for (int nt = 0; nt < 4; nt++) {
            O[nt][0] *= ca; O[nt][1] *= ca;
            O[nt][2] *= cb; O[nt][3] *= cb;
        }
        // ---- O += P @ V  (warp: rows rw.., d-cols 32*cw2..+31)
#pragma unroll
        for (int kc = 0; kc < 64; kc += 8) {
            uint32_t a0 = fbits(p_s[ia * AST + kc + lr]);
            uint32_t a1 = fbits(p_s[ib * AST + kc + lr]);
            uint32_t a2 = fbits(p_s[ia * AST + kc + 4 + lr]);
            uint32_t a3 = fbits(p_s[ib * AST + kc + 4 + lr]);
#pragma unroll
            for (int nt = 0; nt < 4; nt++) {
                int nn = (cw2 << 5) + 8 * nt + lq;
                uint32_t b0 = fbits(v_s[(kc + lr) * VST + nn]);
                uint32_t b1 = fbits(v_s[(kc + 4 + lr) * VST + nn]);
                mma_tf32(O[nt], a0, a1, a2, a3, b0, b1);
            }
        }
    }

    __syncthreads();   // final l_s update visible
    float la = 1.f / l_s[ia];
    float lb = 1.f / l_s[ib];
#pragma unroll
    for (int nt = 0; nt < 4; nt++) {
        int cc = (cw2 << 5) + 8 * nt + 2 * lr;
        *(float2*)(out + qbase + (size_t)ia * H_ + cc) = make_float2(O[nt][0] * la, O[nt][1] * la);
        *(float2*)(out + qbase + (size_t)ib * H_ + cc) = make_float2(O[nt][2] * lb, O[nt][3] * lb);
    }
}

// ---------------- fused residual-add + LayerNorm ----------------
__global__ __launch_bounds__(256)
void ln_kernel(const float* __restrict__ a, const float* __restrict__ b,
               const float* __restrict__ w, const float* __restrict__ beta,
               float* __restrict__ out)
{
    const int row = blockIdx.x;
    const int tid = threadIdx.x;
    const size_t base = (size_t)row * H_;
    float x0 = a[base + tid]       + b[base + tid];
    float x1 = a[base + tid + 256] + b[base + tid + 256];
    float s  = x0 + x1;
    float sq = x0 * x0 + x1 * x1;
#pragma unroll
    for (int o = 16; o > 0; o >>= 1) {
        s  += __shfl_xor_sync(0xffffffffu, s,  o);
        sq += __shfl_xor_sync(0xffffffffu, sq, o);
    }
    __shared__ float rs[8], rq[8];
    int wid = tid >> 5;
    if ((tid & 31) == 0) { rs[wid] = s; rq[wid] = sq; }
    __syncthreads();
    if (tid < 32) {
        float ss = (tid < 8) ? rs[tid] : 0.f;
        float qq = (tid < 8) ? rq[tid] : 0.f;
#pragma unroll
        for (int o = 4; o > 0; o >>= 1) {
            ss += __shfl_xor_sync(0xffffffffu, ss, o);
            qq += __shfl_xor_sync(0xffffffffu, qq, o);
        }
        if (tid == 0) { rs[0] = ss; rq[0] = qq; }
    }
    __syncthreads();
    float mean = rs[0] * (1.f / H_);
    float var  = rq[0] * (1.f / H_) - mean * mean;
    float inv  = rsqrtf(var + 1e-12f);
    out[base + tid]       = w[tid]       * (x0 - mean) * inv + beta[tid];
    out[base + tid + 256] = w[tid + 256] * (x1 - mean) * inv + beta[tid + 256];
}

// ---------------- launcher ----------------
extern "C" void kernel_launch(void* const* d_in, const int* in_sizes, int n_in,
                              void* d_out, int out_size)
{
    const float* x   = (const float*)d_in[0];
    const float* pe  = (const float*)d_in[1];
    const float* Wq  = (const float*)d_in[2];
    const float* bq  = (const float*)d_in[3];
    const float* Wk  = (const float*)d_in[4];
    const float* bk  = (const float*)d_in[5];
    const float* Wv  = (const float*)d_in[6];
    const float* bv  = (const float*)d_in[7];
    const float* Wr  = (const float*)d_in[8];
    const float* br  = (const float*)d_in[9];
    const float* cb  = (const float*)d_in[10];
    const float* pb  = (const float*)d_in[11];
    const float* Wc  = (const float*)d_in[12];
    const float* bc  = (const float*)d_in[13];
    const float* W1  = (const float*)d_in[14];
    const float* b1  = (const float*)d_in[15];
    const float* W2  = (const float*)d_in[16];
    const float* b2  = (const float*)d_in[17];
    const float* lnw = (const float*)d_in[18];
    const float* lnb = (const float*)d_in[19];
    float* out = (float*)d_out;

    float *qcP, *qpP, *kP, *vP, *rP, *attnP, *t1P, *aP, *h1P, *h2P;
    cudaGetSymbolAddress((void**)&qcP,   g_qc);
    cudaGetSymbolAddress((void**)&qpP,   g_qp);
    cudaGetSymbolAddress((void**)&kP,    g_k);
    cudaGetSymbolAddress((void**)&vP,    g_v);
    cudaGetSymbolAddress((void**)&rP,    g_r);
    cudaGetSymbolAddress((void**)&attnP, g_attn);
    cudaGetSymbolAddress((void**)&t1P,   g_t1);
    cudaGetSymbolAddress((void**)&aP,    g_a);
    cudaGetSymbolAddress((void**)&h1P,   g_h1);
    cudaGetSymbolAddress((void**)&h2P,   g_h2);

    const dim3 gBig(H_ / 128, M_ / 128);   // (4, 64)
    const dim3 gPos(H_ / 128, L_ / 128);   // (4, 16)

    gemm_kernel<MODE_NHD, EPI_QCQP><<<gBig, 256>>>(x,  Wq, bq, cb, pb, qcP, qpP, M_, H_, H_);
    gemm_kernel<MODE_NHD, EPI_BIAS><<<gBig, 256>>>(x,  Wk, bk, nullptr, nullptr, kP, nullptr, M_, H_, H_);
    gemm_kernel<MODE_NHD, EPI_BIAS><<<gBig, 256>>>(x,  Wv, bv, nullptr, nullptr, vP, nullptr, M_, H_, H_);
    gemm_kernel<MODE_NHD, EPI_BIAS><<<gPos, 256>>>(pe, Wr, br, nullptr, nullptr, rP, nullptr, L_, H_, H_);

    const int smemB = ATTN_SMEM_FLOATS * (int)sizeof(float);   // 141824
    cudaFuncSetAttribute(attn_kernel, cudaFuncAttributeMaxDynamicSharedMemorySize, smemB);
    attn_kernel<<<dim3(L_ / 64, B_ * N_), 256, smemB>>>(qcP, qpP, kP, vP, rP, attnP);

    gemm_kernel<MODE_T, EPI_BIAS><<<gBig, 256>>>(attnP, Wc, bc, nullptr, nullptr, t1P, nullptr, M_, H_, H_);
    ln_kernel<<<M_, 256>>>(t1P, x, lnw, lnb, aP);

    gemm_kernel<MODE_T, EPI_GELU><<<gBig, 256>>>(aP,  W1, b1, nullptr, nullptr, h1P, nullptr, M_, H_, H_);
    gemm_kernel<MODE_T, EPI_BIAS><<<gBig, 256>>>(h1P, W2, b2, nullptr, nullptr, h2P, nullptr, M_, H_, H_);
    ln_kernel<<<M_, 256>>>(aP, h2P, lnw, lnb, out);
}

// round 7
// speedup vs baseline: 2.9223x; 1.1686x over previous
#include <cuda_runtime.h>
#include <cuda_bf16.h>
#include <math.h>
#include <stdint.h>

#define B_  4
#define L_  2048
#define H_  512
#define N_  8
#define D_  64
#define M_  (B_*L_)   // 8192 rows

// ---------------- scratch ----------------
__device__ float g_qc  [M_*H_];
__device__ float g_qp  [M_*H_];
__device__ float g_k   [M_*H_];
__device__ float g_v   [M_*H_];
__device__ float g_r   [L_*H_];
__device__ float g_attn[M_*H_];
__device__ float g_t1  [M_*H_];
__device__ float g_a   [M_*H_];
__device__ float g_h1  [M_*H_];
__device__ float g_h2  [M_*H_];

// ---------------- helpers ----------------
__device__ __forceinline__ float to_tf32(float x) {
    uint32_t u;
    asm("cvt.rna.tf32.f32 %0, %1;" : "=r"(u) : "f"(x));
    return __uint_as_float(u);
}
__device__ __forceinline__ uint32_t fbits(float x) { return __float_as_uint(x); }
__device__ __forceinline__ uint32_t bf2(float x, float y) {
    __nv_bfloat162 t = __floats2bfloat162_rn(x, y);
    return *(uint32_t*)&t;
}

// tf32: D(16x8) += A(16x8) * B(8x8)
__device__ __forceinline__ void mma_tf32(float* c,
                                         uint32_t a0, uint32_t a1, uint32_t a2, uint32_t a3,
                                         uint32_t b0, uint32_t b1) {
    asm("mma.sync.aligned.m16n8k8.row.col.f32.tf32.tf32.f32 "
        "{%0,%1,%2,%3}, {%4,%5,%6,%7}, {%8,%9}, {%0,%1,%2,%3};"
        : "+f"(c[0]), "+f"(c[1]), "+f"(c[2]), "+f"(c[3])
        : "r"(a0), "r"(a1), "r"(a2), "r"(a3), "r"(b0), "r"(b1));
}
// bf16: D(16x8) += A(16x16) * B(16x8)
__device__ __forceinline__ void mma_bf16(float* c,
                                         uint32_t a0, uint32_t a1, uint32_t a2, uint32_t a3,
                                         uint32_t b0, uint32_t b1) {
    asm("mma.sync.aligned.m16n8k16.row.col.f32.bf16.bf16.f32 "
        "{%0,%1,%2,%3}, {%4,%5,%6,%7}, {%8,%9}, {%0,%1,%2,%3};"
        : "+f"(c[0]), "+f"(c[1]), "+f"(c[2]), "+f"(c[3])
        : "r"(a0), "r"(a1), "r"(a2), "r"(a3), "r"(b0), "r"(b1));
}

// ---------------- GEMM (tf32 tensor cores) ----------------
enum { MODE_NHD = 0, MODE_T = 1 };
enum { EPI_BIAS = 0, EPI_QCQP = 1, EPI_GELU = 2 };

#define GST 136

template<int MODE, int EPI>
__global__ __launch_bounds__(256)
void gemm_kernel(const float* __restrict__ A, const float* __restrict__ W,
                 const float* __restrict__ bias, const float* __restrict__ bias2,
                 const float* __restrict__ bias3,
                 float* __restrict__ out1, float* __restrict__ out2,
                 int M, int N, int K)
{
    __shared__ float As[16][GST];
    __shared__ float Bs[16][GST];
    const int tid  = threadIdx.x;
    const int lane = tid & 31;
    const int w    = tid >> 5;
    const int rw64 = (w >> 2) << 6;
    const int cw32 = (w & 3) << 5;
    const int m0 = blockIdx.y << 7, c0 = blockIdx.x << 7;
    const int lq = lane >> 2;
    const int lr = lane & 3;

    float C[4][4][4];
#pragma unroll
    for (int mt = 0; mt < 4; mt++)
#pragma unroll
        for (int nt = 0; nt < 4; nt++)
#pragma unroll
            for (int e = 0; e < 4; e++) C[mt][nt][e] = 0.f;

    for (int k0 = 0; k0 < K; k0 += 16) {
#pragma unroll
        for (int jj = 0; jj < 2; jj++) {
            int f   = tid + jj * 256;
            int row = f >> 2;
            int kq  = (f & 3) << 2;
            float4 a4 = *(const float4*)(A + (size_t)(m0 + row) * K + k0 + kq);
            As[kq + 0][row] = to_tf32(a4.x); As[kq + 1][row] = to_tf32(a4.y);
            As[kq + 2][row] = to_tf32(a4.z); As[kq + 3][row] = to_tf32(a4.w);
        }
        if (MODE == MODE_NHD) {
#pragma unroll
            for (int jj = 0; jj < 8; jj++) {
                int i  = tid + jj * 256;
                int kk = i >> 7, c = i & 127;
                int cc = c0 + c;
                Bs[kk][c] = to_tf32(W[(size_t)(cc >> 6) * ((size_t)K * 64)
                                      + (size_t)(k0 + kk) * 64 + (cc & 63)]);
            }
        } else {
#pragma unroll
            for (int jj = 0; jj < 8; jj++) {
                int i  = tid + jj * 256;
                int c  = i >> 4, kk = i & 15;
                Bs[kk][c] = to_tf32(W[(size_t)(c0 + c) * K + k0 + kk]);
            }
        }
        __syncthreads();
#pragma unroll
        for (int kc = 0; kc < 16; kc += 8) {
            uint32_t bf[4][2];
#pragma unroll
            for (int nt = 0; nt < 4; nt++) {
                int n = cw32 + 8 * nt + lq;
                bf[nt][0] = fbits(Bs[kc + lr][n]);
                bf[nt][1] = fbits(Bs[kc + 4 + lr][n]);
            }
#pragma unroll
            for (int mt = 0; mt < 4; mt++) {
                int i = rw64 + 16 * mt + lq;
                uint32_t a0 = fbits(As[kc + lr][i]);
                uint32_t a1 = fbits(As[kc + lr][i + 8]);
                uint32_t a2 = fbits(As[kc + 4 + lr][i]);
                uint32_t a3 = fbits(As[kc + 4 + lr][i + 8]);
#pragma unroll
                for (int nt = 0; nt < 4; nt++)
                    mma_tf32(C[mt][nt], a0, a1, a2, a3, bf[nt][0], bf[nt][1]);
            }
        }
        __syncthreads();
    }

#pragma unroll
    for (int mt = 0; mt < 4; mt++) {
        int m = m0 + rw64 + 16 * mt + lq;
#pragma unroll
        for (int nt = 0; nt < 4; nt++) {
            int c = c0 + cw32 + 8 * nt + 2 * lr;
            float b0 = bias[c], b1 = bias[c + 1];
            float v00 = C[mt][nt][0] + b0, v01 = C[mt][nt][1] + b1;
            float v10 = C[mt][nt][2] + b0, v11 = C[mt][nt][3] + b1;
            size_t o0 = (size_t)m * N + c;
            size_t o1 = o0 + (size_t)8 * N;
            if (EPI == EPI_BIAS) {
                *(float2*)(out1 + o0) = make_float2(v00, v01);
                *(float2*)(out1 + o1) = make_float2(v10, v11);
            } else if (EPI == EPI_QCQP) {
                float c20 = bias2[c], c21 = bias2[c + 1];
                float p20 = bias3[c], p21 = bias3[c + 1];
                *(float2*)(out1 + o0) = make_float2(v00 + c20, v01 + c21);
                *(float2*)(out1 + o1) = make_float2(v10 + c20, v11 + c21);
                *(float2*)(out2 + o0) = make_float2(v00 + p20, v01 + p21);
                *(float2*)(out2 + o1) = make_float2(v10 + p20, v11 + p21);
            } else {
                v00 = v00 * 0.5f * (1.f + erff(v00 * 0.70710678118654752f));
                v01 = v01 * 0.5f * (1.f + erff(v01 * 0.70710678118654752f));
                v10 = v10 * 0.5f * (1.f + erff(v10 * 0.70710678118654752f));
                v11 = v11 * 0.5f * (1.f + erff(v11 * 0.70710678118654752f));
                *(float2*)(out1 + o0) = make_float2(v00, v01);
                *(float2*)(out1 + o1) = make_float2(v10, v11);
            }
        }
    }
}

// ---------------- flash attention, bf16 tensor cores ----------------
// bf16 tiles stored as uint32 words (2 bf16), row stride 36 words (72 elems)
// -> word-bank pattern 4*row+lr is conflict-free for mma fragment loads.
#define WST 36
#define SPST 136
// smem words: qc,qp,k,vt: 4*2304; r: 4608; sp: 8704(f32); p: 2304; stats: 384
#define ATTN_SMEM_BYTES ((2304*4 + 4608 + 2304) * 4 + 8704 * 4 + 384 * 4)  // 100864

__global__ __launch_bounds__(256, 2)
void attn_kernel(const float* __restrict__ qc, const float* __restrict__ qp,
                 const float* __restrict__ kmat, const float* __restrict__ vmat,
                 const float* __restrict__ rmat, float* __restrict__ out)
{
    extern __shared__ char smraw[];
    uint32_t* qc32 = (uint32_t*)smraw;        // [i][dw]   64 x 36
    uint32_t* qp32 = qc32 + 64 * WST;
    uint32_t* k32  = qp32 + 64 * WST;         // [j][dw]
    uint32_t* vt32 = k32  + 64 * WST;         // [d][jw]   (transposed)
    uint32_t* r32  = vt32 + 64 * WST;         // [u][dw]  128 x 36
    float*    sp_s = (float*)(r32 + 128 * WST);   // [i][u] 64 x 136 fp32
    uint32_t* p32  = (uint32_t*)(sp_s + 64 * SPST); // [i][jw] 64 x 36
    float*    m_s  = (float*)(p32 + 64 * WST);
    float*    l_s  = m_s + 64;
    float*    redm = l_s + 64;                // [2][64]
    float*    reds = redm + 128;              // [2][64]

    __nv_bfloat16* vt16 = (__nv_bfloat16*)vt32;

    const int tid  = threadIdx.x;
    const int lane = tid & 31;
    const int w    = tid >> 5;
    const int rw   = (w & 3) << 4;
    const int cw2  = w >> 2;
    const int lq = lane >> 2, lr = lane & 3;

    const int bh = blockIdx.y;
    const int b  = bh >> 3, n = bh & 7;
    const int i0 = ((int)gridDim.x - 1 - (int)blockIdx.x) << 6;
    const int col = n << 6;
    const size_t qbase = ((size_t)(b * L_) + i0) * H_ + col;

    if (tid < 64) { m_s[tid] = -INFINITY; l_s[tid] = 0.f; }

    // persistent query tiles -> bf16
#pragma unroll
    for (int jj = 0; jj < 4; jj++) {
        int f = tid + jj * 256;
        int row = f >> 4, cq = (f & 15) << 2;
        float4 a = *(const float4*)(qc + qbase + (size_t)row * H_ + cq);
        qc32[row * WST + (cq >> 1)]     = bf2(a.x, a.y);
        qc32[row * WST + (cq >> 1) + 1] = bf2(a.z, a.w);
        float4 p = *(const float4*)(qp + qbase + (size_t)row * H_ + cq);
        qp32[row * WST + (cq >> 1)]     = bf2(p.x, p.y);
        qp32[row * WST + (cq >> 1) + 1] = bf2(p.z, p.w);
    }

    float O[4][4];
#pragma unroll
    for (int nt = 0; nt < 4; nt++)
#pragma unroll
        for (int e = 0; e < 4; e++) O[nt][e] = 0.f;

    const int ia = rw + lq, ib = ia + 8;

    for (int j0 = 0; j0 <= i0; j0 += 64) {
        __syncthreads();
        const size_t kb = ((size_t)(b * L_) + j0) * H_ + col;
#pragma unroll
        for (int jj = 0; jj < 4; jj++) {
            int f = tid + jj * 256;
            int row = f >> 4, cq = (f & 15) << 2;
            float4 a = *(const float4*)(kmat + kb + (size_t)row * H_ + cq);
            k32[row * WST + (cq >> 1)]     = bf2(a.x, a.y);
            k32[row * WST + (cq >> 1) + 1] = bf2(a.z, a.w);
            float4 vv = *(const float4*)(vmat + kb + (size_t)row * H_ + cq);
            vt16[(cq + 0) * 72 + row] = __float2bfloat16_rn(vv.x);
            vt16[(cq + 1) * 72 + row] = __float2bfloat16_rn(vv.y);
            vt16[(cq + 2) * 72 + row] = __float2bfloat16_rn(vv.z);
            vt16[(cq + 3) * 72 + row] = __float2bfloat16_rn(vv.w);
        }
        const int pbase = (L_ - 64) + j0 - i0;
#pragma unroll
        for (int jj = 0; jj < 8; jj++) {
            int f = tid + jj * 256;
            int row = f >> 4, cq = (f & 15) << 2;
            int p = pbase + row;
            if (p < L_) {
                float4 a = *(const float4*)(rmat + (size_t)p * H_ + col + cq);
                r32[row * WST + (cq >> 1)]     = bf2(a.x, a.y);
                r32[row * WST + (cq >> 1) + 1] = bf2(a.z, a.w);
            } else {
                r32[row * WST + (cq >> 1)]     = 0u;
                r32[row * WST + (cq >> 1) + 1] = 0u;
            }
        }
        __syncthreads();

        // ---- S = qc @ k^T (16x32 per warp), k16 steps
        float S[4][4];
#pragma unroll
        for (int nt = 0; nt < 4; nt++)
#pragma unroll
            for (int e = 0; e < 4; e++) S[nt][e] = 0.f;
#pragma unroll
        for (int kq = 0; kq < 32; kq += 8) {
            uint32_t a0 = qc32[ia * WST + kq + lr];
            uint32_t a1 = qc32[ib * WST + kq + lr];
            uint32_t a2 = qc32[ia * WST + kq + 4 + lr];
            uint32_t a3 = qc32[ib * WST + kq + 4 + lr];
#pragma unroll
            for (int nt = 0; nt < 4; nt++) {
                int nn = (cw2 << 5) + 8 * nt + lq;
                mma_bf16(S[nt], a0, a1, a2, a3,
                         k32[nn * WST + kq + lr], k32[nn * WST + kq + 4 + lr]);
            }
        }
        // ---- Sp = qp @ r^T (16x64 per warp over 128-band)
        float SP[8][4];
#pragma unroll
        for (int nt = 0; nt < 8; nt++)
#pragma unroll
            for (int e = 0; e < 4; e++) SP[nt][e] = 0.f;
#pragma unroll
        for (int kq = 0; kq < 32; kq += 8) {
            uint32_t a0 = qp32[ia * WST + kq + lr];
            uint32_t a1 = qp32[ib * WST + kq + lr];
            uint32_t a2 = qp32[ia * WST + kq + 4 + lr];
            uint32_t a3 = qp32[ib * WST + kq + 4 + lr];
#pragma unroll
            for (int nt = 0; nt < 8; nt++) {
                int nn = (cw2 << 6) + 8 * nt + lq;
                mma_bf16(SP[nt], a0, a1, a2, a3,
                         r32[nn * WST + kq + lr], r32[nn * WST + kq + 4 + lr]);
            }
        }
#pragma unroll
        for (int nt = 0; nt < 8; nt++) {
            int cc = (cw2 << 6) + 8 * nt + 2 * lr;
            *(float2*)&sp_s[ia * SPST + cc] = make_float2(SP[nt][0], SP[nt][1]);
            *(float2*)&sp_s[ib * SPST + cc] = make_float2(SP[nt][2], SP[nt][3]);
        }
        __syncthreads();

        // ---- shift + scale + mask
        const bool diag = (j0 == i0);
#pragma unroll
        for (int nt = 0; nt < 4; nt++) {
            int jbase = (cw2 << 5) + 8 * nt + 2 * lr;
#pragma unroll
            for (int e = 0; e < 4; e++) {
                int iloc = (e >= 2) ? ib : ia;
                int jloc = jbase + (e & 1);
                float s = (S[nt][e] + sp_s[iloc * SPST + 63 + jloc - iloc]) * 0.125f;
                if (diag && jloc > iloc) s = -1e30f;
                S[nt][e] = s;
            }
        }

        // ---- row max across two col halves
        float ma = -INFINITY, mb = -INFINITY;
#pragma unroll
        for (int nt = 0; nt < 4; nt++) {
            ma = fmaxf(ma, fmaxf(S[nt][0], S[nt][1]));
            mb = fmaxf(mb, fmaxf(S[nt][2], S[nt][3]));
        }
        ma = fmaxf(ma, __shfl_xor_sync(0xffffffffu, ma, 1));
        ma = fmaxf(ma, __shfl_xor_sync(0xffffffffu, ma, 2));
        mb = fmaxf(mb, __shfl_xor_sync(0xffffffffu, mb, 1));
        mb = fmaxf(mb, __shfl_xor_sync(0xffffffffu, mb, 2));
        if (lr == 0) { redm[cw2 * 64 + ia] = ma; redm[cw2 * 64 + ib] = mb; }
        __syncthreads();

        float moa = m_s[ia], mob = m_s[ib];
        float mna = fmaxf(moa, fmaxf(redm[ia], redm[64 + ia]));
        float mnb = fmaxf(mob, fmaxf(redm[ib], redm[64 + ib]));
        float ca = __expf(moa - mna), cb = __expf(mob - mnb);

        float sa = 0.f, sb = 0.f;
#pragma unroll
        for (int nt = 0; nt < 4; nt++) {
            float p0 = __expf(S[nt][0] - mna);
            float p1 = __expf(S[nt][1] - mna);
            float p2 = __expf(S[nt][2] - mnb);
            float p3 = __expf(S[nt][3] - mnb);
            sa += p0 + p1; sb += p2 + p3;
            int ccw = (cw2 << 4) + 4 * nt + lr;
            p32[ia * WST + ccw] = bf2(p0, p1);
            p32[ib * WST + ccw] = bf2(p2, p3);
        }
        sa += __shfl_xor_sync(0xffffffffu, sa, 1);
        sa += __shfl_xor_sync(0xffffffffu, sa, 2);
        sb += __shfl_xor_sync(0xffffffffu, sb, 1);
        sb += __shfl_xor_sync(0xffffffffu, sb, 2);
        if (lr == 0) { reds[cw2 * 64 + ia] = sa; reds[cw2 * 64 + ib] = sb; }
        __syncthreads();

        if (cw2 == 0 && lr == 0) {
            l_s[ia] = l_s[ia] * ca + reds[ia] + reds[64 + ia];
            l_s[ib] = l_s[ib] * cb + reds[ib] + reds[64 + ib];
            m_s[ia] = mna; m_s[ib] = mnb;
        }
#pragma unroll
        for (int nt = 0; nt < 4; nt++) {
            O[nt][0] *= ca; O[nt][1] *= ca;
            O[nt][2] *= cb; O[nt][3] *= cb;
        }
        // ---- O += P @ V
#pragma unroll
        for (int kq = 0; kq < 32; kq += 8) {
            uint32_t a0 = p32[ia * WST + kq + lr];
            uint32_t a1 = p32[ib * WST + kq + lr];
            uint32_t a2 = p32[ia * WST + kq + 4 + lr];
            uint32_t a3 = p32[ib * WST + kq + 4 + lr];
#pragma unroll
            for (int nt = 0; nt < 4; nt++) {
                int nn = (cw2 << 5) + 8 * nt + lq;
                mma_bf16(O[nt], a0, a1, a2, a3,
                         vt32[nn * WST + kq + lr], vt32[nn * WST + kq + 4 + lr]);
            }
        }
    }

    __syncthreads();
    float la = 1.f / l_s[ia];
    float lb = 1.f / l_s[ib];
#pragma unroll
    for (int nt = 0; nt < 4; nt++) {
        int cc = (cw2 << 5) + 8 * nt + 2 * lr;
        *(float2*)(out + qbase + (size_t)ia * H_ + cc) = make_float2(O[nt][0] * la, O[nt][1] * la);
        *(float2*)(out + qbase + (size_t)ib * H_ + cc) = make_float2(O[nt][2] * lb, O[nt][3] * lb);
    }
}

// ---------------- fused residual-add + LayerNorm ----------------
__global__ __launch_bounds__(256)
void ln_kernel(const float* __restrict__ a, const float* __restrict__ b,
               const float* __restrict__ w, const float* __restrict__ beta,
               float* __restrict__ out)
{
    const int row = blockIdx.x;
    const int tid = threadIdx.x;
    const size_t base = (size_t)row * H_;
    float x0 = a[base + tid]       + b[base + tid];
    float x1 = a[base + tid + 256] + b[base + tid + 256];
    float s  = x0 + x1;
    float sq = x0 * x0 + x1 * x1;
#pragma unroll
    for (int o = 16; o > 0; o >>= 1) {
        s  += __shfl_xor_sync(0xffffffffu, s,  o);
        sq += __shfl_xor_sync(0xffffffffu, sq, o);
    }
    __shared__ float rs[8], rq[8];
    int wid = tid >> 5;
    if ((tid & 31) == 0) { rs[wid] = s; rq[wid] = sq; }
    __syncthreads();
    if (tid < 32) {
        float ss = (tid < 8) ? rs[tid] : 0.f;
        float qq = (tid < 8) ? rq[tid] : 0.f;
#pragma unroll
        for (int o = 4; o > 0; o >>= 1) {
            ss += __shfl_xor_sync(0xffffffffu, ss, o);
            qq += __shfl_xor_sync(0xffffffffu, qq, o);
        }
        if (tid == 0) { rs[0] = ss; rq[0] = qq; }
    }
    __syncthreads();
    float mean = rs[0] * (1.f / H_);
    float var  = rq[0] * (1.f / H_) - mean * mean;
    float inv  = rsqrtf(var + 1e-12f);
    out[base + tid]       = w[tid]       * (x0 - mean) * inv + beta[tid];
    out[base + tid + 256] = w[tid + 256] * (x1 - mean) * inv + beta[tid + 256];
}

// ---------------- launcher ----------------
extern "C" void kernel_launch(void* const* d_in, const int* in_sizes, int n_in,
                              void* d_out, int out_size)
{
    const float* x   = (const float*)d_in[0];
    const float* pe  = (const float*)d_in[1];
    const float* Wq  = (const float*)d_in[2];
    const float* bq  = (const float*)d_in[3];
    const float* Wk  = (const float*)d_in[4];
    const float* bk  = (const float*)d_in[5];
    const float* Wv  = (const float*)d_in[6];
    const float* bv  = (const float*)d_in[7];
    const float* Wr  = (const float*)d_in[8];
    const float* br  = (const float*)d_in[9];
    const float* cb  = (const float*)d_in[10];
    const float* pb  = (const float*)d_in[11];
    const float* Wc  = (const float*)d_in[12];
    const float* bc  = (const float*)d_in[13];
    const float* W1  = (const float*)d_in[14];
    const float* b1  = (const float*)d_in[15];
    const float* W2  = (const float*)d_in[16];
    const float* b2  = (const float*)d_in[17];
    const float* lnw = (const float*)d_in[18];
    const float* lnb = (const float*)d_in[19];
    float* out = (float*)d_out;

    float *qcP, *qpP, *kP, *vP, *rP, *attnP, *t1P, *aP, *h1P, *h2P;
    cudaGetSymbolAddress((void**)&qcP,   g_qc);
    cudaGetSymbolAddress((void**)&qpP,   g_qp);
    cudaGetSymbolAddress((void**)&kP,    g_k);
    cudaGetSymbolAddress((void**)&vP,    g_v);
    cudaGetSymbolAddress((void**)&rP,    g_r);
    cudaGetSymbolAddress((void**)&attnP, g_attn);
    cudaGetSymbolAddress((void**)&t1P,   g_t1);
    cudaGetSymbolAddress((void**)&aP,    g_a);
    cudaGetSymbolAddress((void**)&h1P,   g_h1);
    cudaGetSymbolAddress((void**)&h2P,   g_h2);

    const dim3 gBig(H_ / 128, M_ / 128);   // (4, 64)
    const dim3 gPos(H_ / 128, L_ / 128);   // (4, 16)

    gemm_kernel<MODE_NHD, EPI_QCQP><<<gBig, 256>>>(x,  Wq, bq, cb, pb, qcP, qpP, M_, H_, H_);
    gemm_kernel<MODE_NHD, EPI_BIAS><<<gBig, 256>>>(x,  Wk, bk, nullptr, nullptr, kP, nullptr, M_, H_, H_);
    gemm_kernel<MODE_NHD, EPI_BIAS><<<gBig, 256>>>(x,  Wv, bv, nullptr, nullptr, vP, nullptr, M_, H_, H_);
    gemm_kernel<MODE_NHD, EPI_BIAS><<<gPos, 256>>>(pe, Wr, br, nullptr, nullptr, rP, nullptr, L_, H_, H_);

    cudaFuncSetAttribute(attn_kernel, cudaFuncAttributeMaxDynamicSharedMemorySize, ATTN_SMEM_BYTES);
    attn_kernel<<<dim3(L_ / 64, B_ * N_), 256, ATTN_SMEM_BYTES>>>(qcP, qpP, kP, vP, rP, attnP);

    gemm_kernel<MODE_T, EPI_BIAS><<<gBig, 256>>>(attnP, Wc, bc, nullptr, nullptr, t1P, nullptr, M_, H_, H_);
    ln_kernel<<<M_, 256>>>(t1P, x, lnw, lnb, aP);

    gemm_kernel<MODE_T, EPI_GELU><<<gBig, 256>>>(aP,  W1, b1, nullptr, nullptr, h1P, nullptr, M_, H_, H_);
    gemm_kernel<MODE_T, EPI_BIAS><<<gBig, 256>>>(h1P, W2, b2, nullptr, nullptr, h2P, nullptr, M_, H_, H_);
    ln_kernel<<<M_, 256>>>(aP, h2P, lnw, lnb, out);
}

// round 8
// speedup vs baseline: 3.6225x; 1.2396x over previous
#include <cuda_runtime.h>
#include <cuda_bf16.h>
#include <math.h>
#include <stdint.h>

#define B_  4
#define L_  2048
#define H_  512
#define N_  8
#define D_  64
#define M_  (B_*L_)   // 8192 rows

// ---------------- scratch ----------------
__device__ float g_qc  [M_*H_];
__device__ float g_qp  [M_*H_];
__device__ float g_k   [M_*H_];
__device__ float g_v   [M_*H_];
__device__ float g_r   [L_*H_];
__device__ float g_attn[M_*H_];
__device__ float g_t1  [M_*H_];
__device__ float g_a   [M_*H_];
__device__ float g_h1  [M_*H_];
__device__ float g_h2  [M_*H_];

// ---------------- helpers ----------------
__device__ __forceinline__ uint32_t fbits(float x) { return __float_as_uint(x); }
__device__ __forceinline__ uint32_t bf2(float x, float y) {
    __nv_bfloat162 t = __floats2bfloat162_rn(x, y);
    return *(uint32_t*)&t;
}
__device__ __forceinline__ void cpa16(void* dst, const void* src) {
    uint32_t d = (uint32_t)__cvta_generic_to_shared(dst);
    asm volatile("cp.async.ca.shared.global [%0], [%1], 16;" :: "r"(d), "l"(src));
}
#define CPA_COMMIT() asm volatile("cp.async.commit_group;")
#define CPA_WAIT1()  asm volatile("cp.async.wait_group 1;")
#define CPA_WAIT0()  asm volatile("cp.async.wait_group 0;")

// tf32: D(16x8) += A(16x8) * B(8x8)  (fp32 regs, HW truncates to tf32)
__device__ __forceinline__ void mma_tf32(float* c,
                                         uint32_t a0, uint32_t a1, uint32_t a2, uint32_t a3,
                                         uint32_t b0, uint32_t b1) {
    asm("mma.sync.aligned.m16n8k8.row.col.f32.tf32.tf32.f32 "
        "{%0,%1,%2,%3}, {%4,%5,%6,%7}, {%8,%9}, {%0,%1,%2,%3};"
        : "+f"(c[0]), "+f"(c[1]), "+f"(c[2]), "+f"(c[3])
        : "r"(a0), "r"(a1), "r"(a2), "r"(a3), "r"(b0), "r"(b1));
}
// bf16: D(16x8) += A(16x16) * B(16x8)
__device__ __forceinline__ void mma_bf16(float* c,
                                         uint32_t a0, uint32_t a1, uint32_t a2, uint32_t a3,
                                         uint32_t b0, uint32_t b1) {
    asm("mma.sync.aligned.m16n8k16.row.col.f32.bf16.bf16.f32 "
        "{%0,%1,%2,%3}, {%4,%5,%6,%7}, {%8,%9}, {%0,%1,%2,%3};"
        : "+f"(c[0]), "+f"(c[1]), "+f"(c[2]), "+f"(c[3])
        : "r"(a0), "r"(a1), "r"(a2), "r"(a3), "r"(b0), "r"(b1));
}

// ---------------- GEMM (tf32, cp.async double-buffered) ----------------
enum { MODE_NHD = 0, MODE_T = 1 };
enum { EPI_BIAS = 0, EPI_QCQP = 1, EPI_GELU = 2 };

template<int MODE, int EPI>
__global__ __launch_bounds__(256)
void gemm_kernel(const float* __restrict__ A, const float* __restrict__ W,
                 const float* __restrict__ bias, const float* __restrict__ bias2,
                 const float* __restrict__ bias3,
                 float* __restrict__ out1, float* __restrict__ out2,
                 int M, int N, int K)
{
    __shared__ float As[2][128][20];    // [stage][row][k] stride 20 -> conflict-free frags
    __shared__ float Bsm[2][2560];      // NHD: [k][c] stride 136 ; T: [c][k] stride 20
    const int tid  = threadIdx.x;
    const int lane = tid & 31;
    const int w    = tid >> 5;
    const int rw64 = (w >> 2) << 6;
    const int cw32 = (w & 3) << 5;
    const int m0 = blockIdx.y << 7, c0 = blockIdx.x << 7;
    const int lq = lane >> 2;
    const int lr = lane & 3;

    float C[4][4][4];
#pragma unroll
    for (int mt = 0; mt < 4; mt++)
#pragma unroll
        for (int nt = 0; nt < 4; nt++)
#pragma unroll
            for (int e = 0; e < 4; e++) C[mt][nt][e] = 0.f;

    // per-thread cp.async source/dst indices
    const int arow0 = tid >> 2, aq0 = (tid & 3) << 2;
    const int arow1 = (tid + 256) >> 2, aq1 = ((tid + 256) & 3) << 2;

    auto load_chunk = [&](int st, int k0) {
        cpa16(&As[st][arow0][aq0], A + (size_t)(m0 + arow0) * K + k0 + aq0);
        cpa16(&As[st][arow1][aq1], A + (size_t)(m0 + arow1) * K + k0 + aq1);
        if (MODE == MODE_NHD) {
#pragma unroll
            for (int jj = 0; jj < 2; jj++) {
                int f = tid + jj * 256;
                int kk = f >> 5, c4 = (f & 31) << 2;
                int cc = c0 + c4;
                cpa16(&Bsm[st][kk * 136 + c4],
                      W + (size_t)(cc >> 6) * ((size_t)K * 64)
                        + (size_t)(k0 + kk) * 64 + (cc & 63));
            }
        } else {
#pragma unroll
            for (int jj = 0; jj < 2; jj++) {
                int f = tid + jj * 256;
                int c = f >> 2, q = (f & 3) << 2;
                cpa16(&Bsm[st][c * 20 + q], W + (size_t)(c0 + c) * K + k0 + q);
            }
        }
    };

    const int NCH = K >> 4;   // 32
    load_chunk(0, 0);
    CPA_COMMIT();

    for (int ch = 0; ch < NCH; ch++) {
        if (ch + 1 < NCH) {
            load_chunk((ch + 1) & 1, (ch + 1) << 4);
            CPA_COMMIT();
            CPA_WAIT1();
        } else {
            CPA_WAIT0();
        }
        __syncthreads();
        const int st = ch & 1;
#pragma unroll
        for (int kc = 0; kc < 16; kc += 8) {
            uint32_t bf[4][2];
#pragma unroll
            for (int nt = 0; nt < 4; nt++) {
                int n = cw32 + 8 * nt + lq;
                if (MODE == MODE_NHD) {
                    bf[nt][0] = fbits(Bsm[st][(kc + lr) * 136 + n]);
                    bf[nt][1] = fbits(Bsm[st][(kc + 4 + lr) * 136 + n]);
                } else {
                    bf[nt][0] = fbits(Bsm[st][n * 20 + kc + lr]);
                    bf[nt][1] = fbits(Bsm[st][n * 20 + kc + 4 + lr]);
                }
            }
#pragma unroll
            for (int mt = 0; mt < 4; mt++) {
                int i = rw64 + 16 * mt + lq;
                uint32_t a0 = fbits(As[st][i][kc + lr]);
                uint32_t a1 = fbits(As[st][i + 8][kc + lr]);
                uint32_t a2 = fbits(As[st][i][kc + 4 + lr]);
                uint32_t a3 = fbits(As[st][i + 8][kc + 4 + lr]);
#pragma unroll
                for (int nt = 0; nt < 4; nt++)
                    mma_tf32(C[mt][nt], a0, a1, a2, a3, bf[nt][0], bf[nt][1]);
            }
        }
        __syncthreads();
    }

#pragma unroll
    for (int mt = 0; mt < 4; mt++) {
        int m = m0 + rw64 + 16 * mt + lq;
#pragma unroll
        for (int nt = 0; nt < 4; nt++) {
            int c = c0 + cw32 + 8 * nt + 2 * lr;
            float b0 = bias[c], b1 = bias[c + 1];
            float v00 = C[mt][nt][0] + b0, v01 = C[mt][nt][1] + b1;
            float v10 = C[mt][nt][2] + b0, v11 = C[mt][nt][3] + b1;
            size_t o0 = (size_t)m * N + c;
            size_t o1 = o0 + (size_t)8 * N;
            if (EPI == EPI_BIAS) {
                *(float2*)(out1 + o0) = make_float2(v00, v01);
                *(float2*)(out1 + o1) = make_float2(v10, v11);
            } else if (EPI == EPI_QCQP) {
                float c20 = bias2[c], c21 = bias2[c + 1];
                float p20 = bias3[c], p21 = bias3[c + 1];
                *(float2*)(out1 + o0) = make_float2(v00 + c20, v01 + c21);
                *(float2*)(out1 + o1) = make_float2(v10 + c20, v11 + c21);
                *(float2*)(out2 + o0) = make_float2(v00 + p20, v01 + p21);
                *(float2*)(out2 + o1) = make_float2(v10 + p20, v11 + p21);
            } else {
                v00 = v00 * 0.5f * (1.f + erff(v00 * 0.70710678118654752f));
                v01 = v01 * 0.5f * (1.f + erff(v01 * 0.70710678118654752f));
                v10 = v10 * 0.5f * (1.f + erff(v10 * 0.70710678118654752f));
                v11 = v11 * 0.5f * (1.f + erff(v11 * 0.70710678118654752f));
                *(float2*)(out1 + o0) = make_float2(v00, v01);
                *(float2*)(out1 + o1) = make_float2(v10, v11);
            }
        }
    }
}

// ---------------- flash attention, bf16 + rolling rel-shift band ----------------
#define WST 36
#define SPR 132
// words: qc/qp/k/vt 4*2304 + r 4608 + sp 8448 + p 2304 + stats 384 = 24960 -> 99840 B
#define ATTN_SMEM_BYTES (24960 * 4)

__global__ __launch_bounds__(256, 2)
void attn_kernel(const float* __restrict__ qc, const float* __restrict__ qp,
                 const float* __restrict__ kmat, const float* __restrict__ vmat,
                 const float* __restrict__ rmat, float* __restrict__ out)
{
    extern __shared__ char smraw[];
    uint32_t* qc32 = (uint32_t*)smraw;            // [i][dw] 64 x 36
    uint32_t* qp32 = qc32 + 64 * WST;
    uint32_t* k32  = qp32 + 64 * WST;             // [j][dw]
    uint32_t* vt32 = k32  + 64 * WST;             // [d][jw] (transposed)
    uint32_t* r32  = vt32 + 64 * WST;             // ring [p&127][dw] 128 x 36
    float*    sp_s = (float*)(r32 + 128 * WST);   // ring [i][p&127] 64 x 132 fp32
    uint32_t* p32  = (uint32_t*)(sp_s + 64 * SPR);// [i][jw] 64 x 36
    float*    m_s  = (float*)(p32 + 64 * WST);
    float*    l_s  = m_s + 64;
    float*    redm = l_s + 64;                    // [2][64]
    float*    reds = redm + 128;                  // [2][64]

    __nv_bfloat16* vt16 = (__nv_bfloat16*)vt32;

    const int tid  = threadIdx.x;
    const int lane = tid & 31;
    const int w    = tid >> 5;
    const int rw   = (w & 3) << 4;
    const int cw2  = w >> 2;
    const int lq = lane >> 2, lr = lane & 3;

    const int bh = blockIdx.y;
    const int b  = bh >> 3, n = bh & 7;
    const int i0 = ((int)gridDim.x - 1 - (int)blockIdx.x) << 6;
    const int col = n << 6;
    const size_t qbase = ((size_t)(b * L_) + i0) * H_ + col;

    if (tid < 64) { m_s[tid] = -INFINITY; l_s[tid] = 0.f; }

    // persistent query tiles -> bf16
#pragma unroll
    for (int jj = 0; jj < 4; jj++) {
        int f = tid + jj * 256;
        int row = f >> 4, cq = (f & 15) << 2;
        float4 a = *(const float4*)(qc + qbase + (size_t)row * H_ + cq);
        qc32[row * WST + (cq >> 1)]     = bf2(a.x, a.y);
        qc32[row * WST + (cq >> 1) + 1] = bf2(a.z, a.w);
        float4 p = *(const float4*)(qp + qbase + (size_t)row * H_ + cq);
        qp32[row * WST + (cq >> 1)]     = bf2(p.x, p.y);
        qp32[row * WST + (cq >> 1) + 1] = bf2(p.z, p.w);
    }

    float O[4][4];
#pragma unroll
    for (int nt = 0; nt < 4; nt++)
#pragma unroll
        for (int e = 0; e < 4; e++) O[nt][e] = 0.f;

    const int ia = rw + lq, ib = ia + 8;

    for (int j0 = 0; j0 <= i0; j0 += 64) {
        __syncthreads();
        const int pbase = (L_ - 64) + j0 - i0;    // multiple of 64
        const int pb64  = pbase & 127;            // 0 or 64
        const size_t kb = ((size_t)(b * L_) + j0) * H_ + col;
#pragma unroll
        for (int jj = 0; jj < 4; jj++) {
            int f = tid + jj * 256;
            int row = f >> 4, cq = (f & 15) << 2;
            float4 a = *(const float4*)(kmat + kb + (size_t)row * H_ + cq);
            k32[row * WST + (cq >> 1)]     = bf2(a.x, a.y);
            k32[row * WST + (cq >> 1) + 1] = bf2(a.z, a.w);
            float4 vv = *(const float4*)(vmat + kb + (size_t)row * H_ + cq);
            vt16[(cq + 0) * 72 + row] = __float2bfloat16_rn(vv.x);
            vt16[(cq + 1) * 72 + row] = __float2bfloat16_rn(vv.y);
            vt16[(cq + 2) * 72 + row] = __float2bfloat16_rn(vv.z);
            vt16[(cq + 3) * 72 + row] = __float2bfloat16_rn(vv.w);
        }
        if (j0 == 0) {
            // full 128-row r window into ring
#pragma unroll
            for (int jj = 0; jj < 8; jj++) {
                int f = tid + jj * 256;
                int row = f >> 4, cq = (f & 15) << 2;
                int p = pbase + row;
                int rr = (pb64 + row) & 127;
                if (p < L_) {
                    float4 a = *(const float4*)(rmat + (size_t)p * H_ + col + cq);
                    r32[rr * WST + (cq >> 1)]     = bf2(a.x, a.y);
                    r32[rr * WST + (cq >> 1) + 1] = bf2(a.z, a.w);
                } else {
                    r32[rr * WST + (cq >> 1)]     = 0u;
                    r32[rr * WST + (cq >> 1) + 1] = 0u;
                }
            }
        } else {
            // only the new upper half: p in [pbase+64, pbase+128)
            const int hb = (pb64 + 64) & 127;     // 0 or 64
#pragma unroll
            for (int jj = 0; jj < 4; jj++) {
                int f = tid + jj * 256;
                int row = f >> 4, cq = (f & 15) << 2;
                int p = pbase + 64 + row;
                int rr = hb + row;
                if (p < L_) {
                    float4 a = *(const float4*)(rmat + (size_t)p * H_ + col + cq);
                    r32[rr * WST + (cq >> 1)]     = bf2(a.x, a.y);
                    r32[rr * WST + (cq >> 1) + 1] = bf2(a.z, a.w);
                } else {
                    r32[rr * WST + (cq >> 1)]     = 0u;
                    r32[rr * WST + (cq >> 1) + 1] = 0u;
                }
            }
        }
        __syncthreads();

        // ---- S = qc @ k^T (16x32 per warp)
        float S[4][4];
#pragma unroll
        for (int nt = 0; nt < 4; nt++)
#pragma unroll
            for (int e = 0; e < 4; e++) S[nt][e] = 0.f;
#pragma unroll
        for (int kq = 0; kq < 32; kq += 8) {
            uint32_t a0 = qc32[ia * WST + kq + lr];
            uint32_t a1 = qc32[ib * WST + kq + lr];
            uint32_t a2 = qc32[ia * WST + kq + 4 + lr];
            uint32_t a3 = qc32[ib * WST + kq + 4 + lr];
#pragma unroll
            for (int nt = 0; nt < 4; nt++) {
                int nn = (cw2 << 5) + 8 * nt + lq;
                mma_bf16(S[nt], a0, a1, a2, a3,
                         k32[nn * WST + kq + lr], k32[nn * WST + kq + 4 + lr]);
            }
        }
        // ---- Sp = qp @ r^T : first iter full 128 band, then only new 64
        if (j0 == 0) {
            float SP[8][4];
#pragma unroll
            for (int nt = 0; nt < 8; nt++)
#pragma unroll
                for (int e = 0; e < 4; e++) SP[nt][e] = 0.f;
#pragma unroll
            for (int kq = 0; kq < 32; kq += 8) {
                uint32_t a0 = qp32[ia * WST + kq + lr];
                uint32_t a1 = qp32[ib * WST + kq + lr];
                uint32_t a2 = qp32[ia * WST + kq + 4 + lr];
                uint32_t a3 = qp32[ib * WST + kq + 4 + lr];
#pragma unroll
                for (int nt = 0; nt < 8; nt++) {
                    int rr = (pb64 + (cw2 << 6) + 8 * nt + lq) & 127;
                    mma_bf16(SP[nt], a0, a1, a2, a3,
                             r32[rr * WST + kq + lr], r32[rr * WST + kq + 4 + lr]);
                }
            }
#pragma unroll
            for (int nt = 0; nt < 8; nt++) {
                int cr = (pb64 + (cw2 << 6) + 8 * nt + 2 * lr) & 127;
                *(float2*)&sp_s[ia * SPR + cr] = make_float2(SP[nt][0], SP[nt][1]);
                *(float2*)&sp_s[ib * SPR + cr] = make_float2(SP[nt][2], SP[nt][3]);
            }
        } else {
            const int hb = (pb64 + 64) & 127;
            float SP[4][4];
#pragma unroll
            for (int nt = 0; nt < 4; nt++)
#pragma unroll
                for (int e = 0; e < 4; e++) SP[nt][e] = 0.f;
#pragma unroll
            for (int kq = 0; kq < 32; kq += 8) {
                uint32_t a0 = qp32[ia * WST + kq + lr];
                uint32_t a1 = qp32[ib * WST + kq + lr];
                uint32_t a2 = qp32[ia * WST + kq + 4 + lr];
                uint32_t a3 = qp32[ib * WST + kq + 4 + lr];
#pragma unroll
                for (int nt = 0; nt < 4; nt++) {
                    int rr = hb + (cw2 << 5) + 8 * nt + lq;
                    mma_bf16(SP[nt], a0, a1, a2, a3,
                             r32[rr * WST + kq + lr], r32[rr * WST + kq + 4 + lr]);
                }
            }
#pragma unroll
            for (int nt = 0; nt < 4; nt++) {
                int cr = hb + (cw2 << 5) + 8 * nt + 2 * lr;
                *(float2*)&sp_s[ia * SPR + cr] = make_float2(SP[nt][0], SP[nt][1]);
                *(float2*)&sp_s[ib * SPR + cr] = make_float2(SP[nt][2], SP[nt][3]);
            }
        }
        __syncthreads();

        // ---- shift + scale + mask
        const bool diag = (j0 == i0);
#pragma unroll
        for (int nt = 0; nt < 4; nt++) {
            int jbase = (cw2 << 5) + 8 * nt + 2 * lr;
#pragma unroll
            for (int e = 0; e < 4; e++) {
                int iloc = (e >= 2) ? ib : ia;
                int jloc = jbase + (e & 1);
                int cr = (pb64 + 63 + jloc - iloc) & 127;
                float s = (S[nt][e] + sp_s[iloc * SPR + cr]) * 0.125f;
                if (diag && jloc > iloc) s = -1e30f;
                S[nt][e] = s;
            }
        }

        // ---- row max across two col halves
        float ma = -INFINITY, mb = -INFINITY;
#pragma unroll
        for (int nt = 0; nt < 4; nt++) {
            ma = fmaxf(ma, fmaxf(S[nt][0], S[nt][1]));
            mb = fmaxf(mb, fmaxf(S[nt][2], S[nt][3]));
        }
        ma = fmaxf(ma, __shfl_xor_sync(0xffffffffu, ma, 1));
        ma = fmaxf(ma, __shfl_xor_sync(0xffffffffu, ma, 2));
        mb = fmaxf(mb, __shfl_xor_sync(0xffffffffu, mb, 1));
        mb = fmaxf(mb, __shfl_xor_sync(0xffffffffu, mb, 2));
        if (lr == 0) { redm[cw2 * 64 + ia] = ma; redm[cw2 * 64 + ib] = mb; }
        __syncthreads();

        float moa = m_s[ia], mob = m_s[ib];
        float mna = fmaxf(moa, fmaxf(redm[ia], redm[64 + ia]));
        float mnb = fmaxf(mob, fmaxf(redm[ib], redm[64 + ib]));
        float ca = __expf(moa - mna), cb = __expf(mob - mnb);

        float sa = 0.f, sb = 0.f;
#pragma unroll
        for (int nt = 0; nt < 4; nt++) {
            float p0 = __expf(S[nt][0] - mna);
            float p1 = __expf(S[nt][1] - mna);
            float p2 = __expf(S[nt][2] - mnb);
            float p3 = __expf(S[nt][3] - mnb);
            sa += p0 + p1; sb += p2 + p3;
            int ccw = (cw2 << 4) + 4 * nt + lr;
            p32[ia * WST + ccw] = bf2(p0, p1);
            p32[ib * WST + ccw] = bf2(p2, p3);
        }
        sa += __shfl_xor_sync(0xffffffffu, sa, 1);
        sa += __shfl_xor_sync(0xffffffffu, sa, 2);
        sb += __shfl_xor_sync(0xffffffffu, sb, 1);
        sb += __shfl_xor_sync(0xffffffffu, sb, 2);
        if (lr == 0) { reds[cw2 * 64 + ia] = sa; reds[cw2 * 64 + ib] = sb; }
        __syncthreads();

        if (cw2 == 0 && lr == 0) {
            l_s[ia] = l_s[ia] * ca + reds[ia] + reds[64 + ia];
            l_s[ib] = l_s[ib] * cb + reds[ib] + reds[64 + ib];
            m_s[ia] = mna; m_s[ib] = mnb;
        }
#pragma unroll
        for (int nt = 0; nt < 4; nt++) {
            O[nt][0] *= ca; O[nt][1] *= ca;
            O[nt][2] *= cb; O[nt][3] *= cb;
        }
        // ---- O += P @ V
#pragma unroll
        for (int kq = 0; kq < 32; kq += 8) {
            uint32_t a0 = p32[ia * WST + kq + lr];
            uint32_t a1 = p32[ib * WST + kq + lr];
            uint32_t a2 = p32[ia * WST + kq + 4 + lr];
            uint32_t a3 = p32[ib * WST + kq + 4 + lr];
#pragma unroll
            for (int nt = 0; nt < 4; nt++) {
                int nn = (cw2 << 5) + 8 * nt + lq;
                mma_bf16(O[nt], a0, a1, a2, a3,
                         vt32[nn * WST + kq + lr], vt32[nn * WST + kq + 4 + lr]);
            }
        }
    }

    __syncthreads();
    float la = 1.f / l_s[ia];
    float lb = 1.f / l_s[ib];
#pragma unroll
    for (int nt = 0; nt < 4; nt++) {
        int cc = (cw2 << 5) + 8 * nt + 2 * lr;
        *(float2*)(out + qbase + (size_t)ia * H_ + cc) = make_float2(O[nt][0] * la, O[nt][1] * la);
        *(float2*)(out + qbase + (size_t)ib * H_ + cc) = make_float2(O[nt][2] * lb, O[nt][3] * lb);
    }
}

// ---------------- fused residual-add + LayerNorm ----------------
__global__ __launch_bounds__(256)
void ln_kernel(const float* __restrict__ a, const float* __restrict__ b,
               const float* __restrict__ w, const float* __restrict__ beta,
               float* __restrict__ out)
{
    const int row = blockIdx.x;
    const int tid = threadIdx.x;
    const size_t base = (size_t)row * H_;
    float x0 = a[base + tid]       + b[base + tid];
    float x1 = a[base + tid + 256] + b[base + tid + 256];
    float s  = x0 + x1;
    float sq = x0 * x0 + x1 * x1;
#pragma unroll
    for (int o = 16; o > 0; o >>= 1) {
        s  += __shfl_xor_sync(0xffffffffu, s,  o);
        sq += __shfl_xor_sync(0xffffffffu, sq, o);
    }
    __shared__ float rs[8], rq[8];
    int wid = tid >> 5;
    if ((tid & 31) == 0) { rs[wid] = s; rq[wid] = sq; }
    __syncthreads();
    if (tid < 32) {
        float ss = (tid < 8) ? rs[tid] : 0.f;
        float qq = (tid < 8) ? rq[tid] : 0.f;
#pragma unroll
        for (int o = 4; o > 0; o >>= 1) {
            ss += __shfl_xor_sync(0xffffffffu, ss, o);
            qq += __shfl_xor_sync(0xffffffffu, qq, o);
        }
        if (tid == 0) { rs[0] = ss; rq[0] = qq; }
    }
    __syncthreads();
    float mean = rs[0] * (1.f / H_);
    float var  = rq[0] * (1.f / H_) - mean * mean;
    float inv  = rsqrtf(var + 1e-12f);
    out[base + tid]       = w[tid]       * (x0 - mean) * inv + beta[tid];
    out[base + tid + 256] = w[tid + 256] * (x1 - mean) * inv + beta[tid + 256];
}

// ---------------- launcher ----------------
extern "C" void kernel_launch(void* const* d_in, const int* in_sizes, int n_in,
                              void* d_out, int out_size)
{
    const float* x   = (const float*)d_in[0];
    const float* pe  = (const float*)d_in[1];
    const float* Wq  = (const float*)d_in[2];
    const float* bq  = (const float*)d_in[3];
    const float* Wk  = (const float*)d_in[4];
    const float* bk  = (const float*)d_in[5];
    const float* Wv  = (const float*)d_in[6];
    const float* bv  = (const float*)d_in[7];
    const float* Wr  = (const float*)d_in[8];
    const float* br  = (const float*)d_in[9];
    const float* cb  = (const float*)d_in[10];
    const float* pb  = (const float*)d_in[11];
    const float* Wc  = (const float*)d_in[12];
    const float* bc  = (const float*)d_in[13];
    const float* W1  = (const float*)d_in[14];
    const float* b1  = (const float*)d_in[15];
    const float* W2  = (const float*)d_in[16];
    const float* b2  = (const float*)d_in[17];
    const float* lnw = (const float*)d_in[18];
    const float* lnb = (const float*)d_in[19];
    float* out = (float*)d_out;

    float *qcP, *qpP, *kP, *vP, *rP, *attnP, *t1P, *aP, *h1P, *h2P;
    cudaGetSymbolAddress((void**)&qcP,   g_qc);
    cudaGetSymbolAddress((void**)&qpP,   g_qp);
    cudaGetSymbolAddress((void**)&kP,    g_k);
    cudaGetSymbolAddress((void**)&vP,    g_v);
    cudaGetSymbolAddress((void**)&rP,    g_r);
    cudaGetSymbolAddress((void**)&attnP, g_attn);
    cudaGetSymbolAddress((void**)&t1P,   g_t1);
    cudaGetSymbolAddress((void**)&aP,    g_a);
    cudaGetSymbolAddress((void**)&h1P,   g_h1);
    cudaGetSymbolAddress((void**)&h2P,   g_h2);

    const dim3 gBig(H_ / 128, M_ / 128);   // (4, 64)
    const dim3 gPos(H_ / 128, L_ / 128);   // (4, 16)

    gemm_kernel<MODE_NHD, EPI_QCQP><<<gBig, 256>>>(x,  Wq, bq, cb, pb, qcP, qpP, M_, H_, H_);
    gemm_kernel<MODE_NHD, EPI_BIAS><<<gBig, 256>>>(x,  Wk, bk, nullptr, nullptr, kP, nullptr, M_, H_, H_);
    gemm_kernel<MODE_NHD, EPI_BIAS><<<gBig, 256>>>(x,  Wv, bv, nullptr, nullptr, vP, nullptr, M_, H_, H_);
    gemm_kernel<MODE_NHD, EPI_BIAS><<<gPos, 256>>>(pe, Wr, br, nullptr, nullptr, rP, nullptr, L_, H_, H_);

    cudaFuncSetAttribute(attn_kernel, cudaFuncAttributeMaxDynamicSharedMemorySize, ATTN_SMEM_BYTES);
    attn_kernel<<<dim3(L_ / 64, B_ * N_), 256, ATTN_SMEM_BYTES>>>(qcP, qpP, kP, vP, rP, attnP);

    gemm_kernel<MODE_T, EPI_BIAS><<<gBig, 256>>>(attnP, Wc, bc, nullptr, nullptr, t1P, nullptr, M_, H_, H_);
    ln_kernel<<<M_, 256>>>(t1P, x, lnw, lnb, aP);

    gemm_kernel<MODE_T, EPI_GELU><<<gBig, 256>>>(aP,  W1, b1, nullptr, nullptr, h1P, nullptr, M_, H_, H_);
    gemm_kernel<MODE_T, EPI_BIAS><<<gBig, 256>>>(h1P, W2, b2, nullptr, nullptr, h2P, nullptr, M_, H_, H_);
    ln_kernel<<<M_, 256>>>(aP, h2P, lnw, lnb, out);
}

// round 9
// speedup vs baseline: 3.8320x; 1.0578x over previous
#include <cuda_runtime.h>
#include <cuda_bf16.h>
#include <math.h>
#include <stdint.h>

#define B_  4
#define L_  2048
#define H_  512
#define N_  8
#define D_  64
#define M_  (B_*L_)   // 8192 rows
#define HW  256       // H_/2 words per row (bf16x2)

// ---------------- scratch ----------------
__device__ uint32_t g_qc[M_*HW];   // bf16x2
__device__ uint32_t g_qp[M_*HW];
__device__ uint32_t g_k [M_*HW];
__device__ uint32_t g_v [M_*HW];
__device__ uint32_t g_r [L_*HW];
__device__ float g_attn[M_*H_];
__device__ float g_t1  [M_*H_];
__device__ float g_a   [M_*H_];
__device__ float g_h1  [M_*H_];
__device__ float g_h2  [M_*H_];

// ---------------- helpers ----------------
__device__ __forceinline__ uint32_t fbits(float x) { return __float_as_uint(x); }
__device__ __forceinline__ uint32_t bf2(float x, float y) {
    __nv_bfloat162 t = __floats2bfloat162_rn(x, y);
    return *(uint32_t*)&t;
}
__device__ __forceinline__ void cpa16(void* dst, const void* src) {
    uint32_t d = (uint32_t)__cvta_generic_to_shared(dst);
    asm volatile("cp.async.ca.shared.global [%0], [%1], 16;" :: "r"(d), "l"(src));
}
#define CPA_COMMIT() asm volatile("cp.async.commit_group;")
#define CPA_WAIT1()  asm volatile("cp.async.wait_group 1;")
#define CPA_WAIT0()  asm volatile("cp.async.wait_group 0;")

__device__ __forceinline__ void mma_tf32(float* c,
                                         uint32_t a0, uint32_t a1, uint32_t a2, uint32_t a3,
                                         uint32_t b0, uint32_t b1) {
    asm("mma.sync.aligned.m16n8k8.row.col.f32.tf32.tf32.f32 "
        "{%0,%1,%2,%3}, {%4,%5,%6,%7}, {%8,%9}, {%0,%1,%2,%3};"
        : "+f"(c[0]), "+f"(c[1]), "+f"(c[2]), "+f"(c[3])
        : "r"(a0), "r"(a1), "r"(a2), "r"(a3), "r"(b0), "r"(b1));
}
__device__ __forceinline__ void mma_bf16(float* c,
                                         uint32_t a0, uint32_t a1, uint32_t a2, uint32_t a3,
                                         uint32_t b0, uint32_t b1) {
    asm("mma.sync.aligned.m16n8k16.row.col.f32.bf16.bf16.f32 "
        "{%0,%1,%2,%3}, {%4,%5,%6,%7}, {%8,%9}, {%0,%1,%2,%3};"
        : "+f"(c[0]), "+f"(c[1]), "+f"(c[2]), "+f"(c[3])
        : "r"(a0), "r"(a1), "r"(a2), "r"(a3), "r"(b0), "r"(b1));
}

// ---------------- GEMM (tf32, cp.async double-buffered) ----------------
enum { MODE_NHD = 0, MODE_T = 1 };
enum { EPI_BIAS = 0, EPI_QCQP_BF = 1, EPI_GELU = 2, EPI_BF = 3 };

template<int MODE, int EPI>
__global__ __launch_bounds__(256)
void gemm_kernel(const float* __restrict__ A, const float* __restrict__ W,
                 const float* __restrict__ bias, const float* __restrict__ bias2,
                 const float* __restrict__ bias3,
                 void* __restrict__ out1v, void* __restrict__ out2v,
                 int M, int N, int K)
{
    __shared__ float As[2][128][20];
    __shared__ float Bsm[2][2560];
    const int tid  = threadIdx.x;
    const int lane = tid & 31;
    const int w    = tid >> 5;
    const int rw64 = (w >> 2) << 6;
    const int cw32 = (w & 3) << 5;
    const int m0 = blockIdx.y << 7, c0 = blockIdx.x << 7;
    const int lq = lane >> 2;
    const int lr = lane & 3;

    float C[4][4][4];
#pragma unroll
    for (int mt = 0; mt < 4; mt++)
#pragma unroll
        for (int nt = 0; nt < 4; nt++)
#pragma unroll
            for (int e = 0; e < 4; e++) C[mt][nt][e] = 0.f;

    const int arow0 = tid >> 2, aq0 = (tid & 3) << 2;
    const int arow1 = (tid + 256) >> 2, aq1 = ((tid + 256) & 3) << 2;

    auto load_chunk = [&](int st, int k0) {
        cpa16(&As[st][arow0][aq0], A + (size_t)(m0 + arow0) * K + k0 + aq0);
        cpa16(&As[st][arow1][aq1], A + (size_t)(m0 + arow1) * K + k0 + aq1);
        if (MODE == MODE_NHD) {
#pragma unroll
            for (int jj = 0; jj < 2; jj++) {
                int f = tid + jj * 256;
                int kk = f >> 5, c4 = (f & 31) << 2;
                int cc = c0 + c4;
                cpa16(&Bsm[st][kk * 136 + c4],
                      W + (size_t)(cc >> 6) * ((size_t)K * 64)
                        + (size_t)(k0 + kk) * 64 + (cc & 63));
            }
        } else {
#pragma unroll
            for (int jj = 0; jj < 2; jj++) {
                int f = tid + jj * 256;
                int c = f >> 2, q = (f & 3) << 2;
                cpa16(&Bsm[st][c * 20 + q], W + (size_t)(c0 + c) * K + k0 + q);
            }
        }
    };

    const int NCH = K >> 4;
    load_chunk(0, 0);
    CPA_COMMIT();

    for (int ch = 0; ch < NCH; ch++) {
        if (ch + 1 < NCH) {
            load_chunk((ch + 1) & 1, (ch + 1) << 4);
            CPA_COMMIT();
            CPA_WAIT1();
        } else {
            CPA_WAIT0();
        }
        __syncthreads();
        const int st = ch & 1;
#pragma unroll
        for (int kc = 0; kc < 16; kc += 8) {
            uint32_t bf[4][2];
#pragma unroll
            for (int nt = 0; nt < 4; nt++) {
                int n = cw32 + 8 * nt + lq;
                if (MODE == MODE_NHD) {
                    bf[nt][0] = fbits(Bsm[st][(kc + lr) * 136 + n]);
                    bf[nt][1] = fbits(Bsm[st][(kc + 4 + lr) * 136 + n]);
                } else {
                    bf[nt][0] = fbits(Bsm[st][n * 20 + kc + lr]);
                    bf[nt][1] = fbits(Bsm[st][n * 20 + kc + 4 + lr]);
                }
            }
#pragma unroll
            for (int mt = 0; mt < 4; mt++) {
                int i = rw64 + 16 * mt + lq;
                uint32_t a0 = fbits(As[st][i][kc + lr]);
                uint32_t a1 = fbits(As[st][i + 8][kc + lr]);
                uint32_t a2 = fbits(As[st][i][kc + 4 + lr]);
                uint32_t a3 = fbits(As[st][i + 8][kc + 4 + lr]);
#pragma unroll
                for (int nt = 0; nt < 4; nt++)
                    mma_tf32(C[mt][nt], a0, a1, a2, a3, bf[nt][0], bf[nt][1]);
            }
        }
        __syncthreads();
    }

    const int NW = N >> 1;
#pragma unroll
    for (int mt = 0; mt < 4; mt++) {
        int m = m0 + rw64 + 16 * mt + lq;
#pragma unroll
        for (int nt = 0; nt < 4; nt++) {
            int c = c0 + cw32 + 8 * nt + 2 * lr;
            float b0 = bias[c], b1 = bias[c + 1];
            float v00 = C[mt][nt][0] + b0, v01 = C[mt][nt][1] + b1;
            float v10 = C[mt][nt][2] + b0, v11 = C[mt][nt][3] + b1;
            if (EPI == EPI_BIAS) {
                float* out1 = (float*)out1v;
                size_t o0 = (size_t)m * N + c, o1 = o0 + (size_t)8 * N;
                *(float2*)(out1 + o0) = make_float2(v00, v01);
                *(float2*)(out1 + o1) = make_float2(v10, v11);
            } else if (EPI == EPI_QCQP_BF) {
                uint32_t* o1 = (uint32_t*)out1v;
                uint32_t* o2 = (uint32_t*)out2v;
                float c20 = bias2[c], c21 = bias2[c + 1];
                float p20 = bias3[c], p21 = bias3[c + 1];
                size_t w0 = (size_t)m * NW + (c >> 1), w1 = w0 + (size_t)8 * NW;
                o1[w0] = bf2(v00 + c20, v01 + c21);
                o1[w1] = bf2(v10 + c20, v11 + c21);
                o2[w0] = bf2(v00 + p20, v01 + p21);
                o2[w1] = bf2(v10 + p20, v11 + p21);
            } else if (EPI == EPI_BF) {
                uint32_t* o1 = (uint32_t*)out1v;
                size_t w0 = (size_t)m * NW + (c >> 1), w1 = w0 + (size_t)8 * NW;
                o1[w0] = bf2(v00, v01);
                o1[w1] = bf2(v10, v11);
            } else { // GELU
                float* out1 = (float*)out1v;
                size_t o0 = (size_t)m * N + c, o1 = o0 + (size_t)8 * N;
                v00 = v00 * 0.5f * (1.f + erff(v00 * 0.70710678118654752f));
                v01 = v01 * 0.5f * (1.f + erff(v01 * 0.70710678118654752f));
                v10 = v10 * 0.5f * (1.f + erff(v10 * 0.70710678118654752f));
                v11 = v11 * 0.5f * (1.f + erff(v11 * 0.70710678118654752f));
                *(float2*)(out1 + o0) = make_float2(v00, v01);
                *(float2*)(out1 + o1) = make_float2(v10, v11);
            }
        }
    }
}

// ---------------- flash attention: bf16 globals, cp.async pipeline ----------------
#define WST 36
#define SPR 132
// words: qc 2304 + qp 2304 + K 2x2304 + vt 2304 + r 4608 + sp 8448 + p 2304 + stats 384
#define ATTN_SMEM_BYTES (27264 * 4)   // 109056

__global__ __launch_bounds__(256, 2)
void attn_kernel(const uint32_t* __restrict__ qc, const uint32_t* __restrict__ qp,
                 const uint32_t* __restrict__ kg, const uint32_t* __restrict__ vg,
                 const uint32_t* __restrict__ rg, float* __restrict__ out)
{
    extern __shared__ char smraw[];
    uint32_t* qc32 = (uint32_t*)smraw;            // [i][dw] 64x36
    uint32_t* qp32 = qc32 + 2304;
    uint32_t* kb32 = qp32 + 2304;                 // 2 stages x 64x36
    uint32_t* vt32 = kb32 + 4608;                 // [d][jw] 64x36
    uint32_t* r32  = vt32 + 2304;                 // ring [p&127][dw] 128x36
    float*    sp_s = (float*)(r32 + 4608);        // ring [i][p&127] 64x132
    uint32_t* p32  = (uint32_t*)(sp_s + 64 * SPR);// [i][jw] 64x36
    float*    m_s  = (float*)(p32 + 2304);
    float*    l_s  = m_s + 64;
    float*    redm = l_s + 64;                    // [2][64]
    float*    reds = redm + 128;                  // [2][64]
    uint16_t* vt16 = (uint16_t*)vt32;

    const int tid  = threadIdx.x;
    const int lane = tid & 31;
    const int w    = tid >> 5;
    const int rw   = (w & 3) << 4;
    const int cw2  = w >> 2;
    const int lq = lane >> 2, lr = lane & 3;

    const int bh = blockIdx.y;
    const int b  = bh >> 3, n = bh & 7;
    const int i0 = ((int)gridDim.x - 1 - (int)blockIdx.x) << 6;
    const int colw = n << 5;   // word col offset
    const size_t qbW = ((size_t)(b * L_) + i0) * HW + colw;

    const int fr  = tid >> 3;           // 0..31
    const int fc4 = (tid & 7) << 2;     // word col {0,4,...,28}

    if (tid < 64) { m_s[tid] = -INFINITY; l_s[tid] = 0.f; }

    const int ni = (i0 >> 6) + 1;
    const int pbase0 = (L_ - 64) - i0;

    // ---- preloop: stage qc/qp, K(0), full r band via cp.async; V(0) into regs
#pragma unroll
    for (int jj = 0; jj < 2; jj++) {
        int row = fr + 32 * jj;
        cpa16(&qc32[row * WST + fc4], qc + qbW + (size_t)row * HW + fc4);
        cpa16(&qp32[row * WST + fc4], qp + qbW + (size_t)row * HW + fc4);
        cpa16(&kb32[row * WST + fc4], kg + ((size_t)(b * L_) ) * HW + qbW - qbW + ((size_t)(b * L_)) * 0 + 0 + 0 + ((size_t)(b * L_ + 0) * HW + colw) + (size_t)row * HW + fc4 - ((size_t)(b * L_)) * HW - colw + colw + ((size_t)(b*L_))*HW - ((size_t)(b*L_))*HW);
    }
    // (rewrite cleanly below — the above K line is replaced)
    // NOTE: compilers fold the zero arithmetic; keep explicit clean version:
#pragma unroll
    for (int jj = 0; jj < 2; jj++) {
        int row = fr + 32 * jj;
        cpa16(&kb32[row * WST + fc4], kg + ((size_t)(b * L_) + row) * HW + colw + fc4);
    }
#pragma unroll
    for (int jj = 0; jj < 4; jj++) {
        int row = fr + 32 * jj;       // 0..127
        int p = pbase0 + row;
        uint32_t* dst = &r32[(p & 127) * WST + fc4];
        if (p < L_) cpa16(dst, rg + (size_t)p * HW + colw + fc4);
        else { uint4 z = make_uint4(0,0,0,0); *(uint4*)dst = z; }
    }
    CPA_COMMIT();
    uint4 vreg[2];
#pragma unroll
    for (int jj = 0; jj < 2; jj++) {
        int row = fr + 32 * jj;
        vreg[jj] = *(const uint4*)(vg + ((size_t)(b * L_) + row) * HW + colw + fc4);
    }

    float O[4][4];
#pragma unroll
    for (int nt = 0; nt < 4; nt++)
#pragma unroll
        for (int e = 0; e < 4; e++) O[nt][e] = 0.f;

    const int ia = rw + lq, ib = ia + 8;

    for (int ch = 0; ch < ni; ch++) {
        const int j0 = ch << 6;
        const int pbase = pbase0 + j0;
        if (ch) __syncthreads();    // sync0: prev iter compute done
        // ---- V regs -> transposed smem
#pragma unroll
        for (int jj = 0; jj < 2; jj++) {
            int j = fr + 32 * jj;
            uint4 cv = vreg[jj];
            int d0 = fc4 << 1;
            vt16[(d0 + 0) * 72 + j] = (uint16_t)(cv.x);
            vt16[(d0 + 1) * 72 + j] = (uint16_t)(cv.x >> 16);
            vt16[(d0 + 2) * 72 + j] = (uint16_t)(cv.y);
            vt16[(d0 + 3) * 72 + j] = (uint16_t)(cv.y >> 16);
            vt16[(d0 + 4) * 72 + j] = (uint16_t)(cv.z);
            vt16[(d0 + 5) * 72 + j] = (uint16_t)(cv.z >> 16);
            vt16[(d0 + 6) * 72 + j] = (uint16_t)(cv.w);
            vt16[(d0 + 7) * 72 + j] = (uint16_t)(cv.w >> 16);
        }
        CPA_WAIT0();
        __syncthreads();            // sync1: K/r/(qc,qp) + vt visible
        const uint32_t* kst = kb32 + (ch & 1) * 2304;

        // ---- S = qc @ k^T
        float S[4][4];
#pragma unroll
        for (int nt = 0; nt < 4; nt++)
#pragma unroll
            for (int e = 0; e < 4; e++) S[nt][e] = 0.f;
#pragma unroll
        for (int kq = 0; kq < 32; kq += 8) {
            uint32_t a0 = qc32[ia * WST + kq + lr];
            uint32_t a1 = qc32[ib * WST + kq + lr];
            uint32_t a2 = qc32[ia * WST + kq + 4 + lr];
            uint32_t a3 = qc32[ib * WST + kq + 4 + lr];
#pragma unroll
            for (int nt = 0; nt < 4; nt++) {
                int nn = (cw2 << 5) + 8 * nt + lq;
                mma_bf16(S[nt], a0, a1, a2, a3,
                         kst[nn * WST + kq + lr], kst[nn * WST + kq + 4 + lr]);
            }
        }
        // ---- K prefetch (other stage; safe after sync1)
        if (ch + 1 < ni) {
#pragma unroll
            for (int jj = 0; jj < 2; jj++) {
                int row = fr + 32 * jj;
                cpa16(&kb32[((ch + 1) & 1) * 2304 + row * WST + fc4],
                      kg + ((size_t)(b * L_) + j0 + 64 + row) * HW + colw + fc4);
            }
        }
        // ---- Sp = qp @ r^T (full band first iter, rolling after)
        if (ch == 0) {
            float SP[8][4];
#pragma unroll
            for (int nt = 0; nt < 8; nt++)
#pragma unroll
                for (int e = 0; e < 4; e++) SP[nt][e] = 0.f;
#pragma unroll
            for (int kq = 0; kq < 32; kq += 8) {
                uint32_t a0 = qp32[ia * WST + kq + lr];
                uint32_t a1 = qp32[ib * WST + kq + lr];
                uint32_t a2 = qp32[ia * WST + kq + 4 + lr];
                uint32_t a3 = qp32[ib * WST + kq + 4 + lr];
#pragma unroll
                for (int nt = 0; nt < 8; nt++) {
                    int rr = (pbase + (cw2 << 6) + 8 * nt + lq) & 127;
                    mma_bf16(SP[nt], a0, a1, a2, a3,
                             r32[rr * WST + kq + lr], r32[rr * WST + kq + 4 + lr]);
                }
            }
#pragma unroll
            for (int nt = 0; nt < 8; nt++) {
                int cr = (pbase + (cw2 << 6) + 8 * nt + 2 * lr) & 127;
                *(float2*)&sp_s[ia * SPR + cr] = make_float2(SP[nt][0], SP[nt][1]);
                *(float2*)&sp_s[ib * SPR + cr] = make_float2(SP[nt][2], SP[nt][3]);
            }
        } else {
            float SP[4][4];
#pragma unroll
            for (int nt = 0; nt < 4; nt++)
#pragma unroll
                for (int e = 0; e < 4; e++) SP[nt][e] = 0.f;
#pragma unroll
            for (int kq = 0; kq < 32; kq += 8) {
                uint32_t a0 = qp32[ia * WST + kq + lr];
                uint32_t a1 = qp32[ib * WST + kq + lr];
                uint32_t a2 = qp32[ia * WST + kq + 4 + lr];
                uint32_t a3 = qp32[ib * WST + kq + 4 + lr];
#pragma unroll
                for (int nt = 0; nt < 4; nt++) {
                    int rr = (pbase + 64 + (cw2 << 5) + 8 * nt + lq) & 127;
                    mma_bf16(SP[nt], a0, a1, a2, a3,
                             r32[rr * WST + kq + lr], r32[rr * WST + kq + 4 + lr]);
                }
            }
#pragma unroll
            for (int nt = 0; nt < 4; nt++) {
                int cr = (pbase + 64 + (cw2 << 5) + 8 * nt + 2 * lr) & 127;
                *(float2*)&sp_s[ia * SPR + cr] = make_float2(SP[nt][0], SP[nt][1]);
                *(float2*)&sp_s[ib * SPR + cr] = make_float2(SP[nt][2], SP[nt][3]);
            }
        }
        __syncthreads();            // sync2: sp visible; r32 reads done

        // ---- r prefetch into old ring half + V regs for next iter
        if (ch + 1 < ni) {
#pragma unroll
            for (int jj = 0; jj < 2; jj++) {
                int row = fr + 32 * jj;
                int p = pbase + 128 + row;
                uint32_t* dst = &r32[(p & 127) * WST + fc4];
                if (p < L_) cpa16(dst, rg + (size_t)p * HW + colw + fc4);
                else { uint4 z = make_uint4(0,0,0,0); *(uint4*)dst = z; }
            }
            CPA_COMMIT();
#pragma unroll
            for (int jj = 0; jj < 2; jj++) {
                int row = fr + 32 * jj;
                vreg[jj] = *(const uint4*)(vg + ((size_t)(b * L_) + j0 + 64 + row) * HW + colw + fc4);
            }
        }

        // ---- shift + scale + mask
        const bool diag = (j0 == i0);
#pragma unroll
        for (int nt = 0; nt < 4; nt++) {
            int jbase = (cw2 << 5) + 8 * nt + 2 * lr;
#pragma unroll
            for (int e = 0; e < 4; e++) {
                int iloc = (e >= 2) ? ib : ia;
                int jloc = jbase + (e & 1);
                int cr = (pbase + 63 + jloc - iloc) & 127;
                float s = (S[nt][e] + sp_s[iloc * SPR + cr]) * 0.125f;
                if (diag && jloc > iloc) s = -1e30f;
                S[nt][e] = s;
            }
        }

        // ---- row max across two col halves
        float ma = -INFINITY, mb = -INFINITY;
#pragma unroll
        for (int nt = 0; nt < 4; nt++) {
            ma = fmaxf(ma, fmaxf(S[nt][0], S[nt][1]));
            mb = fmaxf(mb, fmaxf(S[nt][2], S[nt][3]));
        }
        ma = fmaxf(ma, __shfl_xor_sync(0xffffffffu, ma, 1));
        ma = fmaxf(ma, __shfl_xor_sync(0xffffffffu, ma, 2));
        mb = fmaxf(mb, __shfl_xor_sync(0xffffffffu, mb, 1));
        mb = fmaxf(mb, __shfl_xor_sync(0xffffffffu, mb, 2));
        if (lr == 0) { redm[cw2 * 64 + ia] = ma; redm[cw2 * 64 + ib] = mb; }
        __syncthreads();            // sync3

        float moa = m_s[ia], mob = m_s[ib];
        float mna = fmaxf(moa, fmaxf(redm[ia], redm[64 + ia]));
        float mnb = fmaxf(mob, fmaxf(redm[ib], redm[64 + ib]));
        float ca = __expf(moa - mna), cb = __expf(mob - mnb);

        float sa = 0.f, sb = 0.f;
#pragma unroll
        for (int nt = 0; nt < 4; nt++) {
            float p0 = __expf(S[nt][0] - mna);
            float p1 = __expf(S[nt][1] - mna);
            float p2 = __expf(S[nt][2] - mnb);
            float p3 = __expf(S[nt][3] - mnb);
            sa += p0 + p1; sb += p2 + p3;
            int ccw = (cw2 << 4) + 4 * nt + lr;
            p32[ia * WST + ccw] = bf2(p0, p1);
            p32[ib * WST + ccw] = bf2(p2, p3);
        }
        sa += __shfl_xor_sync(0xffffffffu, sa, 1);
        sa += __shfl_xor_sync(0xffffffffu, sa, 2);
        sb += __shfl_xor_sync(0xffffffffu, sb, 1);
        sb += __shfl_xor_sync(0xffffffffu, sb, 2);
        if (lr == 0) { reds[cw2 * 64 + ia] = sa; reds[cw2 * 64 + ib] = sb; }
        __syncthreads();            // sync4

        if (cw2 == 0 && lr == 0) {
            l_s[ia] = l_s[ia] * ca + reds[ia] + reds[64 + ia];
            l_s[ib] = l_s[ib] * cb + reds[ib] + reds[64 + ib];
            m_s[ia] = mna; m_s[ib] = mnb;
        }
#pragma unroll
        for (int nt = 0; nt < 4; nt++) {
            O[nt][0] *= ca; O[nt][1] *= ca;
            O[nt][2] *= cb; O[nt][3] *= cb;
        }
        // ---- O += P @ V
#pragma unroll
        for (int kq = 0; kq < 32; kq += 8) {
            uint32_t a0 = p32[ia * WST + kq + lr];
            uint32_t a1 = p32[ib * WST + kq + lr];
            uint32_t a2 = p32[ia * WST + kq + 4 + lr];
            uint32_t a3 = p32[ib * WST + kq + 4 + lr];
#pragma unroll
            for (int nt = 0; nt < 4; nt++) {
                int nn = (cw2 << 5) + 8 * nt + lq;
                mma_bf16(O[nt], a0, a1, a2, a3,
                         vt32[nn * WST + kq + lr], vt32[nn * WST + kq + 4 + lr]);
            }
        }
    }

    __syncthreads();
    float la = 1.f / l_s[ia];
    float lb = 1.f / l_s[ib];
    const size_t obase = ((size_t)(b * L_) + i0) * H_ + (n << 6);
#pragma unroll
    for (int nt = 0; nt < 4; nt++) {
        int cc = (cw2 << 5) + 8 * nt + 2 * lr;
        *(float2*)(out + obase + (size_t)ia * H_ + cc) = make_float2(O[nt][0] * la, O[nt][1] * la);
        *(float2*)(out + obase + (size_t)ib * H_ + cc) = make_float2(O[nt][2] * lb, O[nt][3] * lb);
    }
}

// ---------------- fused residual-add + LayerNorm ----------------
__global__ __launch_bounds__(256)
void ln_kernel(const float* __restrict__ a, const float* __restrict__ b,
               const float* __restrict__ w, const float* __restrict__ beta,
               float* __restrict__ out)
{
    const int row = blockIdx.x;
    const int tid = threadIdx.x;
    const size_t base = (size_t)row * H_;
    float x0 = a[base + tid]       + b[base + tid];
    float x1 = a[base + tid + 256] + b[base + tid + 256];
    float s  = x0 + x1;
    float sq = x0 * x0 + x1 * x1;
#pragma unroll
    for (int o = 16; o > 0; o >>= 1) {
        s  += __shfl_xor_sync(0xffffffffu, s,  o);
        sq += __shfl_xor_sync(0xffffffffu, sq, o);
    }
    __shared__ float rs[8], rq[8];
    int wid = tid >> 5;
    if ((tid & 31) == 0) { rs[wid] = s; rq[wid] = sq; }
    __syncthreads();
    if (tid < 32) {
        float ss = (tid < 8) ? rs[tid] : 0.f;
        float qq = (tid < 8) ? rq[tid] : 0.f;
#pragma unroll
        for (int o = 4; o > 0; o >>= 1) {
            ss += __shfl_xor_sync(0xffffffffu, ss, o);
            qq += __shfl_xor_sync(0xffffffffu, qq, o);
        }
        if (tid == 0) { rs[0] = ss; rq[0] = qq; }
    }
    __syncthreads();
    float mean = rs[0] * (1.f / H_);
    float var  = rq[0] * (1.f / H_) - mean * mean;
    float inv  = rsqrtf(var + 1e-12f);
    out[base + tid]       = w[tid]       * (x0 - mean) * inv + beta[tid];
    out[base + tid + 256] = w[tid + 256] * (x1 - mean) * inv + beta[tid + 256];
}

// ---------------- launcher ----------------
extern "C" void kernel_launch(void* const* d_in, const int* in_sizes, int n_in,
                              void* d_out, int out_size)
{
    const float* x   = (const float*)d_in[0];
    const float* pe  = (const float*)d_in[1];
    const float* Wq  = (const float*)d_in[2];
    const float* bq  = (const float*)d_in[3];
    const float* Wk  = (const float*)d_in[4];
    const float* bk  = (const float*)d_in[5];
    const float* Wv  = (const float*)d_in[6];
    const float* bv  = (const float*)d_in[7];
    const float* Wr  = (const float*)d_in[8];
    const float* br  = (const float*)d_in[9];
    const float* cb  = (const float*)d_in[10];
    const float* pb  = (const float*)d_in[11];
    const float* Wc  = (const float*)d_in[12];
    const float* bc  = (const float*)d_in[13];
    const float* W1  = (const float*)d_in[14];
    const float* b1  = (const float*)d_in[15];
    const float* W2  = (const float*)d_in[16];
    const float* b2  = (const float*)d_in[17];
    const float* lnw = (const float*)d_in[18];
    const float* lnb = (const float*)d_in[19];
    float* out = (float*)d_out;

    uint32_t *qcP, *qpP, *kP, *vP, *rP;
    float *attnP, *t1P, *aP, *h1P, *h2P;
    cudaGetSymbolAddress((void**)&qcP,   g_qc);
    cudaGetSymbolAddress((void**)&qpP,   g_qp);
    cudaGetSymbolAddress((void**)&kP,    g_k);
    cudaGetSymbolAddress((void**)&vP,    g_v);
    cudaGetSymbolAddress((void**)&rP,    g_r);
    cudaGetSymbolAddress((void**)&attnP, g_attn);
    cudaGetSymbolAddress((void**)&t1P,   g_t1);
    cudaGetSymbolAddress((void**)&aP,    g_a);
    cudaGetSymbolAddress((void**)&h1P,   g_h1);
    cudaGetSymbolAddress((void**)&h2P,   g_h2);

    const dim3 gBig(H_ / 128, M_ / 128);   // (4, 64)
    const dim3 gPos(H_ / 128, L_ / 128);   // (4, 16)

    gemm_kernel<MODE_NHD, EPI_QCQP_BF><<<gBig, 256>>>(x,  Wq, bq, cb, pb, qcP, qpP, M_, H_, H_);
    gemm_kernel<MODE_NHD, EPI_BF><<<gBig, 256>>>(x,  Wk, bk, nullptr, nullptr, kP, nullptr, M_, H_, H_);
    gemm_kernel<MODE_NHD, EPI_BF><<<gBig, 256>>>(x,  Wv, bv, nullptr, nullptr, vP, nullptr, M_, H_, H_);
    gemm_kernel<MODE_NHD, EPI_BF><<<gPos, 256>>>(pe, Wr, br, nullptr, nullptr, rP, nullptr, L_, H_, H_);

    cudaFuncSetAttribute(attn_kernel, cudaFuncAttributeMaxDynamicSharedMemorySize, ATTN_SMEM_BYTES);
    attn_kernel<<<dim3(L_ / 64, B_ * N_), 256, ATTN_SMEM_BYTES>>>(qcP, qpP, kP, vP, rP, attnP);

    gemm_kernel<MODE_T, EPI_BIAS><<<gBig, 256>>>(attnP, Wc, bc, nullptr, nullptr, t1P, nullptr, M_, H_, H_);
    ln_kernel<<<M_, 256>>>(t1P, x, lnw, lnb, aP);

    gemm_kernel<MODE_T, EPI_GELU><<<gBig, 256>>>(aP,  W1, b1, nullptr, nullptr, h1P, nullptr, M_, H_, H_);
    gemm_kernel<MODE_T, EPI_BIAS><<<gBig, 256>>>(h1P, W2, b2, nullptr, nullptr, h2P, nullptr, M_, H_, H_);
    ln_kernel<<<M_, 256>>>(aP, h2P, lnw, lnb, out);
}

// round 11
// speedup vs baseline: 3.8814x; 1.0129x over previous
#include <cuda_runtime.h>
#include <cuda_bf16.h>
#include <math.h>
#include <stdint.h>

#define B_  4
#define L_  2048
#define H_  512
#define N_  8
#define D_  64
#define M_  (B_*L_)   // 8192 rows
#define HW  256       // H_/2 words per row (bf16x2)

// ---------------- scratch ----------------
__device__ uint32_t g_qc[M_*HW];   // bf16x2
__device__ uint32_t g_qp[M_*HW];
__device__ uint32_t g_k [M_*HW];
__device__ uint32_t g_v [M_*HW];
__device__ uint32_t g_r [L_*HW];
__device__ float g_attn[M_*H_];
__device__ float g_t1  [M_*H_];
__device__ float g_a   [M_*H_];
__device__ float g_h1  [M_*H_];
__device__ float g_h2  [M_*H_];

// ---------------- helpers ----------------
__device__ __forceinline__ uint32_t fbits(float x) { return __float_as_uint(x); }
__device__ __forceinline__ uint32_t bf2(float x, float y) {
    __nv_bfloat162 t = __floats2bfloat162_rn(x, y);
    return *(uint32_t*)&t;
}
__device__ __forceinline__ void cpa16(void* dst, const void* src) {
    uint32_t d = (uint32_t)__cvta_generic_to_shared(dst);
    asm volatile("cp.async.ca.shared.global [%0], [%1], 16;" :: "r"(d), "l"(src));
}
#define CPA_COMMIT() asm volatile("cp.async.commit_group;")
#define CPA_WAIT1()  asm volatile("cp.async.wait_group 1;")
#define CPA_WAIT0()  asm volatile("cp.async.wait_group 0;")

__device__ __forceinline__ void mma_tf32(float* c,
                                         uint32_t a0, uint32_t a1, uint32_t a2, uint32_t a3,
                                         uint32_t b0, uint32_t b1) {
    asm("mma.sync.aligned.m16n8k8.row.col.f32.tf32.tf32.f32 "
        "{%0,%1,%2,%3}, {%4,%5,%6,%7}, {%8,%9}, {%0,%1,%2,%3};"
        : "+f"(c[0]), "+f"(c[1]), "+f"(c[2]), "+f"(c[3])
        : "r"(a0), "r"(a1), "r"(a2), "r"(a3), "r"(b0), "r"(b1));
}
__device__ __forceinline__ void mma_bf16(float* c,
                                         uint32_t a0, uint32_t a1, uint32_t a2, uint32_t a3,
                                         uint32_t b0, uint32_t b1) {
    asm("mma.sync.aligned.m16n8k16.row.col.f32.bf16.bf16.f32 "
        "{%0,%1,%2,%3}, {%4,%5,%6,%7}, {%8,%9}, {%0,%1,%2,%3};"
        : "+f"(c[0]), "+f"(c[1]), "+f"(c[2]), "+f"(c[3])
        : "r"(a0), "r"(a1), "r"(a2), "r"(a3), "r"(b0), "r"(b1));
}

// ---------------- GEMM (tf32, cp.async double-buffered) ----------------
enum { MODE_NHD = 0, MODE_T = 1 };
enum { EPI_BIAS = 0, EPI_QCQP_BF = 1, EPI_GELU = 2, EPI_BF = 3 };

template<int MODE, int EPI>
__global__ __launch_bounds__(256)
void gemm_kernel(const float* __restrict__ A, const float* __restrict__ W,
                 const float* __restrict__ bias, const float* __restrict__ bias2,
                 const float* __restrict__ bias3,
                 void* __restrict__ out1v, void* __restrict__ out2v,
                 int M, int N, int K)
{
    __shared__ float As[2][128][20];
    __shared__ float Bsm[2][2560];
    const int tid  = threadIdx.x;
    const int lane = tid & 31;
    const int w    = tid >> 5;
    const int rw64 = (w >> 2) << 6;
    const int cw32 = (w & 3) << 5;
    const int m0 = blockIdx.y << 7, c0 = blockIdx.x << 7;
    const int lq = lane >> 2;
    const int lr = lane & 3;

    float C[4][4][4];
#pragma unroll
    for (int mt = 0; mt < 4; mt++)
#pragma unroll
        for (int nt = 0; nt < 4; nt++)
#pragma unroll
            for (int e = 0; e < 4; e++) C[mt][nt][e] = 0.f;

    const int arow0 = tid >> 2, aq0 = (tid & 3) << 2;
    const int arow1 = (tid + 256) >> 2, aq1 = ((tid + 256) & 3) << 2;

    auto load_chunk = [&](int st, int k0) {
        cpa16(&As[st][arow0][aq0], A + (size_t)(m0 + arow0) * K + k0 + aq0);
        cpa16(&As[st][arow1][aq1], A + (size_t)(m0 + arow1) * K + k0 + aq1);
        if (MODE == MODE_NHD) {
#pragma unroll
            for (int jj = 0; jj < 2; jj++) {
                int f = tid + jj * 256;
                int kk = f >> 5, c4 = (f & 31) << 2;
                int cc = c0 + c4;
                cpa16(&Bsm[st][kk * 136 + c4],
                      W + (size_t)(cc >> 6) * ((size_t)K * 64)
                        + (size_t)(k0 + kk) * 64 + (cc & 63));
            }
        } else {
#pragma unroll
            for (int jj = 0; jj < 2; jj++) {
                int f = tid + jj * 256;
                int c = f >> 2, q = (f & 3) << 2;
                cpa16(&Bsm[st][c * 20 + q], W + (size_t)(c0 + c) * K + k0 + q);
            }
        }
    };

    const int NCH = K >> 4;
    load_chunk(0, 0);
    CPA_COMMIT();

    for (int ch = 0; ch < NCH; ch++) {
        if (ch + 1 < NCH) {
            load_chunk((ch + 1) & 1, (ch + 1) << 4);
            CPA_COMMIT();
            CPA_WAIT1();
        } else {
            CPA_WAIT0();
        }
        __syncthreads();
        const int st = ch & 1;
#pragma unroll
        for (int kc = 0; kc < 16; kc += 8) {
            uint32_t bf[4][2];
#pragma unroll
            for (int nt = 0; nt < 4; nt++) {
                int n = cw32 + 8 * nt + lq;
                if (MODE == MODE_NHD) {
                    bf[nt][0] = fbits(Bsm[st][(kc + lr) * 136 + n]);
                    bf[nt][1] = fbits(Bsm[st][(kc + 4 + lr) * 136 + n]);
                } else {
                    bf[nt][0] = fbits(Bsm[st][n * 20 + kc + lr]);
                    bf[nt][1] = fbits(Bsm[st][n * 20 + kc + 4 + lr]);
                }
            }
#pragma unroll
            for (int mt = 0; mt < 4; mt++) {
                int i = rw64 + 16 * mt + lq;
                uint32_t a0 = fbits(As[st][i][kc + lr]);
                uint32_t a1 = fbits(As[st][i + 8][kc + lr]);
                uint32_t a2 = fbits(As[st][i][kc + 4 + lr]);
                uint32_t a3 = fbits(As[st][i + 8][kc + 4 + lr]);
#pragma unroll
                for (int nt = 0; nt < 4; nt++)
                    mma_tf32(C[mt][nt], a0, a1, a2, a3, bf[nt][0], bf[nt][1]);
            }
        }
        __syncthreads();
    }

    const int NW = N >> 1;
#pragma unroll
    for (int mt = 0; mt < 4; mt++) {
        int m = m0 + rw64 + 16 * mt + lq;
#pragma unroll
        for (int nt = 0; nt < 4; nt++) {
            int c = c0 + cw32 + 8 * nt + 2 * lr;
            float b0 = bias[c], b1 = bias[c + 1];
            float v00 = C[mt][nt][0] + b0, v01 = C[mt][nt][1] + b1;
            float v10 = C[mt][nt][2] + b0, v11 = C[mt][nt][3] + b1;
            if (EPI == EPI_BIAS) {
                float* out1 = (float*)out1v;
                size_t o0 = (size_t)m * N + c, o1 = o0 + (size_t)8 * N;
                *(float2*)(out1 + o0) = make_float2(v00, v01);
                *(float2*)(out1 + o1) = make_float2(v10, v11);
            } else if (EPI == EPI_QCQP_BF) {
                uint32_t* o1 = (uint32_t*)out1v;
                uint32_t* o2 = (uint32_t*)out2v;
                float c20 = bias2[c], c21 = bias2[c + 1];
                float p20 = bias3[c], p21 = bias3[c + 1];
                size_t w0 = (size_t)m * NW + (c >> 1), w1 = w0 + (size_t)8 * NW;
                o1[w0] = bf2(v00 + c20, v01 + c21);
                o1[w1] = bf2(v10 + c20, v11 + c21);
                o2[w0] = bf2(v00 + p20, v01 + p21);
                o2[w1] = bf2(v10 + p20, v11 + p21);
            } else if (EPI == EPI_BF) {
                uint32_t* o1 = (uint32_t*)out1v;
                size_t w0 = (size_t)m * NW + (c >> 1), w1 = w0 + (size_t)8 * NW;
                o1[w0] = bf2(v00, v01);
                o1[w1] = bf2(v10, v11);
            } else { // GELU
                float* out1 = (float*)out1v;
                size_t o0 = (size_t)m * N + c, o1 = o0 + (size_t)8 * N;
                v00 = v00 * 0.5f * (1.f + erff(v00 * 0.70710678118654752f));
                v01 = v01 * 0.5f * (1.f + erff(v01 * 0.70710678118654752f));
                v10 = v10 * 0.5f * (1.f + erff(v10 * 0.70710678118654752f));
                v11 = v11 * 0.5f * (1.f + erff(v11 * 0.70710678118654752f));
                *(float2*)(out1 + o0) = make_float2(v00, v01);
                *(float2*)(out1 + o1) = make_float2(v10, v11);
            }
        }
    }
}

// ---------------- flash attention: warp-specialized ----------------
// warps 0-3 (compute): 16 query rows x 64 cols each; softmax warp-local in regs
// warps 4-7 (helper): rolling Sp band + K/r cp.async prefetch + V reg-transpose
#define WST 36
#define SPR 132
// words: qc 2304 + qp 2304 + K 2x2304 + vt 2304 + r 4608 + sp 8448 + p 2304 = 26880
#define ATTN_SMEM_BYTES (26880 * 4)   // 107520

__global__ __launch_bounds__(256, 2)
void attn_kernel(const uint32_t* __restrict__ qc, const uint32_t* __restrict__ qp,
                 const uint32_t* __restrict__ kg, const uint32_t* __restrict__ vg,
                 const uint32_t* __restrict__ rg, float* __restrict__ out)
{
    extern __shared__ char smraw[];
    uint32_t* qc32 = (uint32_t*)smraw;            // [i][dw] 64x36
    uint32_t* qp32 = qc32 + 2304;
    uint32_t* kb32 = qp32 + 2304;                 // 2 stages x 64x36
    uint32_t* vt32 = kb32 + 4608;                 // [d][jw] 64x36
    uint32_t* r32  = vt32 + 2304;                 // ring [p&127][dw] 128x36
    float*    sp_s = (float*)(r32 + 4608);        // ring [i][p&127] 64x132
    uint32_t* p32  = (uint32_t*)(sp_s + 64 * SPR);// [i][jw] 64x36
    uint16_t* vt16 = (uint16_t*)vt32;

    const int tid  = threadIdx.x;
    const int lane = tid & 31;
    const int w    = tid >> 5;
    const bool comp = (w < 4);
    const int lq = lane >> 2, lr = lane & 3;

    const int bh = blockIdx.y;
    const int b  = bh >> 3, n = bh & 7;
    const int i0 = ((int)gridDim.x - 1 - (int)blockIdx.x) << 6;
    const int colw = n << 5;   // word col offset
    const size_t rowb = (size_t)(b * L_);
    const size_t qbW = (rowb + i0) * HW + colw;

    // full-block loader indices (preloop)
    const int fr  = tid >> 3;           // 0..31
    const int fc4 = (tid & 7) << 2;     // word col {0,4,...,28}
    // helper K/r loader indices (in-loop, 128 threads, 2 granules/row-pass)
    const int t2  = tid & 127;
    const int hr  = t2 >> 2;            // 0..31
    const int hc  = (t2 & 3) << 2;      // word col {0,4,8,12}; +16 for 2nd granule
    // helper V indices: 64 rows x 2 threads, 4 granules each (full 32-word rows)
    const int vrow = t2 >> 1;           // 0..63
    const int vcb  = (t2 & 1) << 4;     // word col base {0,16}

    const int ni = (i0 >> 6) + 1;
    const int pbase0 = (L_ - 64) - i0;

    // ---- preloop: stage qc/qp, K(0), full r band (all 256 threads)
#pragma unroll
    for (int jj = 0; jj < 2; jj++) {
        int row = fr + 32 * jj;
        cpa16(&qc32[row * WST + fc4], qc + qbW + (size_t)row * HW + fc4);
        cpa16(&qp32[row * WST + fc4], qp + qbW + (size_t)row * HW + fc4);
        cpa16(&kb32[row * WST + fc4], kg + (rowb + row) * HW + colw + fc4);
    }
#pragma unroll
    for (int jj = 0; jj < 4; jj++) {
        int row = fr + 32 * jj;       // 0..127
        int p = pbase0 + row;
        uint32_t* dst = &r32[(p & 127) * WST + fc4];
        if (p < L_) cpa16(dst, rg + (size_t)p * HW + colw + fc4);
        else { uint4 z = make_uint4(0,0,0,0); *(uint4*)dst = z; }
    }
    CPA_COMMIT();

    // helper V(0) into regs: full row coverage (4 granules per thread)
    uint4 vreg[4];
    if (!comp) {
#pragma unroll
        for (int g = 0; g < 4; g++)
            vreg[g] = *(const uint4*)(vg + (rowb + vrow) * HW + colw + vcb + 4 * g);
    }

    // compute-warp state
    float O[8][4];
    float mA = -INFINITY, mB = -INFINITY, lA = 0.f, lB = 0.f;
#pragma unroll
    for (int nt = 0; nt < 8; nt++)
#pragma unroll
        for (int e = 0; e < 4; e++) O[nt][e] = 0.f;

    const int ia = ((w & 3) << 4) + lq, ib = ia + 8;        // compute rows
    const int ja = (((w - 4) & 3) << 4) + lq, jb = ja + 8;  // helper sp rows

    for (int ch = 0; ch < ni; ch++) {
        const int j0 = ch << 6;
        const int pbase = pbase0 + j0;
        if (ch) __syncthreads();    // sync0: prev PV + sp/r reads done
        if (!comp) {
            // V regs -> transposed smem (all 64 d rows)
#pragma unroll
            for (int g = 0; g < 4; g++) {
                int d0 = (vcb + 4 * g) << 1;    // d-half base
                uint4 cv = vreg[g];
                vt16[(d0 + 0) * 72 + vrow] = (uint16_t)(cv.x);
                vt16[(d0 + 1) * 72 + vrow] = (uint16_t)(cv.x >> 16);
                vt16[(d0 + 2) * 72 + vrow] = (uint16_t)(cv.y);
                vt16[(d0 + 3) * 72 + vrow] = (uint16_t)(cv.y >> 16);
                vt16[(d0 + 4) * 72 + vrow] = (uint16_t)(cv.z);
                vt16[(d0 + 5) * 72 + vrow] = (uint16_t)(cv.z >> 16);
                vt16[(d0 + 6) * 72 + vrow] = (uint16_t)(cv.w);
                vt16[(d0 + 7) * 72 + vrow] = (uint16_t)(cv.w >> 16);
            }
        }
        CPA_WAIT0();
        __syncthreads();            // sync1: K/r/qc/qp + vt visible
        const uint32_t* kst = kb32 + (ch & 1) * 2304;

        float S[8][4];
        if (comp) {
            // ---- S = qc @ k^T : 16 rows x 64 cols per warp
#pragma unroll
            for (int nt = 0; nt < 8; nt++)
#pragma unroll
                for (int e = 0; e < 4; e++) S[nt][e] = 0.f;
#pragma unroll
            for (int kq = 0; kq < 32; kq += 8) {
                uint32_t a0 = qc32[ia * WST + kq + lr];
                uint32_t a1 = qc32[ib * WST + kq + lr];
                uint32_t a2 = qc32[ia * WST + kq + 4 + lr];
                uint32_t a3 = qc32[ib * WST + kq + 4 + lr];
#pragma unroll
                for (int nt = 0; nt < 8; nt++) {
                    int nn = 8 * nt + lq;
                    mma_bf16(S[nt], a0, a1, a2, a3,
                             kst[nn * WST + kq + lr], kst[nn * WST + kq + 4 + lr]);
                }
            }
        } else {
            // ---- Sp = qp @ r^T (helper warps): rows ja/jb
            if (ch == 0) {
#pragma unroll
                for (int half = 0; half < 2; half++) {
                    float SP[8][4];
#pragma unroll
                    for (int nt = 0; nt < 8; nt++)
#pragma unroll
                        for (int e = 0; e < 4; e++) SP[nt][e] = 0.f;
#pragma unroll
                    for (int kq = 0; kq < 32; kq += 8) {
                        uint32_t a0 = qp32[ja * WST + kq + lr];
                        uint32_t a1 = qp32[jb * WST + kq + lr];
                        uint32_t a2 = qp32[ja * WST + kq + 4 + lr];
                        uint32_t a3 = qp32[jb * WST + kq + 4 + lr];
#pragma unroll
                        for (int nt = 0; nt < 8; nt++) {
                            int rr = (pbase + 64 * half + 8 * nt + lq) & 127;
                            mma_bf16(SP[nt], a0, a1, a2, a3,
                                     r32[rr * WST + kq + lr], r32[rr * WST + kq + 4 + lr]);
                        }
                    }
#pragma unroll
                    for (int nt = 0; nt < 8; nt++) {
                        int cr = (pbase + 64 * half + 8 * nt + 2 * lr) & 127;
                        *(float2*)&sp_s[ja * SPR + cr] = make_float2(SP[nt][0], SP[nt][1]);
                        *(float2*)&sp_s[jb * SPR + cr] = make_float2(SP[nt][2], SP[nt][3]);
                    }
                }
            } else {
                float SP[8][4];
#pragma unroll
                for (int nt = 0; nt < 8; nt++)
#pragma unroll
                    for (int e = 0; e < 4; e++) SP[nt][e] = 0.f;
#pragma unroll
                for (int kq = 0; kq < 32; kq += 8) {
                    uint32_t a0 = qp32[ja * WST + kq + lr];
                    uint32_t a1 = qp32[jb * WST + kq + lr];
                    uint32_t a2 = qp32[ja * WST + kq + 4 + lr];
                    uint32_t a3 = qp32[jb * WST + kq + 4 + lr];
#pragma unroll
                    for (int nt = 0; nt < 8; nt++) {
                        int rr = (pbase + 64 + 8 * nt + lq) & 127;
                        mma_bf16(SP[nt], a0, a1, a2, a3,
                                 r32[rr * WST + kq + lr], r32[rr * WST + kq + 4 + lr]);
                    }
                }
#pragma unroll
                for (int nt = 0; nt < 8; nt++) {
                    int cr = (pbase + 64 + 8 * nt + 2 * lr) & 127;
                    *(float2*)&sp_s[ja * SPR + cr] = make_float2(SP[nt][0], SP[nt][1]);
                    *(float2*)&sp_s[jb * SPR + cr] = make_float2(SP[nt][2], SP[nt][3]);
                }
            }
        }
        __syncthreads();            // sync2: sp visible; helper r-reads done

        if (comp) {
            // ---- shift + scale + mask
            const bool diag = (j0 == i0);
#pragma unroll
            for (int nt = 0; nt < 8; nt++) {
                int jbase = 8 * nt + 2 * lr;
#pragma unroll
                for (int e = 0; e < 4; e++) {
                    int iloc = (e >= 2) ? ib : ia;
                    int jloc = jbase + (e & 1);
                    int cr = (pbase + 63 + jloc - iloc) & 127;
                    float s = (S[nt][e] + sp_s[iloc * SPR + cr]) * 0.125f;
                    if (diag && jloc > iloc) s = -1e30f;
                    S[nt][e] = s;
                }
            }
            // ---- warp-local softmax (row = 4 lanes)
            float ma = -INFINITY, mb = -INFINITY;
#pragma unroll
            for (int nt = 0; nt < 8; nt++) {
                ma = fmaxf(ma, fmaxf(S[nt][0], S[nt][1]));
                mb = fmaxf(mb, fmaxf(S[nt][2], S[nt][3]));
            }
            ma = fmaxf(ma, __shfl_xor_sync(0xffffffffu, ma, 1));
            ma = fmaxf(ma, __shfl_xor_sync(0xffffffffu, ma, 2));
            mb = fmaxf(mb, __shfl_xor_sync(0xffffffffu, mb, 1));
            mb = fmaxf(mb, __shfl_xor_sync(0xffffffffu, mb, 2));
            float mna = fmaxf(mA, ma), mnb = fmaxf(mB, mb);
            float ca = __expf(mA - mna), cb = __expf(mB - mnb);
            float sa = 0.f, sb = 0.f;
#pragma unroll
            for (int nt = 0; nt < 8; nt++) {
                float p0 = __expf(S[nt][0] - mna);
                float p1 = __expf(S[nt][1] - mna);
                float p2 = __expf(S[nt][2] - mnb);
                float p3 = __expf(S[nt][3] - mnb);
                sa += p0 + p1; sb += p2 + p3;
                int ccw = 4 * nt + lr;
                p32[ia * WST + ccw] = bf2(p0, p1);
                p32[ib * WST + ccw] = bf2(p2, p3);
            }
            sa += __shfl_xor_sync(0xffffffffu, sa, 1);
            sa += __shfl_xor_sync(0xffffffffu, sa, 2);
            sb += __shfl_xor_sync(0xffffffffu, sb, 1);
            sb += __shfl_xor_sync(0xffffffffu, sb, 2);
            lA = lA * ca + sa; lB = lB * cb + sb;
            mA = mna; mB = mnb;
#pragma unroll
            for (int nt = 0; nt < 8; nt++) {
                O[nt][0] *= ca; O[nt][1] *= ca;
                O[nt][2] *= cb; O[nt][3] *= cb;
            }
        } else if (ch + 1 < ni) {
            // ---- helper: prefetch K(ch+1), r(ch+1); V(ch+1) into regs
#pragma unroll
            for (int jj = 0; jj < 2; jj++) {
                int row = hr + 32 * jj;
                cpa16(&kb32[((ch + 1) & 1) * 2304 + row * WST + hc],
                      kg + (rowb + j0 + 64 + row) * HW + colw + hc);
                cpa16(&kb32[((ch + 1) & 1) * 2304 + row * WST + hc + 16],
                      kg + (rowb + j0 + 64 + row) * HW + colw + hc + 16);
                int p = pbase + 128 + row;
                uint32_t* dst = &r32[(p & 127) * WST + hc];
                uint32_t* dst2 = &r32[(p & 127) * WST + hc + 16];
                if (p < L_) {
                    cpa16(dst,  rg + (size_t)p * HW + colw + hc);
                    cpa16(dst2, rg + (size_t)p * HW + colw + hc + 16);
                } else {
                    uint4 z = make_uint4(0,0,0,0);
                    *(uint4*)dst = z; *(uint4*)dst2 = z;
                }
            }
            CPA_COMMIT();
#pragma unroll
            for (int g = 0; g < 4; g++)
                vreg[g] = *(const uint4*)(vg + (rowb + j0 + 64 + vrow) * HW + colw + vcb + 4 * g);
        }
        __syncthreads();            // sync3: P visible

        if (comp) {
            // ---- O += P @ V
#pragma unroll
            for (int kq = 0; kq < 32; kq += 8) {
                uint32_t a0 = p32[ia * WST + kq + lr];
                uint32_t a1 = p32[ib * WST + kq + lr];
                uint32_t a2 = p32[ia * WST + kq + 4 + lr];
                uint32_t a3 = p32[ib * WST + kq + 4 + lr];
#pragma unroll
                for (int nt = 0; nt < 8; nt++) {
                    int nn = 8 * nt + lq;
                    mma_bf16(O[nt], a0, a1, a2, a3,
                             vt32[nn * WST + kq + lr], vt32[nn * WST + kq + 4 + lr]);
                }
            }
        }
    }

    if (comp) {
        float la = 1.f / lA;
        float lb = 1.f / lB;
        const size_t obase = (rowb + i0) * H_ + (n << 6);
#pragma unroll
        for (int nt = 0; nt < 8; nt++) {
            int cc = 8 * nt + 2 * lr;
            *(float2*)(out + obase + (size_t)ia * H_ + cc) = make_float2(O[nt][0] * la, O[nt][1] * la);
            *(float2*)(out + obase + (size_t)ib * H_ + cc) = make_float2(O[nt][2] * lb, O[nt][3] * lb);
        }
    }
}

// ---------------- fused residual-add + LayerNorm ----------------
__global__ __launch_bounds__(256)
void ln_kernel(const float* __restrict__ a, const float* __restrict__ b,
               const float* __restrict__ w, const float* __restrict__ beta,
               float* __restrict__ out)
{
    const int row = blockIdx.x;
    const int tid = threadIdx.x;
    const size_t base = (size_t)row * H_;
    float x0 = a[base + tid]       + b[base + tid];
    float x1 = a[base + tid + 256] + b[base + tid + 256];
    float s  = x0 + x1;
    float sq = x0 * x0 + x1 * x1;
#pragma unroll
    for (int o = 16; o > 0; o >>= 1) {
        s  += __shfl_xor_sync(0xffffffffu, s,  o);
        sq += __shfl_xor_sync(0xffffffffu, sq, o);
    }
    __shared__ float rs[8], rq[8];
    int wid = tid >> 5;
    if ((tid & 31) == 0) { rs[wid] = s; rq[wid] = sq; }
    __syncthreads();
    if (tid < 32) {
        float ss = (tid < 8) ? rs[tid] : 0.f;
        float qq = (tid < 8) ? rq[tid] : 0.f;
#pragma unroll
        for (int o = 4; o > 0; o >>= 1) {
            ss += __shfl_xor_sync(0xffffffffu, ss, o);
            qq += __shfl_xor_sync(0xffffffffu, qq, o);
        }
        if (tid == 0) { rs[0] = ss; rq[0] = qq; }
    }
    __syncthreads();
    float mean = rs[0] * (1.f / H_);
    float var  = rq[0] * (1.f / H_) - mean * mean;
    float inv  = rsqrtf(var + 1e-12f);
    out[base + tid]       = w[tid]       * (x0 - mean) * inv + beta[tid];
    out[base + tid + 256] = w[tid + 256] * (x1 - mean) * inv + beta[tid + 256];
}

// ---------------- launcher ----------------
extern "C" void kernel_launch(void* const* d_in, const int* in_sizes, int n_in,
                              void* d_out, int out_size)
{
    const float* x   = (const float*)d_in[0];
    const float* pe  = (const float*)d_in[1];
    const float* Wq  = (const float*)d_in[2];
    const float* bq  = (const float*)d_in[3];
    const float* Wk  = (const float*)d_in[4];
    const float* bk  = (const float*)d_in[5];
    const float* Wv  = (const float*)d_in[6];
    const float* bv  = (const float*)d_in[7];
    const float* Wr  = (const float*)d_in[8];
    const float* br  = (const float*)d_in[9];
    const float* cb  = (const float*)d_in[10];
    const float* pb  = (const float*)d_in[11];
    const float* Wc  = (const float*)d_in[12];
    const float* bc  = (const float*)d_in[13];
    const float* W1  = (const float*)d_in[14];
    const float* b1  = (const float*)d_in[15];
    const float* W2  = (const float*)d_in[16];
    const float* b2  = (const float*)d_in[17];
    const float* lnw = (const float*)d_in[18];
    const float* lnb = (const float*)d_in[19];
    float* out = (float*)d_out;

    uint32_t *qcP, *qpP, *kP, *vP, *rP;
    float *attnP, *t1P, *aP, *h1P, *h2P;
    cudaGetSymbolAddress((void**)&qcP,   g_qc);
    cudaGetSymbolAddress((void**)&qpP,   g_qp);
    cudaGetSymbolAddress((void**)&kP,    g_k);
    cudaGetSymbolAddress((void**)&vP,    g_v);
    cudaGetSymbolAddress((void**)&rP,    g_r);
    cudaGetSymbolAddress((void**)&attnP, g_attn);
    cudaGetSymbolAddress((void**)&t1P,   g_t1);
    cudaGetSymbolAddress((void**)&aP,    g_a);
    cudaGetSymbolAddress((void**)&h1P,   g_h1);
    cudaGetSymbolAddress((void**)&h2P,   g_h2);

    const dim3 gBig(H_ / 128, M_ / 128);   // (4, 64)
    const dim3 gPos(H_ / 128, L_ / 128);   // (4, 16)

    gemm_kernel<MODE_NHD, EPI_QCQP_BF><<<gBig, 256>>>(x,  Wq, bq, cb, pb, qcP, qpP, M_, H_, H_);
    gemm_kernel<MODE_NHD, EPI_BF><<<gBig, 256>>>(x,  Wk, bk, nullptr, nullptr, kP, nullptr, M_, H_, H_);
    gemm_kernel<MODE_NHD, EPI_BF><<<gBig, 256>>>(x,  Wv, bv, nullptr, nullptr, vP, nullptr, M_, H_, H_);
    gemm_kernel<MODE_NHD, EPI_BF><<<gPos, 256>>>(pe, Wr, br, nullptr, nullptr, rP, nullptr, L_, H_, H_);

    cudaFuncSetAttribute(attn_kernel, cudaFuncAttributeMaxDynamicSharedMemorySize, ATTN_SMEM_BYTES);
    attn_kernel<<<dim3(L_ / 64, B_ * N_), 256, ATTN_SMEM_BYTES>>>(qcP, qpP, kP, vP, rP, attnP);

    gemm_kernel<MODE_T, EPI_BIAS><<<gBig, 256>>>(attnP, Wc, bc, nullptr, nullptr, t1P, nullptr, M_, H_, H_);
    ln_kernel<<<M_, 256>>>(t1P, x, lnw, lnb, aP);

    gemm_kernel<MODE_T, EPI_GELU><<<gBig, 256>>>(aP,  W1, b1, nullptr, nullptr, h1P, nullptr, M_, H_, H_);
    gemm_kernel<MODE_T, EPI_BIAS><<<gBig, 256>>>(h1P, W2, b2, nullptr, nullptr, h2P, nullptr, M_, H_, H_);
    ln_kernel<<<M_, 256>>>(aP, h2P, lnw, lnb, out);
}

// round 13
// speedup vs baseline: 4.5192x; 1.1643x over previous
#include <cuda_runtime.h>
#include <cuda_bf16.h>
#include <math.h>
#include <stdint.h>

#define B_  4
#define L_  2048
#define H_  512
#define N_  8
#define D_  64
#define M_  (B_*L_)   // 8192 rows
#define HW  256       // H_/2 words per row (bf16x2)

// ---------------- scratch ----------------
__device__ uint32_t g_qc[M_*HW];   // bf16x2
__device__ uint32_t g_qp[M_*HW];
__device__ uint32_t g_k [M_*HW];
__device__ uint32_t g_v [M_*HW];
__device__ uint32_t g_r [L_*HW];
__device__ float g_attn[M_*H_];
__device__ float g_t1  [M_*H_];
__device__ float g_a   [M_*H_];
__device__ float g_h1  [M_*H_];
__device__ float g_h2  [M_*H_];

// ---------------- helpers ----------------
__device__ __forceinline__ uint32_t fbits(float x) { return __float_as_uint(x); }
__device__ __forceinline__ uint32_t bf2(float x, float y) {
    __nv_bfloat162 t = __floats2bfloat162_rn(x, y);
    return *(uint32_t*)&t;
}
__device__ __forceinline__ float bfu(uint16_t h) {
    return __uint_as_float(((uint32_t)h) << 16);
}
__device__ __forceinline__ void cpa16(void* dst, const void* src) {
    uint32_t d = (uint32_t)__cvta_generic_to_shared(dst);
    asm volatile("cp.async.ca.shared.global [%0], [%1], 16;" :: "r"(d), "l"(src));
}
#define CPA_COMMIT() asm volatile("cp.async.commit_group;")
#define CPA_WAIT1()  asm volatile("cp.async.wait_group 1;")
#define CPA_WAIT0()  asm volatile("cp.async.wait_group 0;")

__device__ __forceinline__ void mma_tf32(float* c,
                                         uint32_t a0, uint32_t a1, uint32_t a2, uint32_t a3,
                                         uint32_t b0, uint32_t b1) {
    asm("mma.sync.aligned.m16n8k8.row.col.f32.tf32.tf32.f32 "
        "{%0,%1,%2,%3}, {%4,%5,%6,%7}, {%8,%9}, {%0,%1,%2,%3};"
        : "+f"(c[0]), "+f"(c[1]), "+f"(c[2]), "+f"(c[3])
        : "r"(a0), "r"(a1), "r"(a2), "r"(a3), "r"(b0), "r"(b1));
}
__device__ __forceinline__ void mma_bf16(float* c,
                                         uint32_t a0, uint32_t a1, uint32_t a2, uint32_t a3,
                                         uint32_t b0, uint32_t b1) {
    asm("mma.sync.aligned.m16n8k16.row.col.f32.bf16.bf16.f32 "
        "{%0,%1,%2,%3}, {%4,%5,%6,%7}, {%8,%9}, {%0,%1,%2,%3};"
        : "+f"(c[0]), "+f"(c[1]), "+f"(c[2]), "+f"(c[3])
        : "r"(a0), "r"(a1), "r"(a2), "r"(a3), "r"(b0), "r"(b1));
}
__device__ __forceinline__ void ldsm4(uint32_t* r, uint32_t a) {
    asm volatile("ldmatrix.sync.aligned.m8n8.x4.shared.b16 {%0,%1,%2,%3}, [%4];"
        : "=r"(r[0]), "=r"(r[1]), "=r"(r[2]), "=r"(r[3]) : "r"(a));
}
__device__ __forceinline__ void ldsm4t(uint32_t* r, uint32_t a) {
    asm volatile("ldmatrix.sync.aligned.m8n8.x4.trans.shared.b16 {%0,%1,%2,%3}, [%4];"
        : "=r"(r[0]), "=r"(r[1]), "=r"(r[2]), "=r"(r[3]) : "r"(a));
}

// ---------------- GEMM (tf32, cp.async double-buffered) -- unchanged ----------------
enum { MODE_NHD = 0, MODE_T = 1 };
enum { EPI_BIAS = 0, EPI_QCQP_BF = 1, EPI_GELU = 2, EPI_BF = 3 };

template<int MODE, int EPI>
__global__ __launch_bounds__(256)
void gemm_kernel(const float* __restrict__ A, const float* __restrict__ W,
                 const float* __restrict__ bias, const float* __restrict__ bias2,
                 const float* __restrict__ bias3,
                 void* __restrict__ out1v, void* __restrict__ out2v,
                 int M, int N, int K)
{
    __shared__ float As[2][128][20];
    __shared__ float Bsm[2][2560];
    const int tid  = threadIdx.x;
    const int lane = tid & 31;
    const int w    = tid >> 5;
    const int rw64 = (w >> 2) << 6;
    const int cw32 = (w & 3) << 5;
    const int m0 = blockIdx.y << 7, c0 = blockIdx.x << 7;
    const int lq = lane >> 2;
    const int lr = lane & 3;

    float C[4][4][4];
#pragma unroll
    for (int mt = 0; mt < 4; mt++)
#pragma unroll
        for (int nt = 0; nt < 4; nt++)
#pragma unroll
            for (int e = 0; e < 4; e++) C[mt][nt][e] = 0.f;

    const int arow0 = tid >> 2, aq0 = (tid & 3) << 2;
    const int arow1 = (tid + 256) >> 2, aq1 = ((tid + 256) & 3) << 2;

    auto load_chunk = [&](int st, int k0) {
        cpa16(&As[st][arow0][aq0], A + (size_t)(m0 + arow0) * K + k0 + aq0);
        cpa16(&As[st][arow1][aq1], A + (size_t)(m0 + arow1) * K + k0 + aq1);
        if (MODE == MODE_NHD) {
#pragma unroll
            for (int jj = 0; jj < 2; jj++) {
                int f = tid + jj * 256;
                int kk = f >> 5, c4 = (f & 31) << 2;
                int cc = c0 + c4;
                cpa16(&Bsm[st][kk * 136 + c4],
                      W + (size_t)(cc >> 6) * ((size_t)K * 64)
                        + (size_t)(k0 + kk) * 64 + (cc & 63));
            }
        } else {
#pragma unroll
            for (int jj = 0; jj < 2; jj++) {
                int f = tid + jj * 256;
                int c = f >> 2, q = (f & 3) << 2;
                cpa16(&Bsm[st][c * 20 + q], W + (size_t)(c0 + c) * K + k0 + q);
            }
        }
    };

    const int NCH = K >> 4;
    load_chunk(0, 0);
    CPA_COMMIT();

    for (int ch = 0; ch < NCH; ch++) {
        if (ch + 1 < NCH) {
            load_chunk((ch + 1) & 1, (ch + 1) << 4);
            CPA_COMMIT();
            CPA_WAIT1();
        } else {
            CPA_WAIT0();
        }
        __syncthreads();
        const int st = ch & 1;
#pragma unroll
        for (int kc = 0; kc < 16; kc += 8) {
            uint32_t bf[4][2];
#pragma unroll
            for (int nt = 0; nt < 4; nt++) {
                int n = cw32 + 8 * nt + lq;
                if (MODE == MODE_NHD) {
                    bf[nt][0] = fbits(Bsm[st][(kc + lr) * 136 + n]);
                    bf[nt][1] = fbits(Bsm[st][(kc + 4 + lr) * 136 + n]);
                } else {
                    bf[nt][0] = fbits(Bsm[st][n * 20 + kc + lr]);
                    bf[nt][1] = fbits(Bsm[st][n * 20 + kc + 4 + lr]);
                }
            }
#pragma unroll
            for (int mt = 0; mt < 4; mt++) {
                int i = rw64 + 16 * mt + lq;
                uint32_t a0 = fbits(As[st][i][kc + lr]);
                uint32_t a1 = fbits(As[st][i + 8][kc + lr]);
                uint32_t a2 = fbits(As[st][i][kc + 4 + lr]);
                uint32_t a3 = fbits(As[st][i + 8][kc + 4 + lr]);
#pragma unroll
                for (int nt = 0; nt < 4; nt++)
                    mma_tf32(C[mt][nt], a0, a1, a2, a3, bf[nt][0], bf[nt][1]);
            }
        }
        __syncthreads();
    }

    const int NW = N >> 1;
#pragma unroll
    for (int mt = 0; mt < 4; mt++) {
        int m = m0 + rw64 + 16 * mt + lq;
#pragma unroll
        for (int nt = 0; nt < 4; nt++) {
            int c = c0 + cw32 + 8 * nt + 2 * lr;
            float b0 = bias[c], b1 = bias[c + 1];
            float v00 = C[mt][nt][0] + b0, v01 = C[mt][nt][1] + b1;
            float v10 = C[mt][nt][2] + b0, v11 = C[mt][nt][3] + b1;
            if (EPI == EPI_BIAS) {
                float* out1 = (float*)out1v;
                size_t o0 = (size_t)m * N + c, o1 = o0 + (size_t)8 * N;
                *(float2*)(out1 + o0) = make_float2(v00, v01);
                *(float2*)(out1 + o1) = make_float2(v10, v11);
            } else if (EPI == EPI_QCQP_BF) {
                uint32_t* o1 = (uint32_t*)out1v;
                uint32_t* o2 = (uint32_t*)out2v;
                float c20 = bias2[c], c21 = bias2[c + 1];
                float p20 = bias3[c], p21 = bias3[c + 1];
                size_t w0 = (size_t)m * NW + (c >> 1), w1 = w0 + (size_t)8 * NW;
                o1[w0] = bf2(v00 + c20, v01 + c21);
                o1[w1] = bf2(v10 + c20, v11 + c21);
                o2[w0] = bf2(v00 + p20, v01 + p21);
                o2[w1] = bf2(v10 + p20, v11 + p21);
            } else if (EPI == EPI_BF) {
                uint32_t* o1 = (uint32_t*)out1v;
                size_t w0 = (size_t)m * NW + (c >> 1), w1 = w0 + (size_t)8 * NW;
                o1[w0] = bf2(v00, v01);
                o1[w1] = bf2(v10, v11);
            } else { // GELU
                float* out1 = (float*)out1v;
                size_t o0 = (size_t)m * N + c, o1 = o0 + (size_t)8 * N;
                v00 = v00 * 0.5f * (1.f + erff(v00 * 0.70710678118654752f));
                v01 = v01 * 0.5f * (1.f + erff(v01 * 0.70710678118654752f));
                v10 = v10 * 0.5f * (1.f + erff(v10 * 0.70710678118654752f));
                v11 = v11 * 0.5f * (1.f + erff(v11 * 0.70710678118654752f));
                *(float2*)(out1 + o0) = make_float2(v00, v01);
                *(float2*)(out1 + o1) = make_float2(v10, v11);
            }
        }
    }
}

// ---------------- flash attention v3: 1 barrier/iter, ldmatrix, no-max softmax ----------------
#define WST 36           // row stride (words) for qc/qp/K/V/r tiles
#define SPW 97           // sp ring row stride (words); 194 bf16 slots (192 used)
// word offsets
#define QC_O 0
#define QP_O 2304
#define K_O  4608        // 2 stages x 2304
#define V_O  9216        // 2 stages x 2304
#define R_O  13824       // 192 x 36
#define SP_O 20736       // 64 x 97
#define SM_WORDS 26944
#define ATTN_SMEM_BYTES (SM_WORDS * 4)   // 107776

__global__ __launch_bounds__(256, 2)
void attn_kernel(const uint32_t* __restrict__ qcg, const uint32_t* __restrict__ qpg,
                 const uint32_t* __restrict__ kg, const uint32_t* __restrict__ vg,
                 const uint32_t* __restrict__ rg, float* __restrict__ out)
{
    extern __shared__ uint32_t sm[];
    const uint32_t sbase = (uint32_t)__cvta_generic_to_shared(sm);
    uint16_t* sp16 = (uint16_t*)(sm + SP_O);

    const int tid  = threadIdx.x;
    const int lane = tid & 31;
    const int w    = tid >> 5;
    const bool comp = (w < 4);
    const int lq = lane >> 2, lr = lane & 3;
    const int lt = lane >> 3, lu = lane & 7;
    // ldmatrix lane address components
    const int bn  = (lt >> 1) * 8 + lu;   // non-trans B (K/r): n-row
    const int bk  = (lt & 1) * 4;         // non-trans B: k-word
    const int vj  = (lt & 1) * 8 + lu;    // trans B (V): j-row
    const int vd4 = (lt >> 1) * 4;        // trans B: d-word
    const int ar  = (lt & 1) * 8 + lu;    // A: row
    const int ak  = (lt >> 1) * 4;        // A: k-word

    const int bh = blockIdx.y;
    const int b  = bh >> 3, n = bh & 7;
    const int i0 = ((int)gridDim.x - 1 - (int)blockIdx.x) << 6;
    const int colw = n << 5;
    const size_t rowb = (size_t)(b * L_);
    const int ni = (i0 >> 6) + 1;
    const int bl0 = 1984 - i0;            // band base p at j0=0 (>= 0, mult of 64)

    // ---- prologue loads: qc, qp, K(0), V(0), r blocks 0..2
#pragma unroll
    for (int g = 0; g < 2; g++) {
        int idx = tid + 256 * g;
        int row = idx >> 3, gg = (idx & 7) << 2;
        cpa16(sm + QC_O + row * WST + gg, qcg + (rowb + i0 + row) * HW + colw + gg);
        cpa16(sm + QP_O + row * WST + gg, qpg + (rowb + i0 + row) * HW + colw + gg);
        cpa16(sm + K_O + row * WST + gg,  kg  + (rowb + row) * HW + colw + gg);
        cpa16(sm + V_O + row * WST + gg,  vg  + (rowb + row) * HW + colw + gg);
    }
#pragma unroll
    for (int g = 0; g < 6; g++) {
        int idx = tid + 256 * g;
        int row = idx >> 3, gg = (idx & 7) << 2;
        int p = bl0 + row;
        uint32_t* dst = sm + R_O + (p % 192) * WST + gg;
        if (p < L_) cpa16(dst, rg + (size_t)p * HW + colw + gg);
        else        *(uint4*)dst = make_uint4(0, 0, 0, 0);
    }
    CPA_COMMIT();
    CPA_WAIT0();
    __syncthreads();

    // ---- loop-invariant A fragments (comp: qc; helper: qp)
    uint32_t aqf[4][4];
    {
        const uint32_t abase = sbase + (comp ? QC_O : QP_O) * 4;
        const int arow = ((comp ? (w & 3) : (w - 4)) << 4) + ar;
#pragma unroll
        for (int k4 = 0; k4 < 4; k4++)
            ldsm4(aqf[k4], abase + (uint32_t)(arow * WST + k4 * 8 + ak) * 4);
    }

    const int hrow = ((w - 4) & 3) << 4;   // helper warp row base
    auto sp_block = [&](int bidx) {
        const int slotb = (bl0 + 64 * bidx) % 192;
        float SP[8][4];
#pragma unroll
        for (int nt = 0; nt < 8; nt++)
#pragma unroll
            for (int e = 0; e < 4; e++) SP[nt][e] = 0.f;
#pragma unroll
        for (int k4 = 0; k4 < 4; k4++) {
#pragma unroll
            for (int ntp = 0; ntp < 4; ntp++) {
                uint32_t bb[4];
                ldsm4(bb, sbase + (uint32_t)(R_O + (slotb + 16 * ntp + bn) * WST
                                             + k4 * 8 + bk) * 4);
                mma_bf16(SP[2 * ntp],     aqf[k4][0], aqf[k4][1], aqf[k4][2], aqf[k4][3],
                         bb[0], bb[1]);
                mma_bf16(SP[2 * ntp + 1], aqf[k4][0], aqf[k4][1], aqf[k4][2], aqf[k4][3],
                         bb[2], bb[3]);
            }
        }
        const int ja = hrow + lq, jb = ja + 8;
#pragma unroll
        for (int nt = 0; nt < 8; nt++) {
            int sw_ = (slotb + 8 * nt + 2 * lr) >> 1;
            sm[SP_O + ja * SPW + sw_] = bf2(SP[nt][0], SP[nt][1]);
            sm[SP_O + jb * SPW + sw_] = bf2(SP[nt][2], SP[nt][3]);
        }
    };

    // ---- prologue compute: helpers build Sp blocks 0 and 1
    if (!comp) { sp_block(0); sp_block(1); }

    float O[8][4];
    float l_lo = 0.f, l_hi = 0.f;
#pragma unroll
    for (int nt = 0; nt < 8; nt++)
#pragma unroll
        for (int e = 0; e < 4; e++) O[nt][e] = 0.f;
    const int ia = ((w & 3) << 4) + lq, ib = ia + 8;
    const int t2 = tid & 127;

    for (int ch = 0; ch < ni; ch++) {
        __syncthreads();   // the ONE barrier: sp(window ch), K/V(ch), r(ch+2) all visible
        const int j0 = ch << 6;

        if (comp) {
            // ---- S = qc @ K^T
            const uint32_t kst = sbase + (uint32_t)(K_O + (ch & 1) * 2304) * 4;
            float S[8][4];
#pragma unroll
            for (int nt = 0; nt < 8; nt++)
#pragma unroll
                for (int e = 0; e < 4; e++) S[nt][e] = 0.f;
#pragma unroll
            for (int k4 = 0; k4 < 4; k4++) {
#pragma unroll
                for (int ntp = 0; ntp < 4; ntp++) {
                    uint32_t bb[4];
                    ldsm4(bb, kst + (uint32_t)((16 * ntp + bn) * WST + k4 * 8 + bk) * 4);
                    mma_bf16(S[2 * ntp],     aqf[k4][0], aqf[k4][1], aqf[k4][2], aqf[k4][3],
                             bb[0], bb[1]);
                    mma_bf16(S[2 * ntp + 1], aqf[k4][0], aqf[k4][1], aqf[k4][2], aqf[k4][3],
                             bb[2], bb[3]);
                }
            }
            // ---- rel-shift gather + exp (no-max) + pack P
            const int pbase = 1984 + j0 - i0;
            const int pb = pbase % 192;
            const int base_lo = pb + 63 - ia;
            const int base_hi = base_lo - 8;
            const int thr = ia + (i0 - j0);     // keep jloc <= thr (row ia); +8 for row ib
            uint32_t pk[8][2];
#pragma unroll
            for (int nt = 0; nt < 8; nt++) {
                int jl0 = 8 * nt + 2 * lr;
                int i0a = base_lo + jl0; if (i0a >= 192) i0a -= 192; if (i0a >= 192) i0a -= 192;
                int i0b = i0a + 1;       if (i0b >= 192) i0b -= 192;
                int i1a = base_hi + jl0; if (i1a >= 192) i1a -= 192; if (i1a >= 192) i1a -= 192;
                if (i1a < 0) i1a += 192;
                int i1b = i1a + 1;       if (i1b >= 192) i1b -= 192;
                float s0 = (S[nt][0] + bfu(sp16[ia * (2 * SPW) + i0a])) * 0.125f;
                float s1 = (S[nt][1] + bfu(sp16[ia * (2 * SPW) + i0b])) * 0.125f;
                float s2 = (S[nt][2] + bfu(sp16[ib * (2 * SPW) + i1a])) * 0.125f;
                float s3 = (S[nt][3] + bfu(sp16[ib * (2 * SPW) + i1b])) * 0.125f;
                float p0 = (jl0     <= thr)     ? __expf(s0) : 0.f;
                float p1 = (jl0 + 1 <= thr)     ? __expf(s1) : 0.f;
                float p2 = (jl0     <= thr + 8) ? __expf(s2) : 0.f;
                float p3 = (jl0 + 1 <= thr + 8) ? __expf(s3) : 0.f;
                l_lo += p0 + p1; l_hi += p2 + p3;
                pk[nt][0] = bf2(p0, p1);
                pk[nt][1] = bf2(p2, p3);
            }
            // ---- O += P @ V  (A from regs, B via ldmatrix.trans)
            const uint32_t vst = sbase + (uint32_t)(V_O + (ch & 1) * 2304) * 4;
#pragma unroll
            for (int t4 = 0; t4 < 4; t4++) {
                uint32_t a0 = pk[2 * t4][0], a1 = pk[2 * t4][1];
                uint32_t a2 = pk[2 * t4 + 1][0], a3 = pk[2 * t4 + 1][1];
#pragma unroll
                for (int ntp = 0; ntp < 4; ntp++) {
                    uint32_t bb[4];
                    ldsm4t(bb, vst + (uint32_t)((t4 * 16 + vj) * WST + 8 * ntp + vd4) * 4);
                    mma_bf16(O[2 * ntp],     a0, a1, a2, a3, bb[0], bb[1]);
                    mma_bf16(O[2 * ntp + 1], a0, a1, a2, a3, bb[2], bb[3]);
                }
            }
        } else {
            // ---- helper: Sp block ch+2, prefetch K/V(ch+1), r block ch+3
            if (ch + 2 <= ni) sp_block(ch + 2);
            if (ch + 1 < ni) {
#pragma unroll
                for (int g = 0; g < 4; g++) {
                    int idx = t2 + 128 * g;
                    int row = idx >> 3, gg = (idx & 7) << 2;
                    cpa16(sm + K_O + ((ch + 1) & 1) * 2304 + row * WST + gg,
                          kg + (rowb + j0 + 64 + row) * HW + colw + gg);
                    cpa16(sm + V_O + ((ch + 1) & 1) * 2304 + row * WST + gg,
                          vg + (rowb + j0 + 64 + row) * HW + colw + gg);
                }
                if (ch + 3 <= ni) {
#pragma unroll
                    for (int g = 0; g < 4; g++) {
                        int idx = t2 + 128 * g;
                        int row = idx >> 3, gg = (idx & 7) << 2;
                        int p = bl0 + 64 * (ch + 3) + row;
                        uint32_t* dst = sm + R_O + (p % 192) * WST + gg;
                        if (p < L_) cpa16(dst, rg + (size_t)p * HW + colw + gg);
                        else        *(uint4*)dst = make_uint4(0, 0, 0, 0);
                    }
                }
                CPA_COMMIT();
                CPA_WAIT0();
            }
        }
    }

    if (comp) {
        // final row-sum reduce (4 lanes per row) and write
        l_lo += __shfl_xor_sync(0xffffffffu, l_lo, 1);
        l_lo += __shfl_xor_sync(0xffffffffu, l_lo, 2);
        l_hi += __shfl_xor_sync(0xffffffffu, l_hi, 1);
        l_hi += __shfl_xor_sync(0xffffffffu, l_hi, 2);
        float la = 1.f / l_lo, lb = 1.f / l_hi;
        const size_t obase = (rowb + i0) * H_ + (n << 6);
#pragma unroll
        for (int nt = 0; nt < 8; nt++) {
            int cc = 8 * nt + 2 * lr;
            *(float2*)(out + obase + (size_t)ia * H_ + cc) =
                make_float2(O[nt][0] * la, O[nt][1] * la);
            *(float2*)(out + obase + (size_t)ib * H_ + cc) =
                make_float2(O[nt][2] * lb, O[nt][3] * lb);
        }
    }
}

// ---------------- fused residual-add + LayerNorm ----------------
__global__ __launch_bounds__(256)
void ln_kernel(const float* __restrict__ a, const float* __restrict__ b,
               const float* __restrict__ w, const float* __restrict__ beta,
               float* __restrict__ out)
{
    const int row = blockIdx.x;
    const int tid = threadIdx.x;
    const size_t base = (size_t)row * H_;
    float x0 = a[base + tid]       + b[base + tid];
    float x1 = a[base + tid + 256] + b[base + tid + 256];
    float s  = x0 + x1;
    float sq = x0 * x0 + x1 * x1;
#pragma unroll
    for (int o = 16; o > 0; o >>= 1) {
        s  += __shfl_xor_sync(0xffffffffu, s,  o);
        sq += __shfl_xor_sync(0xffffffffu, sq, o);
    }
    __shared__ float rs[8], rq[8];
    int wid = tid >> 5;
    if ((tid & 31) == 0) { rs[wid] = s; rq[wid] = sq; }
    __syncthreads();
    if (tid < 32) {
        float ss = (tid < 8) ? rs[tid] : 0.f;
        float qq = (tid < 8) ? rq[tid] : 0.f;
#pragma unroll
        for (int o = 4; o > 0; o >>= 1) {
            ss += __shfl_xor_sync(0xffffffffu, ss, o);
            qq += __shfl_xor_sync(0xffffffffu, qq, o);
        }
        if (tid == 0) { rs[0] = ss; rq[0] = qq; }
    }
    __syncthreads();
    float mean = rs[0] * (1.f / H_);
    float var  = rq[0] * (1.f / H_) - mean * mean;
    float inv  = rsqrtf(var + 1e-12f);
    out[base + tid]       = w[tid]       * (x0 - mean) * inv + beta[tid];
    out[base + tid + 256] = w[tid + 256] * (x1 - mean) * inv + beta[tid + 256];
}

// ---------------- launcher ----------------
extern "C" void kernel_launch(void* const* d_in, const int* in_sizes, int n_in,
                              void* d_out, int out_size)
{
    const float* x   = (const float*)d_in[0];
    const float* pe  = (const float*)d_in[1];
    const float* Wq  = (const float*)d_in[2];
    const float* bq  = (const float*)d_in[3];
    const float* Wk  = (const float*)d_in[4];
    const float* bk  = (const float*)d_in[5];
    const float* Wv  = (const float*)d_in[6];
    const float* bv  = (const float*)d_in[7];
    const float* Wr  = (const float*)d_in[8];
    const float* br  = (const float*)d_in[9];
    const float* cb  = (const float*)d_in[10];
    const float* pb  = (const float*)d_in[11];
    const float* Wc  = (const float*)d_in[12];
    const float* bc  = (const float*)d_in[13];
    const float* W1  = (const float*)d_in[14];
    const float* b1  = (const float*)d_in[15];
    const float* W2  = (const float*)d_in[16];
    const float* b2  = (const float*)d_in[17];
    const float* lnw = (const float*)d_in[18];
    const float* lnb = (const float*)d_in[19];
    float* out = (float*)d_out;

    uint32_t *qcP, *qpP, *kP, *vP, *rP;
    float *attnP, *t1P, *aP, *h1P, *h2P;
    cudaGetSymbolAddress((void**)&qcP,   g_qc);
    cudaGetSymbolAddress((void**)&qpP,   g_qp);
    cudaGetSymbolAddress((void**)&kP,    g_k);
    cudaGetSymbolAddress((void**)&vP,    g_v);
    cudaGetSymbolAddress((void**)&rP,    g_r);
    cudaGetSymbolAddress((void**)&attnP, g_attn);
    cudaGetSymbolAddress((void**)&t1P,   g_t1);
    cudaGetSymbolAddress((void**)&aP,    g_a);
    cudaGetSymbolAddress((void**)&h1P,   g_h1);
    cudaGetSymbolAddress((void**)&h2P,   g_h2);

    const dim3 gBig(H_ / 128, M_ / 128);   // (4, 64)
    const dim3 gPos(H_ / 128, L_ / 128);   // (4, 16)

    gemm_kernel<MODE_NHD, EPI_QCQP_BF><<<gBig, 256>>>(x,  Wq, bq, cb, pb, qcP, qpP, M_, H_, H_);
    gemm_kernel<MODE_NHD, EPI_BF><<<gBig, 256>>>(x,  Wk, bk, nullptr, nullptr, kP, nullptr, M_, H_, H_);
    gemm_kernel<MODE_NHD, EPI_BF><<<gBig, 256>>>(x,  Wv, bv, nullptr, nullptr, vP, nullptr, M_, H_, H_);
    gemm_kernel<MODE_NHD, EPI_BF><<<gPos, 256>>>(pe, Wr, br, nullptr, nullptr, rP, nullptr, L_, H_, H_);

    cudaFuncSetAttribute(attn_kernel, cudaFuncAttributeMaxDynamicSharedMemorySize, ATTN_SMEM_BYTES);
    attn_kernel<<<dim3(L_ / 64, B_ * N_), 256, ATTN_SMEM_BYTES>>>(qcP, qpP, kP, vP, rP, attnP);

    gemm_kernel<MODE_T, EPI_BIAS><<<gBig, 256>>>(attnP, Wc, bc, nullptr, nullptr, t1P, nullptr, M_, H_, H_);
    ln_kernel<<<M_, 256>>>(t1P, x, lnw, lnb, aP);

    gemm_kernel<MODE_T, EPI_GELU><<<gBig, 256>>>(aP,  W1, b1, nullptr, nullptr, h1P, nullptr, M_, H_, H_);
    gemm_kernel<MODE_T, EPI_BIAS><<<gBig, 256>>>(h1P, W2, b2, nullptr, nullptr, h2P, nullptr, M_, H_, H_);
    ln_kernel<<<M_, 256>>>(aP, h2P, lnw, lnb, out);
}